// round 1
// baseline (speedup 1.0000x reference)
#include <cuda_runtime.h>
#include <math.h>

// Problem constants (from reference): N=100000, E=131072, D=256, C=3, L=128, ZOUT=768
#define MAXN 100000
#define MAXE 131072

// ---------------- scratch (device globals; no allocation allowed) ----------------
__device__ float g_Zc[(size_t)MAXN * 384];      // [N, C*L]
__device__ float g_ZXT[256 * 384];              // ZX transposed: [d, c*128+l]
__device__ float g_P[(size_t)MAXE * 256];       // xi*xj
__device__ float g_ZZ[(size_t)MAXE * 384];      // Zi*Zj flattened
__device__ float g_G1[(size_t)MAXE * 256];      // silu(rxz @ zw1^T + b)
__device__ float g_G2[(size_t)MAXE * 256];      // silu(rxz^T @ zw1^T + b)
__device__ float g_H[(size_t)MAXE * 256];
__device__ float g_T[(size_t)MAXE * 256];
__device__ float g_XIJ[(size_t)MAXE * 768];     // pre-LN
__device__ float g_U1[(size_t)MAXE * 768];      // silu(G1 @ zw2^T + b), pre-LN
__device__ float g_U2[(size_t)MAXE * 768];
__device__ float g_XZX[(size_t)MAXE * 768];     // pre-LN

__device__ __forceinline__ float silu_f(float v) { return v / (1.0f + __expf(-v)); }

// ---------------- K0: Zc[n,c,l] = sum_i zc_w[c,i] Z[n,i,l] + zc_b[c] ----------------
__global__ void zc_kernel(const float* __restrict__ Z,
                          const float* __restrict__ zcw,
                          const float* __restrict__ zcb,
                          float* __restrict__ Zc, int NL) {
    int idx = blockIdx.x * 256 + threadIdx.x;
    if (idx >= NL) return;
    int n = idx >> 7, l = idx & 127;
    size_t base = (size_t)n * 384 + l;
    float z0 = Z[base], z1 = Z[base + 128], z2 = Z[base + 256];
    #pragma unroll
    for (int c = 0; c < 3; c++) {
        Zc[base + (size_t)c * 128] =
            zcw[c * 3 + 0] * z0 + zcw[c * 3 + 1] * z1 + zcw[c * 3 + 2] * z2 + zcb[c];
    }
}

// ---------------- K1: ZXT[d,k] += coeff * sum_n x[n,d] * Zc[n,k]  (split-K, atomic) --
// A = x [Ktot, 256], B = Zc [Ktot, 384], C = ZXT [256, 384]
__global__ __launch_bounds__(256) void gemm_tn_splitk(
    const float* __restrict__ A, const float* __restrict__ B,
    float* __restrict__ C, int M, int N, int Ktot, int kChunk, float scale) {
    __shared__ float As[16][128];
    __shared__ float Bs[16][128];
    int row0 = blockIdx.y * 128;
    int col0 = blockIdx.x * 128;
    int n0 = blockIdx.z * kChunk;
    int nEnd = min(n0 + kChunk, Ktot);
    int tid = threadIdx.x;
    int ty = tid >> 4, tx = tid & 15;

    float acc[8][8];
    #pragma unroll
    for (int i = 0; i < 8; i++)
        #pragma unroll
        for (int j = 0; j < 8; j++) acc[i][j] = 0.0f;

    for (int k0 = n0; k0 < nEnd; k0 += 16) {
        #pragma unroll
        for (int i = 0; i < 2; i++) {
            int f = tid + i * 256;          // 0..511
            int r = f >> 5;                 // node row 0..15
            int q = f & 31;                 // float4 col 0..31
            int node = k0 + r;
            float4 va = make_float4(0.f, 0.f, 0.f, 0.f);
            float4 vb = make_float4(0.f, 0.f, 0.f, 0.f);
            if (node < nEnd) {
                va = *reinterpret_cast<const float4*>(&A[(size_t)node * M + row0 + q * 4]);
                vb = *reinterpret_cast<const float4*>(&B[(size_t)node * N + col0 + q * 4]);
            }
            *reinterpret_cast<float4*>(&As[r][q * 4]) = va;
            *reinterpret_cast<float4*>(&Bs[r][q * 4]) = vb;
        }
        __syncthreads();
        #pragma unroll
        for (int kk = 0; kk < 16; kk++) {
            float a[8], b[8];
            *reinterpret_cast<float4*>(&a[0]) = *reinterpret_cast<float4*>(&As[kk][ty * 8]);
            *reinterpret_cast<float4*>(&a[4]) = *reinterpret_cast<float4*>(&As[kk][ty * 8 + 4]);
            *reinterpret_cast<float4*>(&b[0]) = *reinterpret_cast<float4*>(&Bs[kk][tx * 8]);
            *reinterpret_cast<float4*>(&b[4]) = *reinterpret_cast<float4*>(&Bs[kk][tx * 8 + 4]);
            #pragma unroll
            for (int i = 0; i < 8; i++)
                #pragma unroll
                for (int j = 0; j < 8; j++) acc[i][j] += a[i] * b[j];
        }
        __syncthreads();
    }
    #pragma unroll
    for (int i = 0; i < 8; i++) {
        int row = row0 + ty * 8 + i;
        #pragma unroll
        for (int j = 0; j < 8; j++) {
            int col = col0 + tx * 8 + j;
            atomicAdd(&C[(size_t)row * N + col], acc[i][j] * scale);
        }
    }
}

// ---------------- K2: per-edge prep: P, ZZ, G1, G2 ----------------
__global__ __launch_bounds__(128) void edge_prep(
    const float* __restrict__ x, const float* __restrict__ Z,
    const int* __restrict__ tar,
    const float* __restrict__ zw1, const float* __restrict__ zb1,
    float* __restrict__ P, float* __restrict__ ZZ,
    float* __restrict__ G1, float* __restrict__ G2, int E) {
    int e = blockIdx.x;
    int t = threadIdx.x;
    int src = tar[e], dst = tar[E + e];

    __shared__ float sZi[384], sZj[384];
    __shared__ float red[9][4];
    __shared__ float r9[9], rT9[9];

    // P = xi * xj
    const float* xs = x + (size_t)src * 256;
    const float* xd = x + (size_t)dst * 256;
    float* Pe = P + (size_t)e * 256;
    Pe[t]       = xs[t] * xd[t];
    Pe[t + 128] = xs[t + 128] * xd[t + 128];

    // stage Zi, Zj
    const float* Zi = Z + (size_t)src * 384;
    const float* Zj = Z + (size_t)dst * 384;
    for (int i = t; i < 384; i += 128) { sZi[i] = Zi[i]; sZj[i] = Zj[i]; }
    __syncthreads();

    // ZZ = Zi * Zj (flattened)
    float* ZZe = ZZ + (size_t)e * 384;
    for (int i = t; i < 384; i += 128) ZZe[i] = sZi[i] * sZj[i];

    // rxz[c][d] = (1/128) * sum_l Zi[c,l]*Zj[d,l]
    float loc[9];
    #pragma unroll
    for (int c = 0; c < 3; c++)
        #pragma unroll
        for (int d = 0; d < 3; d++)
            loc[c * 3 + d] = sZi[c * 128 + t] * sZj[d * 128 + t];
    #pragma unroll
    for (int off = 16; off > 0; off >>= 1)
        #pragma unroll
        for (int q = 0; q < 9; q++)
            loc[q] += __shfl_down_sync(0xffffffffu, loc[q], off);
    int warp = t >> 5, lane = t & 31;
    if (lane == 0)
        #pragma unroll
        for (int q = 0; q < 9; q++) red[q][warp] = loc[q];
    __syncthreads();
    if (t < 9) r9[t] = (red[t][0] + red[t][1] + red[t][2] + red[t][3]) * (1.0f / 128.0f);
    __syncthreads();
    if (t < 9) { int c = t / 3, d = t % 3; rT9[t] = r9[d * 3 + c]; }
    __syncthreads();

    // G1/G2: 9 -> 256 linear + silu
    #pragma unroll
    for (int rep = 0; rep < 2; rep++) {
        int o = t + rep * 128;
        const float* w = zw1 + (size_t)o * 9;
        float s1 = zb1[o], s2 = zb1[o];
        #pragma unroll
        for (int q = 0; q < 9; q++) { s1 += r9[q] * w[q]; s2 += rT9[q] * w[q]; }
        G1[(size_t)e * 256 + o] = silu_f(s1);
        G2[(size_t)e * 256 + o] = silu_f(s2);
    }
}

// ---------------- K3: C[m,o] = act(sum_k A[m,k] W[o,k] + b[o]) ----------------
template <bool SILU>
__global__ __launch_bounds__(256) void gemm_nt(
    const float* __restrict__ A, const float* __restrict__ W,
    const float* __restrict__ bias, float* __restrict__ C,
    int M, int N, int K) {
    __shared__ float As[16][128];
    __shared__ float Ws[16][128];
    int row0 = blockIdx.y * 128;
    int col0 = blockIdx.x * 128;
    int tid = threadIdx.x;
    int ty = tid >> 4, tx = tid & 15;

    float acc[8][8];
    #pragma unroll
    for (int i = 0; i < 8; i++)
        #pragma unroll
        for (int j = 0; j < 8; j++) acc[i][j] = 0.0f;

    for (int k0 = 0; k0 < K; k0 += 16) {
        #pragma unroll
        for (int i = 0; i < 2; i++) {
            int f = tid + i * 256;    // 0..511
            int r = f >> 2;           // row 0..127
            int q = f & 3;            // float4 in k
            float4 va = *reinterpret_cast<const float4*>(&A[(size_t)(row0 + r) * K + k0 + q * 4]);
            As[q * 4 + 0][r] = va.x; As[q * 4 + 1][r] = va.y;
            As[q * 4 + 2][r] = va.z; As[q * 4 + 3][r] = va.w;
            float4 vw = *reinterpret_cast<const float4*>(&W[(size_t)(col0 + r) * K + k0 + q * 4]);
            Ws[q * 4 + 0][r] = vw.x; Ws[q * 4 + 1][r] = vw.y;
            Ws[q * 4 + 2][r] = vw.z; Ws[q * 4 + 3][r] = vw.w;
        }
        __syncthreads();
        #pragma unroll
        for (int kk = 0; kk < 16; kk++) {
            float a[8], b[8];
            *reinterpret_cast<float4*>(&a[0]) = *reinterpret_cast<float4*>(&As[kk][ty * 8]);
            *reinterpret_cast<float4*>(&a[4]) = *reinterpret_cast<float4*>(&As[kk][ty * 8 + 4]);
            *reinterpret_cast<float4*>(&b[0]) = *reinterpret_cast<float4*>(&Ws[kk][tx * 8]);
            *reinterpret_cast<float4*>(&b[4]) = *reinterpret_cast<float4*>(&Ws[kk][tx * 8 + 4]);
            #pragma unroll
            for (int i = 0; i < 8; i++)
                #pragma unroll
                for (int j = 0; j < 8; j++) acc[i][j] += a[i] * b[j];
        }
        __syncthreads();
    }

    float bv[8];
    #pragma unroll
    for (int j = 0; j < 8; j++) bv[j] = bias ? bias[col0 + tx * 8 + j] : 0.0f;

    #pragma unroll
    for (int i = 0; i < 8; i++) {
        int row = row0 + ty * 8 + i;
        float o[8];
        #pragma unroll
        for (int j = 0; j < 8; j++) {
            float v = acc[i][j] + bv[j];
            if (SILU) v = silu_f(v);
            o[j] = v;
        }
        float* Cp = C + (size_t)row * N + col0 + tx * 8;
        *reinterpret_cast<float4*>(&Cp[0]) = make_float4(o[0], o[1], o[2], o[3]);
        *reinterpret_cast<float4*>(&Cp[4]) = make_float4(o[4], o[5], o[6], o[7]);
    }
}

// ---------------- K4: 4 LayerNorms + product + final dot ----------------
__global__ __launch_bounds__(256) void final_kernel(
    const float* __restrict__ XIJ, const float* __restrict__ U1,
    const float* __restrict__ U2, const float* __restrict__ XZX,
    const float* __restrict__ xg, const float* __restrict__ xb,
    const float* __restrict__ zg, const float* __restrict__ zb,
    const float* __restrict__ zxg, const float* __restrict__ zxb,
    const float* __restrict__ lw, const float* __restrict__ lb,
    float* __restrict__ out, int E) {
    int e = blockIdx.x;
    int t = threadIdx.x;
    const float* pxij = XIJ + (size_t)e * 768;
    const float* pu1  = U1  + (size_t)e * 768;
    const float* pu2  = U2  + (size_t)e * 768;
    const float* pxzx = XZX + (size_t)e * 768;

    __shared__ float red[8][8];
    __shared__ float stats[8];
    __shared__ float dred[8];

    float v0[3], v1[3], v2[3], v3[3];
    float s[8];
    #pragma unroll
    for (int q = 0; q < 8; q++) s[q] = 0.0f;
    #pragma unroll
    for (int k = 0; k < 3; k++) {
        int col = t + k * 256;
        float a = pxij[col], b = pu1[col], c = pu2[col], d = pxzx[col];
        v0[k] = a; v1[k] = b; v2[k] = c; v3[k] = d;
        s[0] += a; s[1] += a * a;
        s[2] += b; s[3] += b * b;
        s[4] += c; s[5] += c * c;
        s[6] += d; s[7] += d * d;
    }
    #pragma unroll
    for (int off = 16; off > 0; off >>= 1)
        #pragma unroll
        for (int q = 0; q < 8; q++)
            s[q] += __shfl_down_sync(0xffffffffu, s[q], off);
    int warp = t >> 5, lane = t & 31;
    if (lane == 0)
        #pragma unroll
        for (int q = 0; q < 8; q++) red[q][warp] = s[q];
    __syncthreads();
    if (t < 8) {
        float tot = 0.0f;
        #pragma unroll
        for (int w = 0; w < 8; w++) tot += red[t][w];
        stats[t] = tot;
    }
    __syncthreads();

    const float inv = 1.0f / 768.0f;
    const float eps = 1e-5f;
    float m0 = stats[0] * inv, r0 = rsqrtf(stats[1] * inv - m0 * m0 + eps);
    float m1 = stats[2] * inv, r1 = rsqrtf(stats[3] * inv - m1 * m1 + eps);
    float m2 = stats[4] * inv, r2 = rsqrtf(stats[5] * inv - m2 * m2 + eps);
    float m3 = stats[6] * inv, r3 = rsqrtf(stats[7] * inv - m3 * m3 + eps);

    float dot = 0.0f;
    #pragma unroll
    for (int k = 0; k < 3; k++) {
        int col = t + k * 256;
        float a  = (v0[k] - m0) * r0 * xg[col]  + xb[col];
        float b1 = (v1[k] - m1) * r1 * zg[col]  + zb[col];
        float b2 = (v2[k] - m2) * r2 * zg[col]  + zb[col];
        float c  = (v3[k] - m3) * r3 * zxg[col] + zxb[col];
        dot += a * (b1 + b2) * c * lw[col];
    }
    #pragma unroll
    for (int off = 16; off > 0; off >>= 1)
        dot += __shfl_down_sync(0xffffffffu, dot, off);
    if (lane == 0) dred[warp] = dot;
    __syncthreads();
    if (t == 0) {
        float tot = 0.0f;
        #pragma unroll
        for (int w = 0; w < 8; w++) tot += dred[w];
        out[e] = tot + lb[0];
    }
}

// ---------------- launch ----------------
extern "C" void kernel_launch(void* const* d_in, const int* in_sizes, int n_in,
                              void* d_out, int out_size) {
    const float* x   = (const float*)d_in[0];
    const float* Z   = (const float*)d_in[1];
    const int*   tar = (const int*)  d_in[3];
    const float* xij_w1 = (const float*)d_in[4];
    const float* xij_b1 = (const float*)d_in[5];
    const float* xij_w2 = (const float*)d_in[6];
    const float* xij_b2 = (const float*)d_in[7];
    const float* xij_ln_g = (const float*)d_in[8];
    const float* xij_ln_b = (const float*)d_in[9];
    const float* z_w1 = (const float*)d_in[10];
    const float* z_b1 = (const float*)d_in[11];
    const float* z_w2 = (const float*)d_in[12];
    const float* z_b2 = (const float*)d_in[13];
    const float* z_ln_g = (const float*)d_in[14];
    const float* z_ln_b = (const float*)d_in[15];
    const float* zc_w = (const float*)d_in[16];
    const float* zc_b = (const float*)d_in[17];
    const float* zx_w = (const float*)d_in[18];
    const float* zx_b = (const float*)d_in[19];
    const float* zx_ln_g = (const float*)d_in[20];
    const float* zx_ln_b = (const float*)d_in[21];
    const float* lin_w = (const float*)d_in[22];
    const float* lin_b = (const float*)d_in[23];

    int N = in_sizes[0] / 256;
    int E = in_sizes[3] / 2;
    float zx_coeff = (float)(1.0 / (sqrt((double)N) * 3840.0));  // n^-0.5 / (3*128*10)

    float *Zc, *ZXT, *P, *ZZ, *G1, *G2, *H, *T, *XIJ, *U1, *U2, *XZX;
    cudaGetSymbolAddress((void**)&Zc,  g_Zc);
    cudaGetSymbolAddress((void**)&ZXT, g_ZXT);
    cudaGetSymbolAddress((void**)&P,   g_P);
    cudaGetSymbolAddress((void**)&ZZ,  g_ZZ);
    cudaGetSymbolAddress((void**)&G1,  g_G1);
    cudaGetSymbolAddress((void**)&G2,  g_G2);
    cudaGetSymbolAddress((void**)&H,   g_H);
    cudaGetSymbolAddress((void**)&T,   g_T);
    cudaGetSymbolAddress((void**)&XIJ, g_XIJ);
    cudaGetSymbolAddress((void**)&U1,  g_U1);
    cudaGetSymbolAddress((void**)&U2,  g_U2);
    cudaGetSymbolAddress((void**)&XZX, g_XZX);

    // zx path (node side)
    int NL = N * 128;
    zc_kernel<<<(NL + 255) / 256, 256>>>(Z, zc_w, zc_b, Zc, NL);
    cudaMemsetAsync(ZXT, 0, 256 * 384 * sizeof(float), 0);
    {
        int kChunk = 1568;  // multiple of 16
        int splits = (N + kChunk - 1) / kChunk;
        dim3 grid(3, 2, splits);  // N=384 -> 3 tiles, M=256 -> 2 tiles
        gemm_tn_splitk<<<grid, 256>>>(x, Zc, ZXT, 256, 384, N, kChunk, zx_coeff);
    }

    // edge prep
    edge_prep<<<E, 128>>>(x, Z, tar, z_w1, z_b1, P, ZZ, G1, G2, E);

    // edge GEMMs
    dim3 g256(2, E / 128), g768(6, E / 128);
    gemm_nt<true ><<<g256, 256>>>(P,  xij_w1, xij_b1, H,   E, 256, 256);
    gemm_nt<false><<<g768, 256>>>(H,  xij_w2, xij_b2, XIJ, E, 768, 256);
    gemm_nt<true ><<<g768, 256>>>(G1, z_w2,   z_b2,   U1,  E, 768, 256);
    gemm_nt<true ><<<g768, 256>>>(G2, z_w2,   z_b2,   U2,  E, 768, 256);
    gemm_nt<false><<<g256, 256>>>(ZZ, ZXT,    nullptr,T,   E, 256, 384);
    gemm_nt<false><<<g768, 256>>>(T,  zx_w,   zx_b,   XZX, E, 768, 256);

    // fused LN + product + projection
    final_kernel<<<E, 256>>>(XIJ, U1, U2, XZX,
                             xij_ln_g, xij_ln_b, z_ln_g, z_ln_b,
                             zx_ln_g, zx_ln_b, lin_w, lin_b,
                             (float*)d_out, E);
}

// round 3
// speedup vs baseline: 1.6395x; 1.6395x over previous
#include <cuda_runtime.h>
#include <cuda_bf16.h>
#include <math.h>
#include <stdint.h>

#define MAXN 100000
#define MAXE 131072

// ---------------- scratch (device globals; no allocation allowed) ----------------
__device__ __align__(128) float g_Zc[(size_t)MAXN * 384];
__device__ __align__(128) float g_ZXT[256 * 384];
__device__ __align__(128) float g_XIJ[(size_t)MAXE * 768];
__device__ __align__(128) float g_U[(size_t)2 * MAXE * 768];   // U1 | U2
__device__ __align__(128) float g_XZX[(size_t)MAXE * 768];

// bf16 hi/lo planes
__device__ __align__(128) __nv_bfloat16 g_Ph [(size_t)MAXE * 256];
__device__ __align__(128) __nv_bfloat16 g_Pl [(size_t)MAXE * 256];
__device__ __align__(128) __nv_bfloat16 g_ZZh[(size_t)MAXE * 384];
__device__ __align__(128) __nv_bfloat16 g_ZZl[(size_t)MAXE * 384];
__device__ __align__(128) __nv_bfloat16 g_Gh [(size_t)2 * MAXE * 256];  // G1 | G2
__device__ __align__(128) __nv_bfloat16 g_Gl [(size_t)2 * MAXE * 256];
__device__ __align__(128) __nv_bfloat16 g_Hh [(size_t)MAXE * 256];
__device__ __align__(128) __nv_bfloat16 g_Hl [(size_t)MAXE * 256];
__device__ __align__(128) __nv_bfloat16 g_Th [(size_t)MAXE * 256];
__device__ __align__(128) __nv_bfloat16 g_Tl [(size_t)MAXE * 256];
// weight planes
__device__ __align__(128) __nv_bfloat16 g_W1h[256 * 256],  g_W1l[256 * 256];
__device__ __align__(128) __nv_bfloat16 g_W2h[768 * 256],  g_W2l[768 * 256];
__device__ __align__(128) __nv_bfloat16 g_ZW2h[768 * 256], g_ZW2l[768 * 256];
__device__ __align__(128) __nv_bfloat16 g_ZXWh[768 * 256], g_ZXWl[768 * 256];
__device__ __align__(128) __nv_bfloat16 g_ZXTh[256 * 384], g_ZXTl[256 * 384];

__device__ __forceinline__ float silu_f(float v) { return v / (1.0f + __expf(-v)); }

__device__ __forceinline__ void split_store(float v,
        __nv_bfloat16* __restrict__ hi, __nv_bfloat16* __restrict__ lo, size_t i) {
    __nv_bfloat16 h = __float2bfloat16(v);
    hi[i] = h;
    lo[i] = __float2bfloat16(v - __bfloat162float(h));
}

__device__ __forceinline__ uint32_t smem_u32(const void* p) {
    uint32_t a;
    asm("{ .reg .u64 t; cvta.to.shared.u64 t, %1; cvt.u32.u64 %0, t; }" : "=r"(a) : "l"(p));
    return a;
}

#define CP_ASYNC16(saddr, gptr) \
    asm volatile("cp.async.cg.shared.global [%0], [%1], 16;" :: "r"(saddr), "l"(gptr))
#define CP_COMMIT() asm volatile("cp.async.commit_group;")

__device__ __forceinline__ void ldm_x4(uint32_t addr, uint32_t& r0, uint32_t& r1,
                                       uint32_t& r2, uint32_t& r3) {
    asm volatile("ldmatrix.sync.aligned.m8n8.x4.shared.b16 {%0,%1,%2,%3}, [%4];"
                 : "=r"(r0), "=r"(r1), "=r"(r2), "=r"(r3) : "r"(addr));
}
__device__ __forceinline__ void mma_bf16(float* c, const uint32_t* a, const uint32_t* b) {
    asm volatile(
        "mma.sync.aligned.m16n8k16.row.col.f32.bf16.bf16.f32 "
        "{%0,%1,%2,%3}, {%4,%5,%6,%7}, {%8,%9}, {%0,%1,%2,%3};"
        : "+f"(c[0]), "+f"(c[1]), "+f"(c[2]), "+f"(c[3])
        : "r"(a[0]), "r"(a[1]), "r"(a[2]), "r"(a[3]), "r"(b[0]), "r"(b[1]));
}

// ================= HMMA GEMM: C[m,n] = act(sum_k A[m,k]*B[n,k] + bias[n]) ==========
// 128x128 block tile, BK=32, 8 warps (2x4), warp tile 64x32, 3-pass bf16 hi/lo.
// SMEM per buffer: 4 planes x 128 rows x 80B (32 bf16 + 8 pad) = 40960B; 2 buffers.
static constexpr int PLANE_B = 10240;
static constexpr int BUF_B   = 40960;
static constexpr int GEMM_SMEM = 2 * BUF_B;  // 81920

template <bool SILU, bool SPLIT>
__global__ __launch_bounds__(256, 1) void gemm_mma(
    const __nv_bfloat16* __restrict__ Ahi, const __nv_bfloat16* __restrict__ Alo,
    const __nv_bfloat16* __restrict__ Bhi, const __nv_bfloat16* __restrict__ Blo,
    const float* __restrict__ bias,
    float* __restrict__ Cf,
    __nv_bfloat16* __restrict__ Chi, __nv_bfloat16* __restrict__ Clo,
    int M, int N, int K) {
    extern __shared__ char smem[];
    const uint32_t sb = smem_u32(smem);
    const int tid = threadIdx.x, wid = tid >> 5, lane = tid & 31;
    const int col0 = blockIdx.x * 128;
    const int row0 = blockIdx.y * 128;
    const int wm = wid >> 2, wn = wid & 3;   // warp tile origin: (wm*64, wn*32)

    // cp.async per-thread coords: each thread handles 2 (row, 16B-chunk) pairs/plane
    const int ldr0 = tid >> 2, ldc0 = tid & 3;           // pair 0: rows 0..63
    const int ldr1 = ldr0 + 64;                           // pair 1: rows 64..127

    const __nv_bfloat16* planes[4] = { Ahi, Alo, Bhi, Blo };
    const int baseRow[4] = { row0, row0, col0, col0 };

    auto load_chunk = [&](int i) {
        const uint32_t bufb = sb + (i & 1) * BUF_B;
        const int k0 = i * 32;
        #pragma unroll
        for (int p = 0; p < 4; p++) {
            const __nv_bfloat16* src = planes[p];
            uint32_t s0 = bufb + p * PLANE_B + ldr0 * 80 + ldc0 * 16;
            const __nv_bfloat16* g0 = src + (size_t)(baseRow[p] + ldr0) * K + k0 + ldc0 * 8;
            CP_ASYNC16(s0, g0);
            uint32_t s1 = bufb + p * PLANE_B + ldr1 * 80 + ldc0 * 16;
            const __nv_bfloat16* g1 = src + (size_t)(baseRow[p] + ldr1) * K + k0 + ldc0 * 8;
            CP_ASYNC16(s1, g1);
        }
        CP_COMMIT();
    };

    float acc[4][4][4];
    #pragma unroll
    for (int i = 0; i < 4; i++)
        #pragma unroll
        for (int j = 0; j < 4; j++)
            #pragma unroll
            for (int q = 0; q < 4; q++) acc[i][j][q] = 0.0f;

    // ldmatrix lane-dependent offsets
    const int rowA = wm * 64 + (lane & 15);
    const int kparA = (lane >> 4) * 8;
    const int rowB = wn * 32 + (lane & 7) + ((lane >> 4) << 3);
    const int kparB = ((lane >> 3) & 1) * 8;

    const int nCh = K >> 5;
    load_chunk(0);

    for (int i = 0; i < nCh; i++) {
        if (i + 1 < nCh) {
            load_chunk(i + 1);
            asm volatile("cp.async.wait_group 1;");
        } else {
            asm volatile("cp.async.wait_group 0;");
        }
        __syncthreads();

        const uint32_t bufb = sb + (i & 1) * BUF_B;
        #pragma unroll
        for (int ks = 0; ks < 2; ks++) {
            // B fragments (hi & lo), 4 n-frags of 8 cols each
            uint32_t bh[4][2], bl[4][2];
            #pragma unroll
            for (int nf2 = 0; nf2 < 2; nf2++) {
                uint32_t addrH = bufb + 2 * PLANE_B +
                    (uint32_t)(rowB + nf2 * 16) * 80 + (uint32_t)(kparB + ks * 16) * 2;
                ldm_x4(addrH, bh[nf2 * 2][0], bh[nf2 * 2][1],
                              bh[nf2 * 2 + 1][0], bh[nf2 * 2 + 1][1]);
                uint32_t addrL = addrH + PLANE_B;
                ldm_x4(addrL, bl[nf2 * 2][0], bl[nf2 * 2][1],
                              bl[nf2 * 2 + 1][0], bl[nf2 * 2 + 1][1]);
            }
            #pragma unroll
            for (int mf = 0; mf < 4; mf++) {
                uint32_t ah[4], al[4];
                uint32_t addrH = bufb +
                    (uint32_t)(rowA + mf * 16) * 80 + (uint32_t)(kparA + ks * 16) * 2;
                ldm_x4(addrH, ah[0], ah[1], ah[2], ah[3]);
                ldm_x4(addrH + PLANE_B, al[0], al[1], al[2], al[3]);
                #pragma unroll
                for (int nf = 0; nf < 4; nf++) {
                    mma_bf16(acc[mf][nf], ah, bh[nf]);   // hi*hi
                    mma_bf16(acc[mf][nf], ah, bl[nf]);   // hi*lo
                    mma_bf16(acc[mf][nf], al, bh[nf]);   // lo*hi
                }
            }
        }
        __syncthreads();
    }

    // epilogue: direct global stores
    const int qrow = lane >> 2, qcol = (lane & 3) * 2;
    #pragma unroll
    for (int nf = 0; nf < 4; nf++) {
        const int col = col0 + wn * 32 + nf * 8 + qcol;
        float b0 = bias ? bias[col] : 0.0f;
        float b1 = bias ? bias[col + 1] : 0.0f;
        #pragma unroll
        for (int mf = 0; mf < 4; mf++) {
            #pragma unroll
            for (int h = 0; h < 2; h++) {
                const int row = row0 + wm * 64 + mf * 16 + qrow + h * 8;
                float v0 = acc[mf][nf][h * 2 + 0] + b0;
                float v1 = acc[mf][nf][h * 2 + 1] + b1;
                if (SILU) { v0 = silu_f(v0); v1 = silu_f(v1); }
                size_t gi = (size_t)row * N + col;
                if (SPLIT) {
                    __nv_bfloat16 h0 = __float2bfloat16(v0);
                    __nv_bfloat16 h1 = __float2bfloat16(v1);
                    *reinterpret_cast<__nv_bfloat162*>(Chi + gi) =
                        __nv_bfloat162(h0, h1);
                    *reinterpret_cast<__nv_bfloat162*>(Clo + gi) = __nv_bfloat162(
                        __float2bfloat16(v0 - __bfloat162float(h0)),
                        __float2bfloat16(v1 - __bfloat162float(h1)));
                } else {
                    *reinterpret_cast<float2*>(Cf + gi) = make_float2(v0, v1);
                }
            }
        }
    }
}

// ---------------- split fp32 -> bf16 hi/lo planes ----------------
__global__ void split_kernel(const float* __restrict__ src,
                             __nv_bfloat16* __restrict__ hi,
                             __nv_bfloat16* __restrict__ lo, int n) {
    int i = blockIdx.x * 256 + threadIdx.x;
    if (i < n) split_store(src[i], hi, lo, i);
}

// ---------------- K0: Zc ----------------
__global__ void zc_kernel(const float* __restrict__ Z,
                          const float* __restrict__ zcw,
                          const float* __restrict__ zcb,
                          float* __restrict__ Zc, int NL) {
    int idx = blockIdx.x * 256 + threadIdx.x;
    if (idx >= NL) return;
    int n = idx >> 7, l = idx & 127;
    size_t base = (size_t)n * 384 + l;
    float z0 = Z[base], z1 = Z[base + 128], z2 = Z[base + 256];
    #pragma unroll
    for (int c = 0; c < 3; c++) {
        Zc[base + (size_t)c * 128] =
            zcw[c * 3 + 0] * z0 + zcw[c * 3 + 1] * z1 + zcw[c * 3 + 2] * z2 + zcb[c];
    }
}

// ---------------- K1: ZXT (split-K fp32 SIMT) ----------------
__global__ __launch_bounds__(256) void gemm_tn_splitk(
    const float* __restrict__ A, const float* __restrict__ B,
    float* __restrict__ C, int M, int N, int Ktot, int kChunk, float scale) {
    __shared__ float As[16][128];
    __shared__ float Bs[16][128];
    int row0 = blockIdx.y * 128;
    int col0 = blockIdx.x * 128;
    int n0 = blockIdx.z * kChunk;
    int nEnd = min(n0 + kChunk, Ktot);
    int tid = threadIdx.x;
    int ty = tid >> 4, tx = tid & 15;

    float acc[8][8];
    #pragma unroll
    for (int i = 0; i < 8; i++)
        #pragma unroll
        for (int j = 0; j < 8; j++) acc[i][j] = 0.0f;

    for (int k0 = n0; k0 < nEnd; k0 += 16) {
        #pragma unroll
        for (int i = 0; i < 2; i++) {
            int f = tid + i * 256;
            int r = f >> 5;
            int q = f & 31;
            int node = k0 + r;
            float4 va = make_float4(0.f, 0.f, 0.f, 0.f);
            float4 vb = make_float4(0.f, 0.f, 0.f, 0.f);
            if (node < nEnd) {
                va = *reinterpret_cast<const float4*>(&A[(size_t)node * M + row0 + q * 4]);
                vb = *reinterpret_cast<const float4*>(&B[(size_t)node * N + col0 + q * 4]);
            }
            *reinterpret_cast<float4*>(&As[r][q * 4]) = va;
            *reinterpret_cast<float4*>(&Bs[r][q * 4]) = vb;
        }
        __syncthreads();
        #pragma unroll
        for (int kk = 0; kk < 16; kk++) {
            float a[8], b[8];
            *reinterpret_cast<float4*>(&a[0]) = *reinterpret_cast<float4*>(&As[kk][ty * 8]);
            *reinterpret_cast<float4*>(&a[4]) = *reinterpret_cast<float4*>(&As[kk][ty * 8 + 4]);
            *reinterpret_cast<float4*>(&b[0]) = *reinterpret_cast<float4*>(&Bs[kk][tx * 8]);
            *reinterpret_cast<float4*>(&b[4]) = *reinterpret_cast<float4*>(&Bs[kk][tx * 8 + 4]);
            #pragma unroll
            for (int i = 0; i < 8; i++)
                #pragma unroll
                for (int j = 0; j < 8; j++) acc[i][j] += a[i] * b[j];
        }
        __syncthreads();
    }
    #pragma unroll
    for (int i = 0; i < 8; i++) {
        int row = row0 + ty * 8 + i;
        #pragma unroll
        for (int j = 0; j < 8; j++) {
            int col = col0 + tx * 8 + j;
            atomicAdd(&C[(size_t)row * N + col], acc[i][j] * scale);
        }
    }
}

// ---------------- K2: per-edge prep (emits bf16 planes; G1|G2 merged) ----------------
__global__ __launch_bounds__(128) void edge_prep(
    const float* __restrict__ x, const float* __restrict__ Z,
    const int* __restrict__ tar,
    const float* __restrict__ zw1, const float* __restrict__ zb1,
    __nv_bfloat16* __restrict__ Phi, __nv_bfloat16* __restrict__ Plo,
    __nv_bfloat16* __restrict__ ZZhi, __nv_bfloat16* __restrict__ ZZlo,
    __nv_bfloat16* __restrict__ Ghi, __nv_bfloat16* __restrict__ Glo, int E) {
    int e = blockIdx.x;
    int t = threadIdx.x;
    int src = tar[e], dst = tar[E + e];

    __shared__ float sZi[384], sZj[384];
    __shared__ float red[9][4];
    __shared__ float r9[9], rT9[9];

    const float* xs = x + (size_t)src * 256;
    const float* xd = x + (size_t)dst * 256;
    split_store(xs[t] * xd[t],             Phi, Plo, (size_t)e * 256 + t);
    split_store(xs[t + 128] * xd[t + 128], Phi, Plo, (size_t)e * 256 + t + 128);

    const float* Zi = Z + (size_t)src * 384;
    const float* Zj = Z + (size_t)dst * 384;
    for (int i = t; i < 384; i += 128) { sZi[i] = Zi[i]; sZj[i] = Zj[i]; }
    __syncthreads();

    for (int i = t; i < 384; i += 128)
        split_store(sZi[i] * sZj[i], ZZhi, ZZlo, (size_t)e * 384 + i);

    float loc[9];
    #pragma unroll
    for (int c = 0; c < 3; c++)
        #pragma unroll
        for (int d = 0; d < 3; d++)
            loc[c * 3 + d] = sZi[c * 128 + t] * sZj[d * 128 + t];
    #pragma unroll
    for (int off = 16; off > 0; off >>= 1)
        #pragma unroll
        for (int q = 0; q < 9; q++)
            loc[q] += __shfl_down_sync(0xffffffffu, loc[q], off);
    int warp = t >> 5, lane = t & 31;
    if (lane == 0)
        #pragma unroll
        for (int q = 0; q < 9; q++) red[q][warp] = loc[q];
    __syncthreads();
    if (t < 9) r9[t] = (red[t][0] + red[t][1] + red[t][2] + red[t][3]) * (1.0f / 128.0f);
    __syncthreads();
    if (t < 9) { int c = t / 3, d = t % 3; rT9[t] = r9[d * 3 + c]; }
    __syncthreads();

    #pragma unroll
    for (int rep = 0; rep < 2; rep++) {
        int o = t + rep * 128;
        const float* w = zw1 + (size_t)o * 9;
        float s1 = zb1[o], s2 = zb1[o];
        #pragma unroll
        for (int q = 0; q < 9; q++) { s1 += r9[q] * w[q]; s2 += rT9[q] * w[q]; }
        split_store(silu_f(s1), Ghi, Glo, (size_t)e * 256 + o);
        split_store(silu_f(s2), Ghi, Glo, (size_t)(E + e) * 256 + o);
    }
}

// ---------------- K4: 4 LayerNorms + product + final dot ----------------
__global__ __launch_bounds__(256) void final_kernel(
    const float* __restrict__ XIJ, const float* __restrict__ U,
    const float* __restrict__ XZX,
    const float* __restrict__ xg, const float* __restrict__ xb,
    const float* __restrict__ zg, const float* __restrict__ zb,
    const float* __restrict__ zxg, const float* __restrict__ zxb,
    const float* __restrict__ lw, const float* __restrict__ lb,
    float* __restrict__ out, int E) {
    int e = blockIdx.x;
    int t = threadIdx.x;
    const float* pxij = XIJ + (size_t)e * 768;
    const float* pu1  = U   + (size_t)e * 768;
    const float* pu2  = U   + (size_t)(E + e) * 768;
    const float* pxzx = XZX + (size_t)e * 768;

    __shared__ float red[8][8];
    __shared__ float stats[8];
    __shared__ float dred[8];

    float v0[3], v1[3], v2[3], v3[3];
    float s[8];
    #pragma unroll
    for (int q = 0; q < 8; q++) s[q] = 0.0f;
    #pragma unroll
    for (int k = 0; k < 3; k++) {
        int col = t + k * 256;
        float a = pxij[col], b = pu1[col], c = pu2[col], d = pxzx[col];
        v0[k] = a; v1[k] = b; v2[k] = c; v3[k] = d;
        s[0] += a; s[1] += a * a;
        s[2] += b; s[3] += b * b;
        s[4] += c; s[5] += c * c;
        s[6] += d; s[7] += d * d;
    }
    #pragma unroll
    for (int off = 16; off > 0; off >>= 1)
        #pragma unroll
        for (int q = 0; q < 8; q++)
            s[q] += __shfl_down_sync(0xffffffffu, s[q], off);
    int warp = t >> 5, lane = t & 31;
    if (lane == 0)
        #pragma unroll
        for (int q = 0; q < 8; q++) red[q][warp] = s[q];
    __syncthreads();
    if (t < 8) {
        float tot = 0.0f;
        #pragma unroll
        for (int w = 0; w < 8; w++) tot += red[t][w];
        stats[t] = tot;
    }
    __syncthreads();

    const float inv = 1.0f / 768.0f;
    const float eps = 1e-5f;
    float m0 = stats[0] * inv, r0 = rsqrtf(stats[1] * inv - m0 * m0 + eps);
    float m1 = stats[2] * inv, r1 = rsqrtf(stats[3] * inv - m1 * m1 + eps);
    float m2 = stats[4] * inv, r2 = rsqrtf(stats[5] * inv - m2 * m2 + eps);
    float m3 = stats[6] * inv, r3 = rsqrtf(stats[7] * inv - m3 * m3 + eps);

    float dot = 0.0f;
    #pragma unroll
    for (int k = 0; k < 3; k++) {
        int col = t + k * 256;
        float a  = (v0[k] - m0) * r0 * xg[col]  + xb[col];
        float b1 = (v1[k] - m1) * r1 * zg[col]  + zb[col];
        float b2 = (v2[k] - m2) * r2 * zg[col]  + zb[col];
        float c  = (v3[k] - m3) * r3 * zxg[col] + zxb[col];
        dot += a * (b1 + b2) * c * lw[col];
    }
    #pragma unroll
    for (int off = 16; off > 0; off >>= 1)
        dot += __shfl_down_sync(0xffffffffu, dot, off);
    if (lane == 0) dred[warp] = dot;
    __syncthreads();
    if (t == 0) {
        float tot = 0.0f;
        #pragma unroll
        for (int w = 0; w < 8; w++) tot += dred[w];
        out[e] = tot + lb[0];
    }
}

// ---------------- launch ----------------
extern "C" void kernel_launch(void* const* d_in, const int* in_sizes, int n_in,
                              void* d_out, int out_size) {
    const float* x   = (const float*)d_in[0];
    const float* Z   = (const float*)d_in[1];
    const int*   tar = (const int*)  d_in[3];
    const float* xij_w1 = (const float*)d_in[4];
    const float* xij_b1 = (const float*)d_in[5];
    const float* xij_w2 = (const float*)d_in[6];
    const float* xij_b2 = (const float*)d_in[7];
    const float* xij_ln_g = (const float*)d_in[8];
    const float* xij_ln_b = (const float*)d_in[9];
    const float* z_w1 = (const float*)d_in[10];
    const float* z_b1 = (const float*)d_in[11];
    const float* z_w2 = (const float*)d_in[12];
    const float* z_b2 = (const float*)d_in[13];
    const float* z_ln_g = (const float*)d_in[14];
    const float* z_ln_b = (const float*)d_in[15];
    const float* zc_w = (const float*)d_in[16];
    const float* zc_b = (const float*)d_in[17];
    const float* zx_w = (const float*)d_in[18];
    const float* zx_b = (const float*)d_in[19];
    const float* zx_ln_g = (const float*)d_in[20];
    const float* zx_ln_b = (const float*)d_in[21];
    const float* lin_w = (const float*)d_in[22];
    const float* lin_b = (const float*)d_in[23];

    int N = in_sizes[0] / 256;
    int E = in_sizes[3] / 2;
    float zx_coeff = (float)(1.0 / (sqrt((double)N) * 3840.0));

    float *Zc, *ZXT, *XIJ, *U, *XZX;
    cudaGetSymbolAddress((void**)&Zc,  g_Zc);
    cudaGetSymbolAddress((void**)&ZXT, g_ZXT);
    cudaGetSymbolAddress((void**)&XIJ, g_XIJ);
    cudaGetSymbolAddress((void**)&U,   g_U);
    cudaGetSymbolAddress((void**)&XZX, g_XZX);

    __nv_bfloat16 *Ph,*Pl,*ZZh,*ZZl,*Gh,*Gl,*Hh,*Hl,*Th,*Tl;
    __nv_bfloat16 *W1h,*W1l,*W2h,*W2l,*ZW2h,*ZW2l,*ZXWh,*ZXWl,*ZXTh,*ZXTl;
    cudaGetSymbolAddress((void**)&Ph,  g_Ph);  cudaGetSymbolAddress((void**)&Pl,  g_Pl);
    cudaGetSymbolAddress((void**)&ZZh, g_ZZh); cudaGetSymbolAddress((void**)&ZZl, g_ZZl);
    cudaGetSymbolAddress((void**)&Gh,  g_Gh);  cudaGetSymbolAddress((void**)&Gl,  g_Gl);
    cudaGetSymbolAddress((void**)&Hh,  g_Hh);  cudaGetSymbolAddress((void**)&Hl,  g_Hl);
    cudaGetSymbolAddress((void**)&Th,  g_Th);  cudaGetSymbolAddress((void**)&Tl,  g_Tl);
    cudaGetSymbolAddress((void**)&W1h, g_W1h); cudaGetSymbolAddress((void**)&W1l, g_W1l);
    cudaGetSymbolAddress((void**)&W2h, g_W2h); cudaGetSymbolAddress((void**)&W2l, g_W2l);
    cudaGetSymbolAddress((void**)&ZW2h,g_ZW2h);cudaGetSymbolAddress((void**)&ZW2l,g_ZW2l);
    cudaGetSymbolAddress((void**)&ZXWh,g_ZXWh);cudaGetSymbolAddress((void**)&ZXWl,g_ZXWl);
    cudaGetSymbolAddress((void**)&ZXTh,g_ZXTh);cudaGetSymbolAddress((void**)&ZXTl,g_ZXTl);

    cudaFuncSetAttribute(gemm_mma<true,  true >, cudaFuncAttributeMaxDynamicSharedMemorySize, GEMM_SMEM);
    cudaFuncSetAttribute(gemm_mma<false, false>, cudaFuncAttributeMaxDynamicSharedMemorySize, GEMM_SMEM);
    cudaFuncSetAttribute(gemm_mma<true,  false>, cudaFuncAttributeMaxDynamicSharedMemorySize, GEMM_SMEM);
    cudaFuncSetAttribute(gemm_mma<false, true >, cudaFuncAttributeMaxDynamicSharedMemorySize, GEMM_SMEM);

    // weight plane splits
    split_kernel<<<(65536 + 255) / 256, 256>>>(xij_w1, W1h, W1l, 65536);
    split_kernel<<<(196608 + 255) / 256, 256>>>(xij_w2, W2h, W2l, 196608);
    split_kernel<<<(196608 + 255) / 256, 256>>>(z_w2,  ZW2h, ZW2l, 196608);
    split_kernel<<<(196608 + 255) / 256, 256>>>(zx_w,  ZXWh, ZXWl, 196608);

    // zx node path
    int NL = N * 128;
    zc_kernel<<<(NL + 255) / 256, 256>>>(Z, zc_w, zc_b, Zc, NL);
    cudaMemsetAsync(ZXT, 0, 256 * 384 * sizeof(float), 0);
    {
        int kChunk = 1568;
        int splits = (N + kChunk - 1) / kChunk;
        dim3 grid(3, 2, splits);
        gemm_tn_splitk<<<grid, 256>>>(x, Zc, ZXT, 256, 384, N, kChunk, zx_coeff);
    }
    split_kernel<<<(98304 + 255) / 256, 256>>>(ZXT, ZXTh, ZXTl, 98304);

    // edge prep
    edge_prep<<<E, 128>>>(x, Z, tar, z_w1, z_b1, Ph, Pl, ZZh, ZZl, Gh, Gl, E);

    // tensor-core edge GEMMs (HMMA)
    dim3 g256(2, E / 128), g768(6, E / 128), gU(6, 2 * E / 128);
    gemm_mma<true,  true ><<<g256, 256, GEMM_SMEM>>>(Ph, Pl, W1h, W1l, xij_b1,
                                                     nullptr, Hh, Hl, E, 256, 256);
    gemm_mma<false, false><<<g768, 256, GEMM_SMEM>>>(Hh, Hl, W2h, W2l, xij_b2,
                                                     XIJ, nullptr, nullptr, E, 768, 256);
    gemm_mma<true,  false><<<gU,   256, GEMM_SMEM>>>(Gh, Gl, ZW2h, ZW2l, z_b2,
                                                     U, nullptr, nullptr, 2 * E, 768, 256);
    gemm_mma<false, true ><<<g256, 256, GEMM_SMEM>>>(ZZh, ZZl, ZXTh, ZXTl, nullptr,
                                                     nullptr, Th, Tl, E, 256, 384);
    gemm_mma<false, false><<<g768, 256, GEMM_SMEM>>>(Th, Tl, ZXWh, ZXWl, zx_b,
                                                     XZX, nullptr, nullptr, E, 768, 256);

    final_kernel<<<E, 256>>>(XIJ, U, XZX,
                             xij_ln_g, xij_ln_b, z_ln_g, z_ln_b,
                             zx_ln_g, zx_ln_b, lin_w, lin_b,
                             (float*)d_out, E);
}

// round 5
// speedup vs baseline: 1.8640x; 1.1369x over previous
#include <cuda_runtime.h>
#include <cuda_bf16.h>
#include <math.h>
#include <stdint.h>

#define MAXN 100000
#define MAXE 131072

// ---------------- scratch (device globals; no allocation allowed) ----------------
__device__ __align__(128) float g_ZXT[256 * 384];
__device__ __align__(128) float g_XIJ[(size_t)MAXE * 768];
__device__ __align__(128) float g_U[(size_t)2 * MAXE * 768];   // U1 | U2
__device__ __align__(128) float g_XZX[(size_t)MAXE * 768];

// bf16 hi/lo planes
__device__ __align__(128) __nv_bfloat16 g_xh [(size_t)MAXN * 256];
__device__ __align__(128) __nv_bfloat16 g_xl [(size_t)MAXN * 256];
__device__ __align__(128) __nv_bfloat16 g_Zch[(size_t)MAXN * 384];
__device__ __align__(128) __nv_bfloat16 g_Zcl[(size_t)MAXN * 384];
__device__ __align__(128) __nv_bfloat16 g_Ph [(size_t)MAXE * 256];
__device__ __align__(128) __nv_bfloat16 g_Pl [(size_t)MAXE * 256];
__device__ __align__(128) __nv_bfloat16 g_ZZh[(size_t)MAXE * 384];
__device__ __align__(128) __nv_bfloat16 g_ZZl[(size_t)MAXE * 384];
__device__ __align__(128) __nv_bfloat16 g_Gh [(size_t)2 * MAXE * 256];  // G1 | G2
__device__ __align__(128) __nv_bfloat16 g_Gl [(size_t)2 * MAXE * 256];
__device__ __align__(128) __nv_bfloat16 g_Hh [(size_t)MAXE * 256];
__device__ __align__(128) __nv_bfloat16 g_Hl [(size_t)MAXE * 256];
__device__ __align__(128) __nv_bfloat16 g_Th [(size_t)MAXE * 256];
__device__ __align__(128) __nv_bfloat16 g_Tl [(size_t)MAXE * 256];
// weight planes
__device__ __align__(128) __nv_bfloat16 g_W1h[256 * 256],  g_W1l[256 * 256];
__device__ __align__(128) __nv_bfloat16 g_W2h[768 * 256],  g_W2l[768 * 256];
__device__ __align__(128) __nv_bfloat16 g_ZW2h[768 * 256], g_ZW2l[768 * 256];
__device__ __align__(128) __nv_bfloat16 g_ZXWh[768 * 256], g_ZXWl[768 * 256];
__device__ __align__(128) __nv_bfloat16 g_ZXTh[256 * 384], g_ZXTl[256 * 384];

__device__ __forceinline__ float silu_f(float v) { return v / (1.0f + __expf(-v)); }

__device__ __forceinline__ void split_store(float v,
        __nv_bfloat16* __restrict__ hi, __nv_bfloat16* __restrict__ lo, size_t i) {
    __nv_bfloat16 h = __float2bfloat16(v);
    hi[i] = h;
    lo[i] = __float2bfloat16(v - __bfloat162float(h));
}

__device__ __forceinline__ uint32_t smem_u32(const void* p) {
    uint32_t a;
    asm("{ .reg .u64 t; cvta.to.shared.u64 t, %1; cvt.u32.u64 %0, t; }" : "=r"(a) : "l"(p));
    return a;
}

#define CP_ASYNC16(saddr, gptr) \
    asm volatile("cp.async.cg.shared.global [%0], [%1], 16;" :: "r"(saddr), "l"(gptr))
#define CP_COMMIT() asm volatile("cp.async.commit_group;")

__device__ __forceinline__ void ldm_x4(uint32_t addr, uint32_t& r0, uint32_t& r1,
                                       uint32_t& r2, uint32_t& r3) {
    asm volatile("ldmatrix.sync.aligned.m8n8.x4.shared.b16 {%0,%1,%2,%3}, [%4];"
                 : "=r"(r0), "=r"(r1), "=r"(r2), "=r"(r3) : "r"(addr));
}
__device__ __forceinline__ void ldm_x4t(uint32_t addr, uint32_t& r0, uint32_t& r1,
                                        uint32_t& r2, uint32_t& r3) {
    asm volatile("ldmatrix.sync.aligned.m8n8.x4.trans.shared.b16 {%0,%1,%2,%3}, [%4];"
                 : "=r"(r0), "=r"(r1), "=r"(r2), "=r"(r3) : "r"(addr));
}
__device__ __forceinline__ void mma_bf16(float* c, const uint32_t* a, const uint32_t* b) {
    asm volatile(
        "mma.sync.aligned.m16n8k16.row.col.f32.bf16.bf16.f32 "
        "{%0,%1,%2,%3}, {%4,%5,%6,%7}, {%8,%9}, {%0,%1,%2,%3};"
        : "+f"(c[0]), "+f"(c[1]), "+f"(c[2]), "+f"(c[3])
        : "r"(a[0]), "r"(a[1]), "r"(a[2]), "r"(a[3]), "r"(b[0]), "r"(b[1]));
}

// ================= HMMA GEMM: C[m,n] = act(sum_k A[m,k]*B[n,k] + bias[n]) ==========
// 128x128 block tile, BK=32, 8 warps (2x4), warp tile 64x32, 3-pass bf16 hi/lo.
static constexpr int PLANE_B = 10240;   // 128 rows * 80B
static constexpr int BUF_B   = 40960;
static constexpr int GEMM_SMEM = 2 * BUF_B;  // 81920

template <bool SILU, bool SPLIT>
__global__ __launch_bounds__(256, 1) void gemm_mma(
    const __nv_bfloat16* __restrict__ Ahi, const __nv_bfloat16* __restrict__ Alo,
    const __nv_bfloat16* __restrict__ Bhi, const __nv_bfloat16* __restrict__ Blo,
    const float* __restrict__ bias,
    float* __restrict__ Cf,
    __nv_bfloat16* __restrict__ Chi, __nv_bfloat16* __restrict__ Clo,
    int M, int N, int K) {
    extern __shared__ char smem[];
    const uint32_t sb = smem_u32(smem);
    const int tid = threadIdx.x, wid = tid >> 5, lane = tid & 31;
    const int col0 = blockIdx.x * 128;
    const int row0 = blockIdx.y * 128;
    const int wm = wid >> 2, wn = wid & 3;

    const int ldr0 = tid >> 2, ldc0 = tid & 3;
    const int ldr1 = ldr0 + 64;

    const __nv_bfloat16* planes[4] = { Ahi, Alo, Bhi, Blo };
    const int baseRow[4] = { row0, row0, col0, col0 };

    auto load_chunk = [&](int i) {
        const uint32_t bufb = sb + (i & 1) * BUF_B;
        const int k0 = i * 32;
        #pragma unroll
        for (int p = 0; p < 4; p++) {
            const __nv_bfloat16* src = planes[p];
            uint32_t s0 = bufb + p * PLANE_B + ldr0 * 80 + ldc0 * 16;
            CP_ASYNC16(s0, src + (size_t)(baseRow[p] + ldr0) * K + k0 + ldc0 * 8);
            uint32_t s1 = bufb + p * PLANE_B + ldr1 * 80 + ldc0 * 16;
            CP_ASYNC16(s1, src + (size_t)(baseRow[p] + ldr1) * K + k0 + ldc0 * 8);
        }
        CP_COMMIT();
    };

    float acc[4][4][4];
    #pragma unroll
    for (int i = 0; i < 4; i++)
        #pragma unroll
        for (int j = 0; j < 4; j++)
            #pragma unroll
            for (int q = 0; q < 4; q++) acc[i][j][q] = 0.0f;

    const int rowA = wm * 64 + (lane & 15);
    const int kparA = (lane >> 4) * 8;
    const int rowB = wn * 32 + (lane & 7) + ((lane >> 4) << 3);
    const int kparB = ((lane >> 3) & 1) * 8;

    const int nCh = K >> 5;
    load_chunk(0);

    for (int i = 0; i < nCh; i++) {
        if (i + 1 < nCh) {
            load_chunk(i + 1);
            asm volatile("cp.async.wait_group 1;");
        } else {
            asm volatile("cp.async.wait_group 0;");
        }
        __syncthreads();

        const uint32_t bufb = sb + (i & 1) * BUF_B;
        #pragma unroll
        for (int ks = 0; ks < 2; ks++) {
            uint32_t bh[4][2], bl[4][2];
            #pragma unroll
            for (int nf2 = 0; nf2 < 2; nf2++) {
                uint32_t addrH = bufb + 2 * PLANE_B +
                    (uint32_t)(rowB + nf2 * 16) * 80 + (uint32_t)(kparB + ks * 16) * 2;
                ldm_x4(addrH, bh[nf2 * 2][0], bh[nf2 * 2][1],
                              bh[nf2 * 2 + 1][0], bh[nf2 * 2 + 1][1]);
                ldm_x4(addrH + PLANE_B, bl[nf2 * 2][0], bl[nf2 * 2][1],
                              bl[nf2 * 2 + 1][0], bl[nf2 * 2 + 1][1]);
            }
            uint32_t ah[4][4], al[4][4];
            #pragma unroll
            for (int mf = 0; mf < 4; mf++) {
                uint32_t addrH = bufb +
                    (uint32_t)(rowA + mf * 16) * 80 + (uint32_t)(kparA + ks * 16) * 2;
                ldm_x4(addrH, ah[mf][0], ah[mf][1], ah[mf][2], ah[mf][3]);
                ldm_x4(addrH + PLANE_B, al[mf][0], al[mf][1], al[mf][2], al[mf][3]);
            }
            // pass-major schedule: 16 independent accumulators between reuses
            #pragma unroll
            for (int mf = 0; mf < 4; mf++)
                #pragma unroll
                for (int nf = 0; nf < 4; nf++)
                    mma_bf16(acc[mf][nf], ah[mf], bh[nf]);   // hi*hi
            #pragma unroll
            for (int mf = 0; mf < 4; mf++)
                #pragma unroll
                for (int nf = 0; nf < 4; nf++)
                    mma_bf16(acc[mf][nf], ah[mf], bl[nf]);   // hi*lo
            #pragma unroll
            for (int mf = 0; mf < 4; mf++)
                #pragma unroll
                for (int nf = 0; nf < 4; nf++)
                    mma_bf16(acc[mf][nf], al[mf], bh[nf]);   // lo*hi
        }
        __syncthreads();
    }

    const int qrow = lane >> 2, qcol = (lane & 3) * 2;
    #pragma unroll
    for (int nf = 0; nf < 4; nf++) {
        const int col = col0 + wn * 32 + nf * 8 + qcol;
        float b0 = bias ? bias[col] : 0.0f;
        float b1 = bias ? bias[col + 1] : 0.0f;
        #pragma unroll
        for (int mf = 0; mf < 4; mf++) {
            #pragma unroll
            for (int h = 0; h < 2; h++) {
                const int row = row0 + wm * 64 + mf * 16 + qrow + h * 8;
                float v0 = acc[mf][nf][h * 2 + 0] + b0;
                float v1 = acc[mf][nf][h * 2 + 1] + b1;
                if (SILU) { v0 = silu_f(v0); v1 = silu_f(v1); }
                size_t gi = (size_t)row * N + col;
                if (SPLIT) {
                    __nv_bfloat16 h0 = __float2bfloat16(v0);
                    __nv_bfloat16 h1 = __float2bfloat16(v1);
                    *reinterpret_cast<__nv_bfloat162*>(Chi + gi) = __nv_bfloat162(h0, h1);
                    *reinterpret_cast<__nv_bfloat162*>(Clo + gi) = __nv_bfloat162(
                        __float2bfloat16(v0 - __bfloat162float(h0)),
                        __float2bfloat16(v1 - __bfloat162float(h1)));
                } else {
                    *reinterpret_cast<float2*>(Cf + gi) = make_float2(v0, v1);
                }
            }
        }
    }
}

// ============ HMMA split-K TN GEMM: C[m,n] += s * sum_k A[k,m]*B[k,n] =============
// A = x planes [Ktot,256], B = Zc planes [Ktot,384]; both node(k)-major -> ldmatrix.trans
static constexpr int TK_PITCH = 272;                // 128 bf16 + 16B pad
static constexpr int TK_PLANE = 32 * TK_PITCH;      // 8704
static constexpr int TK_BUF   = 4 * TK_PLANE;       // 34816
static constexpr int TK_SMEM  = 2 * TK_BUF;         // 69632

__global__ __launch_bounds__(256, 1) void gemm_tn_mma(
    const __nv_bfloat16* __restrict__ Ahi, const __nv_bfloat16* __restrict__ Alo,
    const __nv_bfloat16* __restrict__ Bhi, const __nv_bfloat16* __restrict__ Blo,
    float* __restrict__ C, int Mc, int Nc, int Ktot, int kChunk, float scale) {
    extern __shared__ char smem[];
    const uint32_t sb = smem_u32(smem);
    const int tid = threadIdx.x, wid = tid >> 5, lane = tid & 31;
    const int col0 = blockIdx.x * 128;
    const int row0 = blockIdx.y * 128;
    const int n0 = blockIdx.z * kChunk;
    const int nEnd = min(n0 + kChunk, Ktot);
    const int wm = wid >> 2, wn = wid & 3;

    const __nv_bfloat16* planes[4] = { Ahi, Alo, Bhi, Blo };
    const int baseCol[4] = { row0, row0, col0, col0 };
    const int strideK[4] = { Mc, Mc, Nc, Nc };

    const int lr0 = tid >> 4, lc0 = tid & 15;      // rows 0..15
    const int lr1 = lr0 + 16;

    // NOTE: buffer parity keyed on LOCAL chunk index i (matches consumer).
    auto load_chunk = [&](int i, int k0) {
        const uint32_t bufb = sb + (i & 1) * TK_BUF;
        #pragma unroll
        for (int p = 0; p < 4; p++) {
            const __nv_bfloat16* src = planes[p];
            #pragma unroll
            for (int rep = 0; rep < 2; rep++) {
                int r = rep ? lr1 : lr0;
                int node = k0 + r;
                uint32_t sa = bufb + p * TK_PLANE + r * TK_PITCH + lc0 * 16;
                if (node < nEnd) {
                    CP_ASYNC16(sa, src + (size_t)node * strideK[p] + baseCol[p] + lc0 * 8);
                } else {
                    *reinterpret_cast<uint4*>(smem + (sa - sb)) = make_uint4(0, 0, 0, 0);
                }
            }
        }
        CP_COMMIT();
    };

    float acc[4][4][4];
    #pragma unroll
    for (int i = 0; i < 4; i++)
        #pragma unroll
        for (int j = 0; j < 4; j++)
            #pragma unroll
            for (int q = 0; q < 4; q++) acc[i][j][q] = 0.0f;

    // trans-ldmatrix lane coords
    const int krA = (lane & 7) + ((lane >> 4) << 3);
    const int mcA = ((lane >> 3) & 1) * 8;
    const int krB = (lane & 7) + (((lane >> 3) & 1) << 3);
    const int ncB = (lane >> 4) * 8;

    const int nCh = (nEnd - n0 + 31) >> 5;
    load_chunk(0, n0);

    for (int i = 0; i < nCh; i++) {
        const int k0 = n0 + i * 32;
        if (i + 1 < nCh) {
            load_chunk(i + 1, k0 + 32);
            asm volatile("cp.async.wait_group 1;");
        } else {
            asm volatile("cp.async.wait_group 0;");
        }
        __syncthreads();

        const uint32_t bufb = sb + (i & 1) * TK_BUF;
        #pragma unroll
        for (int ks = 0; ks < 2; ks++) {
            uint32_t bh[4][2], bl[4][2];
            #pragma unroll
            for (int nf2 = 0; nf2 < 2; nf2++) {
                uint32_t aH = bufb + 2 * TK_PLANE +
                    (uint32_t)(krB + ks * 16) * TK_PITCH +
                    (uint32_t)(wn * 32 + nf2 * 16 + ncB) * 2;
                ldm_x4t(aH, bh[nf2 * 2][0], bh[nf2 * 2][1],
                            bh[nf2 * 2 + 1][0], bh[nf2 * 2 + 1][1]);
                ldm_x4t(aH + TK_PLANE, bl[nf2 * 2][0], bl[nf2 * 2][1],
                            bl[nf2 * 2 + 1][0], bl[nf2 * 2 + 1][1]);
            }
            uint32_t ah[4][4], al[4][4];
            #pragma unroll
            for (int mf = 0; mf < 4; mf++) {
                uint32_t aH = bufb +
                    (uint32_t)(krA + ks * 16) * TK_PITCH +
                    (uint32_t)(wm * 64 + mf * 16 + mcA) * 2;
                ldm_x4t(aH, ah[mf][0], ah[mf][1], ah[mf][2], ah[mf][3]);
                ldm_x4t(aH + TK_PLANE, al[mf][0], al[mf][1], al[mf][2], al[mf][3]);
            }
            #pragma unroll
            for (int mf = 0; mf < 4; mf++)
                #pragma unroll
                for (int nf = 0; nf < 4; nf++)
                    mma_bf16(acc[mf][nf], ah[mf], bh[nf]);
            #pragma unroll
            for (int mf = 0; mf < 4; mf++)
                #pragma unroll
                for (int nf = 0; nf < 4; nf++)
                    mma_bf16(acc[mf][nf], ah[mf], bl[nf]);
            #pragma unroll
            for (int mf = 0; mf < 4; mf++)
                #pragma unroll
                for (int nf = 0; nf < 4; nf++)
                    mma_bf16(acc[mf][nf], al[mf], bh[nf]);
        }
        __syncthreads();
    }

    const int qrow = lane >> 2, qcol = (lane & 3) * 2;
    #pragma unroll
    for (int mf = 0; mf < 4; mf++) {
        #pragma unroll
        for (int nf = 0; nf < 4; nf++) {
            #pragma unroll
            for (int h = 0; h < 2; h++) {
                const int row = row0 + wm * 64 + mf * 16 + qrow + h * 8;
                const int col = col0 + wn * 32 + nf * 8 + qcol;
                atomicAdd(&C[(size_t)row * Nc + col], acc[mf][nf][h * 2 + 0] * scale);
                atomicAdd(&C[(size_t)row * Nc + col + 1], acc[mf][nf][h * 2 + 1] * scale);
            }
        }
    }
}

// ---------------- split fp32 -> bf16 hi/lo planes ----------------
__global__ void split_kernel(const float* __restrict__ src,
                             __nv_bfloat16* __restrict__ hi,
                             __nv_bfloat16* __restrict__ lo, int n) {
    int i = blockIdx.x * 256 + threadIdx.x;
    if (i < n) split_store(src[i], hi, lo, i);
}

// ---------------- K0: Zc (emits bf16 planes directly) ----------------
__global__ void zc_kernel(const float* __restrict__ Z,
                          const float* __restrict__ zcw,
                          const float* __restrict__ zcb,
                          __nv_bfloat16* __restrict__ Zch,
                          __nv_bfloat16* __restrict__ Zcl, int NL) {
    int idx = blockIdx.x * 256 + threadIdx.x;
    if (idx >= NL) return;
    int n = idx >> 7, l = idx & 127;
    size_t base = (size_t)n * 384 + l;
    float z0 = Z[base], z1 = Z[base + 128], z2 = Z[base + 256];
    #pragma unroll
    for (int c = 0; c < 3; c++) {
        float v = zcw[c * 3 + 0] * z0 + zcw[c * 3 + 1] * z1 + zcw[c * 3 + 2] * z2 + zcb[c];
        split_store(v, Zch, Zcl, base + (size_t)c * 128);
    }
}

// ---------------- K2: per-edge prep (emits bf16 planes; G1|G2 merged) ----------------
__global__ __launch_bounds__(128) void edge_prep(
    const float* __restrict__ x, const float* __restrict__ Z,
    const int* __restrict__ tar,
    const float* __restrict__ zw1, const float* __restrict__ zb1,
    __nv_bfloat16* __restrict__ Phi, __nv_bfloat16* __restrict__ Plo,
    __nv_bfloat16* __restrict__ ZZhi, __nv_bfloat16* __restrict__ ZZlo,
    __nv_bfloat16* __restrict__ Ghi, __nv_bfloat16* __restrict__ Glo, int E) {
    int e = blockIdx.x;
    int t = threadIdx.x;
    int src = tar[e], dst = tar[E + e];

    __shared__ float sZi[384], sZj[384];
    __shared__ float red[9][4];
    __shared__ float r9[9], rT9[9];

    const float* xs = x + (size_t)src * 256;
    const float* xd = x + (size_t)dst * 256;
    split_store(xs[t] * xd[t],             Phi, Plo, (size_t)e * 256 + t);
    split_store(xs[t + 128] * xd[t + 128], Phi, Plo, (size_t)e * 256 + t + 128);

    const float* Zi = Z + (size_t)src * 384;
    const float* Zj = Z + (size_t)dst * 384;
    for (int i = t; i < 384; i += 128) { sZi[i] = Zi[i]; sZj[i] = Zj[i]; }
    __syncthreads();

    for (int i = t; i < 384; i += 128)
        split_store(sZi[i] * sZj[i], ZZhi, ZZlo, (size_t)e * 384 + i);

    float loc[9];
    #pragma unroll
    for (int c = 0; c < 3; c++)
        #pragma unroll
        for (int d = 0; d < 3; d++)
            loc[c * 3 + d] = sZi[c * 128 + t] * sZj[d * 128 + t];
    #pragma unroll
    for (int off = 16; off > 0; off >>= 1)
        #pragma unroll
        for (int q = 0; q < 9; q++)
            loc[q] += __shfl_down_sync(0xffffffffu, loc[q], off);
    int warp = t >> 5, lane = t & 31;
    if (lane == 0)
        #pragma unroll
        for (int q = 0; q < 9; q++) red[q][warp] = loc[q];
    __syncthreads();
    if (t < 9) r9[t] = (red[t][0] + red[t][1] + red[t][2] + red[t][3]) * (1.0f / 128.0f);
    __syncthreads();
    if (t < 9) { int c = t / 3, d = t % 3; rT9[t] = r9[d * 3 + c]; }
    __syncthreads();

    #pragma unroll
    for (int rep = 0; rep < 2; rep++) {
        int o = t + rep * 128;
        const float* w = zw1 + (size_t)o * 9;
        float s1 = zb1[o], s2 = zb1[o];
        #pragma unroll
        for (int q = 0; q < 9; q++) { s1 += r9[q] * w[q]; s2 += rT9[q] * w[q]; }
        split_store(silu_f(s1), Ghi, Glo, (size_t)e * 256 + o);
        split_store(silu_f(s2), Ghi, Glo, (size_t)(E + e) * 256 + o);
    }
}

// ---------------- K4: 4 LayerNorms + product + final dot ----------------
__global__ __launch_bounds__(256) void final_kernel(
    const float* __restrict__ XIJ, const float* __restrict__ U,
    const float* __restrict__ XZX,
    const float* __restrict__ xg, const float* __restrict__ xb,
    const float* __restrict__ zg, const float* __restrict__ zb,
    const float* __restrict__ zxg, const float* __restrict__ zxb,
    const float* __restrict__ lw, const float* __restrict__ lb,
    float* __restrict__ out, int E) {
    int e = blockIdx.x;
    int t = threadIdx.x;
    const float* pxij = XIJ + (size_t)e * 768;
    const float* pu1  = U   + (size_t)e * 768;
    const float* pu2  = U   + (size_t)(E + e) * 768;
    const float* pxzx = XZX + (size_t)e * 768;

    __shared__ float red[8][8];
    __shared__ float stats[8];
    __shared__ float dred[8];

    float v0[3], v1[3], v2[3], v3[3];
    float s[8];
    #pragma unroll
    for (int q = 0; q < 8; q++) s[q] = 0.0f;
    #pragma unroll
    for (int k = 0; k < 3; k++) {
        int col = t + k * 256;
        float a = pxij[col], b = pu1[col], c = pu2[col], d = pxzx[col];
        v0[k] = a; v1[k] = b; v2[k] = c; v3[k] = d;
        s[0] += a; s[1] += a * a;
        s[2] += b; s[3] += b * b;
        s[4] += c; s[5] += c * c;
        s[6] += d; s[7] += d * d;
    }
    #pragma unroll
    for (int off = 16; off > 0; off >>= 1)
        #pragma unroll
        for (int q = 0; q < 8; q++)
            s[q] += __shfl_down_sync(0xffffffffu, s[q], off);
    int warp = t >> 5, lane = t & 31;
    if (lane == 0)
        #pragma unroll
        for (int q = 0; q < 8; q++) red[q][warp] = s[q];
    __syncthreads();
    if (t < 8) {
        float tot = 0.0f;
        #pragma unroll
        for (int w = 0; w < 8; w++) tot += red[t][w];
        stats[t] = tot;
    }
    __syncthreads();

    const float inv = 1.0f / 768.0f;
    const float eps = 1e-5f;
    float m0 = stats[0] * inv, r0 = rsqrtf(stats[1] * inv - m0 * m0 + eps);
    float m1 = stats[2] * inv, r1 = rsqrtf(stats[3] * inv - m1 * m1 + eps);
    float m2 = stats[4] * inv, r2 = rsqrtf(stats[5] * inv - m2 * m2 + eps);
    float m3 = stats[6] * inv, r3 = rsqrtf(stats[7] * inv - m3 * m3 + eps);

    float dot = 0.0f;
    #pragma unroll
    for (int k = 0; k < 3; k++) {
        int col = t + k * 256;
        float a  = (v0[k] - m0) * r0 * xg[col]  + xb[col];
        float b1 = (v1[k] - m1) * r1 * zg[col]  + zb[col];
        float b2 = (v2[k] - m2) * r2 * zg[col]  + zb[col];
        float c  = (v3[k] - m3) * r3 * zxg[col] + zxb[col];
        dot += a * (b1 + b2) * c * lw[col];
    }
    #pragma unroll
    for (int off = 16; off > 0; off >>= 1)
        dot += __shfl_down_sync(0xffffffffu, dot, off);
    if (lane == 0) dred[warp] = dot;
    __syncthreads();
    if (t == 0) {
        float tot = 0.0f;
        #pragma unroll
        for (int w = 0; w < 8; w++) tot += dred[w];
        out[e] = tot + lb[0];
    }
}

// ---------------- launch ----------------
extern "C" void kernel_launch(void* const* d_in, const int* in_sizes, int n_in,
                              void* d_out, int out_size) {
    const float* x   = (const float*)d_in[0];
    const float* Z   = (const float*)d_in[1];
    const int*   tar = (const int*)  d_in[3];
    const float* xij_w1 = (const float*)d_in[4];
    const float* xij_b1 = (const float*)d_in[5];
    const float* xij_w2 = (const float*)d_in[6];
    const float* xij_b2 = (const float*)d_in[7];
    const float* xij_ln_g = (const float*)d_in[8];
    const float* xij_ln_b = (const float*)d_in[9];
    const float* z_w1 = (const float*)d_in[10];
    const float* z_b1 = (const float*)d_in[11];
    const float* z_w2 = (const float*)d_in[12];
    const float* z_b2 = (const float*)d_in[13];
    const float* z_ln_g = (const float*)d_in[14];
    const float* z_ln_b = (const float*)d_in[15];
    const float* zc_w = (const float*)d_in[16];
    const float* zc_b = (const float*)d_in[17];
    const float* zx_w = (const float*)d_in[18];
    const float* zx_b = (const float*)d_in[19];
    const float* zx_ln_g = (const float*)d_in[20];
    const float* zx_ln_b = (const float*)d_in[21];
    const float* lin_w = (const float*)d_in[22];
    const float* lin_b = (const float*)d_in[23];

    int N = in_sizes[0] / 256;
    int E = in_sizes[3] / 2;
    float zx_coeff = (float)(1.0 / (sqrt((double)N) * 3840.0));

    float *ZXT, *XIJ, *U, *XZX;
    cudaGetSymbolAddress((void**)&ZXT, g_ZXT);
    cudaGetSymbolAddress((void**)&XIJ, g_XIJ);
    cudaGetSymbolAddress((void**)&U,   g_U);
    cudaGetSymbolAddress((void**)&XZX, g_XZX);

    __nv_bfloat16 *xh,*xl,*Zch,*Zcl,*Ph,*Pl,*ZZh,*ZZl,*Gh,*Gl,*Hh,*Hl,*Th,*Tl;
    __nv_bfloat16 *W1h,*W1l,*W2h,*W2l,*ZW2h,*ZW2l,*ZXWh,*ZXWl,*ZXTh,*ZXTl;
    cudaGetSymbolAddress((void**)&xh,  g_xh);  cudaGetSymbolAddress((void**)&xl,  g_xl);
    cudaGetSymbolAddress((void**)&Zch, g_Zch); cudaGetSymbolAddress((void**)&Zcl, g_Zcl);
    cudaGetSymbolAddress((void**)&Ph,  g_Ph);  cudaGetSymbolAddress((void**)&Pl,  g_Pl);
    cudaGetSymbolAddress((void**)&ZZh, g_ZZh); cudaGetSymbolAddress((void**)&ZZl, g_ZZl);
    cudaGetSymbolAddress((void**)&Gh,  g_Gh);  cudaGetSymbolAddress((void**)&Gl,  g_Gl);
    cudaGetSymbolAddress((void**)&Hh,  g_Hh);  cudaGetSymbolAddress((void**)&Hl,  g_Hl);
    cudaGetSymbolAddress((void**)&Th,  g_Th);  cudaGetSymbolAddress((void**)&Tl,  g_Tl);
    cudaGetSymbolAddress((void**)&W1h, g_W1h); cudaGetSymbolAddress((void**)&W1l, g_W1l);
    cudaGetSymbolAddress((void**)&W2h, g_W2h); cudaGetSymbolAddress((void**)&W2l, g_W2l);
    cudaGetSymbolAddress((void**)&ZW2h,g_ZW2h);cudaGetSymbolAddress((void**)&ZW2l,g_ZW2l);
    cudaGetSymbolAddress((void**)&ZXWh,g_ZXWh);cudaGetSymbolAddress((void**)&ZXWl,g_ZXWl);
    cudaGetSymbolAddress((void**)&ZXTh,g_ZXTh);cudaGetSymbolAddress((void**)&ZXTl,g_ZXTl);

    cudaFuncSetAttribute(gemm_mma<true,  true >, cudaFuncAttributeMaxDynamicSharedMemorySize, GEMM_SMEM);
    cudaFuncSetAttribute(gemm_mma<false, false>, cudaFuncAttributeMaxDynamicSharedMemorySize, GEMM_SMEM);
    cudaFuncSetAttribute(gemm_mma<true,  false>, cudaFuncAttributeMaxDynamicSharedMemorySize, GEMM_SMEM);
    cudaFuncSetAttribute(gemm_mma<false, true >, cudaFuncAttributeMaxDynamicSharedMemorySize, GEMM_SMEM);
    cudaFuncSetAttribute(gemm_tn_mma, cudaFuncAttributeMaxDynamicSharedMemorySize, TK_SMEM);

    // weight plane splits
    split_kernel<<<(65536 + 255) / 256, 256>>>(xij_w1, W1h, W1l, 65536);
    split_kernel<<<(196608 + 255) / 256, 256>>>(xij_w2, W2h, W2l, 196608);
    split_kernel<<<(196608 + 255) / 256, 256>>>(z_w2,  ZW2h, ZW2l, 196608);
    split_kernel<<<(196608 + 255) / 256, 256>>>(zx_w,  ZXWh, ZXWl, 196608);

    // zx node path (tensorized split-K)
    int NL = N * 128;
    split_kernel<<<(N * 256 + 255) / 256, 256>>>(x, xh, xl, N * 256);
    zc_kernel<<<(NL + 255) / 256, 256>>>(Z, zc_w, zc_b, Zch, Zcl, NL);
    cudaMemsetAsync(ZXT, 0, 256 * 384 * sizeof(float), 0);
    {
        int kChunk = 4000;   // multiple of 32
        int splits = (N + kChunk - 1) / kChunk;
        dim3 grid(3, 2, splits);
        gemm_tn_mma<<<grid, 256, TK_SMEM>>>(xh, xl, Zch, Zcl, ZXT, 256, 384, N, kChunk, zx_coeff);
    }
    split_kernel<<<(98304 + 255) / 256, 256>>>(ZXT, ZXTh, ZXTl, 98304);

    // edge prep
    edge_prep<<<E, 128>>>(x, Z, tar, z_w1, z_b1, Ph, Pl, ZZh, ZZl, Gh, Gl, E);

    // tensor-core edge GEMMs (HMMA)
    dim3 g256(2, E / 128), g768(6, E / 128), gU(6, 2 * E / 128);
    gemm_mma<true,  true ><<<g256, 256, GEMM_SMEM>>>(Ph, Pl, W1h, W1l, xij_b1,
                                                     nullptr, Hh, Hl, E, 256, 256);
    gemm_mma<false, false><<<g768, 256, GEMM_SMEM>>>(Hh, Hl, W2h, W2l, xij_b2,
                                                     XIJ, nullptr, nullptr, E, 768, 256);
    gemm_mma<true,  false><<<gU,   256, GEMM_SMEM>>>(Gh, Gl, ZW2h, ZW2l, z_b2,
                                                     U, nullptr, nullptr, 2 * E, 768, 256);
    gemm_mma<false, true ><<<g256, 256, GEMM_SMEM>>>(ZZh, ZZl, ZXTh, ZXTl, nullptr,
                                                     nullptr, Th, Tl, E, 256, 384);
    gemm_mma<false, false><<<g768, 256, GEMM_SMEM>>>(Th, Tl, ZXWh, ZXWl, zx_b,
                                                     XZX, nullptr, nullptr, E, 768, 256);

    final_kernel<<<E, 256>>>(XIJ, U, XZX,
                             xij_ln_g, xij_ln_b, z_ln_g, z_ln_b,
                             zx_ln_g, zx_ln_b, lin_w, lin_b,
                             (float*)d_out, E);
}

// round 6
// speedup vs baseline: 1.9596x; 1.0513x over previous
#include <cuda_runtime.h>
#include <cuda_bf16.h>
#include <math.h>
#include <stdint.h>

#define MAXN 100000
#define MAXE 131072

// ---------------- scratch (device globals; no allocation allowed) ----------------
__device__ __align__(128) float g_ZXT[256 * 384];
__device__ __align__(128) float g_XIJ[(size_t)MAXE * 768];
__device__ __align__(128) float g_U[(size_t)2 * MAXE * 768];   // U1 | U2
__device__ __align__(128) float g_XZX[(size_t)MAXE * 768];

// bf16 hi/lo planes
__device__ __align__(128) __nv_bfloat16 g_xh [(size_t)MAXN * 256];
__device__ __align__(128) __nv_bfloat16 g_xl [(size_t)MAXN * 256];
__device__ __align__(128) __nv_bfloat16 g_Zch[(size_t)MAXN * 384];
__device__ __align__(128) __nv_bfloat16 g_Zcl[(size_t)MAXN * 384];
__device__ __align__(128) __nv_bfloat16 g_Ph [(size_t)MAXE * 256];
__device__ __align__(128) __nv_bfloat16 g_Pl [(size_t)MAXE * 256];
__device__ __align__(128) __nv_bfloat16 g_ZZh[(size_t)MAXE * 384];
__device__ __align__(128) __nv_bfloat16 g_ZZl[(size_t)MAXE * 384];
__device__ __align__(128) __nv_bfloat16 g_Gh [(size_t)2 * MAXE * 256];  // G1 | G2
__device__ __align__(128) __nv_bfloat16 g_Gl [(size_t)2 * MAXE * 256];
__device__ __align__(128) __nv_bfloat16 g_Hh [(size_t)MAXE * 256];
__device__ __align__(128) __nv_bfloat16 g_Hl [(size_t)MAXE * 256];
__device__ __align__(128) __nv_bfloat16 g_Th [(size_t)MAXE * 256];
__device__ __align__(128) __nv_bfloat16 g_Tl [(size_t)MAXE * 256];
// weight planes
__device__ __align__(128) __nv_bfloat16 g_W1h[256 * 256],  g_W1l[256 * 256];
__device__ __align__(128) __nv_bfloat16 g_W2h[768 * 256],  g_W2l[768 * 256];
__device__ __align__(128) __nv_bfloat16 g_ZW2h[768 * 256], g_ZW2l[768 * 256];
__device__ __align__(128) __nv_bfloat16 g_ZXWh[768 * 256], g_ZXWl[768 * 256];
__device__ __align__(128) __nv_bfloat16 g_ZXTh[256 * 384], g_ZXTl[256 * 384];

__device__ __forceinline__ float silu_f(float v) { return v / (1.0f + __expf(-v)); }

__device__ __forceinline__ void split_store(float v,
        __nv_bfloat16* __restrict__ hi, __nv_bfloat16* __restrict__ lo, size_t i) {
    __nv_bfloat16 h = __float2bfloat16(v);
    hi[i] = h;
    lo[i] = __float2bfloat16(v - __bfloat162float(h));
}

__device__ __forceinline__ uint32_t smem_u32(const void* p) {
    uint32_t a;
    asm("{ .reg .u64 t; cvta.to.shared.u64 t, %1; cvt.u32.u64 %0, t; }" : "=r"(a) : "l"(p));
    return a;
}

#define CP_ASYNC16(saddr, gptr) \
    asm volatile("cp.async.cg.shared.global [%0], [%1], 16;" :: "r"(saddr), "l"(gptr))
#define CP_COMMIT() asm volatile("cp.async.commit_group;")

__device__ __forceinline__ void ldm_x4(uint32_t addr, uint32_t& r0, uint32_t& r1,
                                       uint32_t& r2, uint32_t& r3) {
    asm volatile("ldmatrix.sync.aligned.m8n8.x4.shared.b16 {%0,%1,%2,%3}, [%4];"
                 : "=r"(r0), "=r"(r1), "=r"(r2), "=r"(r3) : "r"(addr));
}
__device__ __forceinline__ void ldm_x4t(uint32_t addr, uint32_t& r0, uint32_t& r1,
                                        uint32_t& r2, uint32_t& r3) {
    asm volatile("ldmatrix.sync.aligned.m8n8.x4.trans.shared.b16 {%0,%1,%2,%3}, [%4];"
                 : "=r"(r0), "=r"(r1), "=r"(r2), "=r"(r3) : "r"(addr));
}
__device__ __forceinline__ void mma_bf16(float* c, const uint32_t* a, const uint32_t* b) {
    asm volatile(
        "mma.sync.aligned.m16n8k16.row.col.f32.bf16.bf16.f32 "
        "{%0,%1,%2,%3}, {%4,%5,%6,%7}, {%8,%9}, {%0,%1,%2,%3};"
        : "+f"(c[0]), "+f"(c[1]), "+f"(c[2]), "+f"(c[3])
        : "r"(a[0]), "r"(a[1]), "r"(a[2]), "r"(a[3]), "r"(b[0]), "r"(b[1]));
}

// ================= HMMA GEMM: C[m,n] = act(sum_k A[m,k]*B[n,k] + bias[n]) ==========
// 256x128 CTA tile, BK=32, 8 warps (4x2), warp tile 64x64, 3-pass bf16 hi/lo.
static constexpr int PLANE_A  = 20480;  // 256 rows * 80B
static constexpr int PLANE_Bs = 10240;  // 128 rows * 80B
static constexpr int OFF_AH = 0, OFF_AL = 20480, OFF_BH = 40960, OFF_BL = 51200;
static constexpr int BUF_B   = 61440;
static constexpr int GEMM_SMEM = 2 * BUF_B;  // 122880

template <bool SILU, bool SPLIT>
__global__ __launch_bounds__(256, 1) void gemm_mma(
    const __nv_bfloat16* __restrict__ Ahi, const __nv_bfloat16* __restrict__ Alo,
    const __nv_bfloat16* __restrict__ Bhi, const __nv_bfloat16* __restrict__ Blo,
    const float* __restrict__ bias,
    float* __restrict__ Cf,
    __nv_bfloat16* __restrict__ Chi, __nv_bfloat16* __restrict__ Clo,
    int M, int N, int K) {
    extern __shared__ char smem[];
    const uint32_t sb = smem_u32(smem);
    const int tid = threadIdx.x, wid = tid >> 5, lane = tid & 31;
    const int col0 = blockIdx.x * 128;
    const int row0 = blockIdx.y * 256;
    const int wm = wid & 3, wn = wid >> 2;   // warp tile origin: (wm*64, wn*64)

    const int ldr = tid >> 2, ldc = tid & 3;

    auto load_chunk = [&](int i) {
        const uint32_t bufb = sb + (i & 1) * BUF_B;
        const int k0 = i * 32;
        #pragma unroll
        for (int g = 0; g < 4; g++) {
            int r = ldr + g * 64;
            CP_ASYNC16(bufb + OFF_AH + r * 80 + ldc * 16,
                       Ahi + (size_t)(row0 + r) * K + k0 + ldc * 8);
            CP_ASYNC16(bufb + OFF_AL + r * 80 + ldc * 16,
                       Alo + (size_t)(row0 + r) * K + k0 + ldc * 8);
        }
        #pragma unroll
        for (int g = 0; g < 2; g++) {
            int r = ldr + g * 64;
            CP_ASYNC16(bufb + OFF_BH + r * 80 + ldc * 16,
                       Bhi + (size_t)(col0 + r) * K + k0 + ldc * 8);
            CP_ASYNC16(bufb + OFF_BL + r * 80 + ldc * 16,
                       Blo + (size_t)(col0 + r) * K + k0 + ldc * 8);
        }
        CP_COMMIT();
    };

    float acc[4][8][4];
    #pragma unroll
    for (int i = 0; i < 4; i++)
        #pragma unroll
        for (int j = 0; j < 8; j++)
            #pragma unroll
            for (int q = 0; q < 4; q++) acc[i][j][q] = 0.0f;

    const int rowA = wm * 64 + (lane & 15);
    const int kparA = (lane >> 4) * 8;
    const int rowB = wn * 64 + (lane & 7) + ((lane >> 4) << 3);
    const int kparB = ((lane >> 3) & 1) * 8;

    const int nCh = K >> 5;
    load_chunk(0);

    for (int i = 0; i < nCh; i++) {
        if (i + 1 < nCh) {
            load_chunk(i + 1);
            asm volatile("cp.async.wait_group 1;");
        } else {
            asm volatile("cp.async.wait_group 0;");
        }
        __syncthreads();

        const uint32_t bufb = sb + (i & 1) * BUF_B;
        #pragma unroll
        for (int ks = 0; ks < 2; ks++) {
            uint32_t ah[4][4], al[4][4];
            #pragma unroll
            for (int mf = 0; mf < 4; mf++) {
                uint32_t addrH = bufb + OFF_AH +
                    (uint32_t)(rowA + mf * 16) * 80 + (uint32_t)(kparA + ks * 16) * 2;
                ldm_x4(addrH, ah[mf][0], ah[mf][1], ah[mf][2], ah[mf][3]);
                ldm_x4(addrH + (OFF_AL - OFF_AH),
                       al[mf][0], al[mf][1], al[mf][2], al[mf][3]);
            }
            #pragma unroll
            for (int nf2 = 0; nf2 < 4; nf2++) {
                uint32_t bh[2][2], bl[2][2];
                uint32_t addrB = bufb + OFF_BH +
                    (uint32_t)(rowB + nf2 * 16) * 80 + (uint32_t)(kparB + ks * 16) * 2;
                ldm_x4(addrB, bh[0][0], bh[0][1], bh[1][0], bh[1][1]);
                ldm_x4(addrB + (OFF_BL - OFF_BH),
                       bl[0][0], bl[0][1], bl[1][0], bl[1][1]);
                // pass-major within pair: 8 independent accs between reuses
                #pragma unroll
                for (int mf = 0; mf < 4; mf++)
                    #pragma unroll
                    for (int j = 0; j < 2; j++)
                        mma_bf16(acc[mf][nf2 * 2 + j], ah[mf], bh[j]);   // hi*hi
                #pragma unroll
                for (int mf = 0; mf < 4; mf++)
                    #pragma unroll
                    for (int j = 0; j < 2; j++)
                        mma_bf16(acc[mf][nf2 * 2 + j], ah[mf], bl[j]);   // hi*lo
                #pragma unroll
                for (int mf = 0; mf < 4; mf++)
                    #pragma unroll
                    for (int j = 0; j < 2; j++)
                        mma_bf16(acc[mf][nf2 * 2 + j], al[mf], bh[j]);   // lo*hi
            }
        }
        __syncthreads();
    }

    const int qrow = lane >> 2, qcol = (lane & 3) * 2;
    #pragma unroll
    for (int nf = 0; nf < 8; nf++) {
        const int col = col0 + wn * 64 + nf * 8 + qcol;
        float b0 = bias ? bias[col] : 0.0f;
        float b1 = bias ? bias[col + 1] : 0.0f;
        #pragma unroll
        for (int mf = 0; mf < 4; mf++) {
            #pragma unroll
            for (int h = 0; h < 2; h++) {
                const int row = row0 + wm * 64 + mf * 16 + qrow + h * 8;
                float v0 = acc[mf][nf][h * 2 + 0] + b0;
                float v1 = acc[mf][nf][h * 2 + 1] + b1;
                if (SILU) { v0 = silu_f(v0); v1 = silu_f(v1); }
                size_t gi = (size_t)row * N + col;
                if (SPLIT) {
                    __nv_bfloat16 h0 = __float2bfloat16(v0);
                    __nv_bfloat16 h1 = __float2bfloat16(v1);
                    *reinterpret_cast<__nv_bfloat162*>(Chi + gi) = __nv_bfloat162(h0, h1);
                    *reinterpret_cast<__nv_bfloat162*>(Clo + gi) = __nv_bfloat162(
                        __float2bfloat16(v0 - __bfloat162float(h0)),
                        __float2bfloat16(v1 - __bfloat162float(h1)));
                } else {
                    *reinterpret_cast<float2*>(Cf + gi) = make_float2(v0, v1);
                }
            }
        }
    }
}

// ============ HMMA split-K TN GEMM: C[m,n] += s * sum_k A[k,m]*B[k,n] =============
static constexpr int TK_PITCH = 272;
static constexpr int TK_PLANE = 32 * TK_PITCH;
static constexpr int TK_BUF   = 4 * TK_PLANE;
static constexpr int TK_SMEM  = 2 * TK_BUF;

__global__ __launch_bounds__(256, 1) void gemm_tn_mma(
    const __nv_bfloat16* __restrict__ Ahi, const __nv_bfloat16* __restrict__ Alo,
    const __nv_bfloat16* __restrict__ Bhi, const __nv_bfloat16* __restrict__ Blo,
    float* __restrict__ C, int Mc, int Nc, int Ktot, int kChunk, float scale) {
    extern __shared__ char smem[];
    const uint32_t sb = smem_u32(smem);
    const int tid = threadIdx.x, wid = tid >> 5, lane = tid & 31;
    const int col0 = blockIdx.x * 128;
    const int row0 = blockIdx.y * 128;
    const int n0 = blockIdx.z * kChunk;
    const int nEnd = min(n0 + kChunk, Ktot);
    const int wm = wid >> 2, wn = wid & 3;

    const __nv_bfloat16* planes[4] = { Ahi, Alo, Bhi, Blo };
    const int baseCol[4] = { row0, row0, col0, col0 };
    const int strideK[4] = { Mc, Mc, Nc, Nc };

    const int lr0 = tid >> 4, lc0 = tid & 15;
    const int lr1 = lr0 + 16;

    auto load_chunk = [&](int i, int k0) {
        const uint32_t bufb = sb + (i & 1) * TK_BUF;
        #pragma unroll
        for (int p = 0; p < 4; p++) {
            const __nv_bfloat16* src = planes[p];
            #pragma unroll
            for (int rep = 0; rep < 2; rep++) {
                int r = rep ? lr1 : lr0;
                int node = k0 + r;
                uint32_t sa = bufb + p * TK_PLANE + r * TK_PITCH + lc0 * 16;
                if (node < nEnd) {
                    CP_ASYNC16(sa, src + (size_t)node * strideK[p] + baseCol[p] + lc0 * 8);
                } else {
                    *reinterpret_cast<uint4*>(smem + (sa - sb)) = make_uint4(0, 0, 0, 0);
                }
            }
        }
        CP_COMMIT();
    };

    float acc[4][4][4];
    #pragma unroll
    for (int i = 0; i < 4; i++)
        #pragma unroll
        for (int j = 0; j < 4; j++)
            #pragma unroll
            for (int q = 0; q < 4; q++) acc[i][j][q] = 0.0f;

    const int krA = (lane & 7) + ((lane >> 4) << 3);
    const int mcA = ((lane >> 3) & 1) * 8;
    const int krB = (lane & 7) + (((lane >> 3) & 1) << 3);
    const int ncB = (lane >> 4) * 8;

    const int nCh = (nEnd - n0 + 31) >> 5;
    load_chunk(0, n0);

    for (int i = 0; i < nCh; i++) {
        const int k0 = n0 + i * 32;
        if (i + 1 < nCh) {
            load_chunk(i + 1, k0 + 32);
            asm volatile("cp.async.wait_group 1;");
        } else {
            asm volatile("cp.async.wait_group 0;");
        }
        __syncthreads();

        const uint32_t bufb = sb + (i & 1) * TK_BUF;
        #pragma unroll
        for (int ks = 0; ks < 2; ks++) {
            uint32_t bh[4][2], bl[4][2];
            #pragma unroll
            for (int nf2 = 0; nf2 < 2; nf2++) {
                uint32_t aH = bufb + 2 * TK_PLANE +
                    (uint32_t)(krB + ks * 16) * TK_PITCH +
                    (uint32_t)(wn * 32 + nf2 * 16 + ncB) * 2;
                ldm_x4t(aH, bh[nf2 * 2][0], bh[nf2 * 2][1],
                            bh[nf2 * 2 + 1][0], bh[nf2 * 2 + 1][1]);
                ldm_x4t(aH + TK_PLANE, bl[nf2 * 2][0], bl[nf2 * 2][1],
                            bl[nf2 * 2 + 1][0], bl[nf2 * 2 + 1][1]);
            }
            uint32_t ah[4][4], al[4][4];
            #pragma unroll
            for (int mf = 0; mf < 4; mf++) {
                uint32_t aH = bufb +
                    (uint32_t)(krA + ks * 16) * TK_PITCH +
                    (uint32_t)(wm * 64 + mf * 16 + mcA) * 2;
                ldm_x4t(aH, ah[mf][0], ah[mf][1], ah[mf][2], ah[mf][3]);
                ldm_x4t(aH + TK_PLANE, al[mf][0], al[mf][1], al[mf][2], al[mf][3]);
            }
            #pragma unroll
            for (int mf = 0; mf < 4; mf++)
                #pragma unroll
                for (int nf = 0; nf < 4; nf++)
                    mma_bf16(acc[mf][nf], ah[mf], bh[nf]);
            #pragma unroll
            for (int mf = 0; mf < 4; mf++)
                #pragma unroll
                for (int nf = 0; nf < 4; nf++)
                    mma_bf16(acc[mf][nf], ah[mf], bl[nf]);
            #pragma unroll
            for (int mf = 0; mf < 4; mf++)
                #pragma unroll
                for (int nf = 0; nf < 4; nf++)
                    mma_bf16(acc[mf][nf], al[mf], bh[nf]);
        }
        __syncthreads();
    }

    const int qrow = lane >> 2, qcol = (lane & 3) * 2;
    #pragma unroll
    for (int mf = 0; mf < 4; mf++) {
        #pragma unroll
        for (int nf = 0; nf < 4; nf++) {
            #pragma unroll
            for (int h = 0; h < 2; h++) {
                const int row = row0 + wm * 64 + mf * 16 + qrow + h * 8;
                const int col = col0 + wn * 32 + nf * 8 + qcol;
                atomicAdd(&C[(size_t)row * Nc + col], acc[mf][nf][h * 2 + 0] * scale);
                atomicAdd(&C[(size_t)row * Nc + col + 1], acc[mf][nf][h * 2 + 1] * scale);
            }
        }
    }
}

// ---------------- split fp32 -> bf16 hi/lo planes ----------------
__global__ void split_kernel(const float* __restrict__ src,
                             __nv_bfloat16* __restrict__ hi,
                             __nv_bfloat16* __restrict__ lo, int n) {
    int i = blockIdx.x * 256 + threadIdx.x;
    if (i < n) split_store(src[i], hi, lo, i);
}

// ---------------- K0: Zc (emits bf16 planes directly) ----------------
__global__ void zc_kernel(const float* __restrict__ Z,
                          const float* __restrict__ zcw,
                          const float* __restrict__ zcb,
                          __nv_bfloat16* __restrict__ Zch,
                          __nv_bfloat16* __restrict__ Zcl, int NL) {
    int idx = blockIdx.x * 256 + threadIdx.x;
    if (idx >= NL) return;
    int n = idx >> 7, l = idx & 127;
    size_t base = (size_t)n * 384 + l;
    float z0 = Z[base], z1 = Z[base + 128], z2 = Z[base + 256];
    #pragma unroll
    for (int c = 0; c < 3; c++) {
        float v = zcw[c * 3 + 0] * z0 + zcw[c * 3 + 1] * z1 + zcw[c * 3 + 2] * z2 + zcb[c];
        split_store(v, Zch, Zcl, base + (size_t)c * 128);
    }
}

// ---------------- K2: per-edge prep ----------------
__global__ __launch_bounds__(128) void edge_prep(
    const float* __restrict__ x, const float* __restrict__ Z,
    const int* __restrict__ tar,
    const float* __restrict__ zw1, const float* __restrict__ zb1,
    __nv_bfloat16* __restrict__ Phi, __nv_bfloat16* __restrict__ Plo,
    __nv_bfloat16* __restrict__ ZZhi, __nv_bfloat16* __restrict__ ZZlo,
    __nv_bfloat16* __restrict__ Ghi, __nv_bfloat16* __restrict__ Glo, int E) {
    int e = blockIdx.x;
    int t = threadIdx.x;
    int src = tar[e], dst = tar[E + e];

    __shared__ float sZi[384], sZj[384];
    __shared__ float red[9][4];
    __shared__ float r9[9], rT9[9];

    const float* xs = x + (size_t)src * 256;
    const float* xd = x + (size_t)dst * 256;
    split_store(xs[t] * xd[t],             Phi, Plo, (size_t)e * 256 + t);
    split_store(xs[t + 128] * xd[t + 128], Phi, Plo, (size_t)e * 256 + t + 128);

    const float* Zi = Z + (size_t)src * 384;
    const float* Zj = Z + (size_t)dst * 384;
    for (int i = t; i < 384; i += 128) { sZi[i] = Zi[i]; sZj[i] = Zj[i]; }
    __syncthreads();

    for (int i = t; i < 384; i += 128)
        split_store(sZi[i] * sZj[i], ZZhi, ZZlo, (size_t)e * 384 + i);

    float loc[9];
    #pragma unroll
    for (int c = 0; c < 3; c++)
        #pragma unroll
        for (int d = 0; d < 3; d++)
            loc[c * 3 + d] = sZi[c * 128 + t] * sZj[d * 128 + t];
    #pragma unroll
    for (int off = 16; off > 0; off >>= 1)
        #pragma unroll
        for (int q = 0; q < 9; q++)
            loc[q] += __shfl_down_sync(0xffffffffu, loc[q], off);
    int warp = t >> 5, lane = t & 31;
    if (lane == 0)
        #pragma unroll
        for (int q = 0; q < 9; q++) red[q][warp] = loc[q];
    __syncthreads();
    if (t < 9) r9[t] = (red[t][0] + red[t][1] + red[t][2] + red[t][3]) * (1.0f / 128.0f);
    __syncthreads();
    if (t < 9) { int c = t / 3, d = t % 3; rT9[t] = r9[d * 3 + c]; }
    __syncthreads();

    #pragma unroll
    for (int rep = 0; rep < 2; rep++) {
        int o = t + rep * 128;
        const float* w = zw1 + (size_t)o * 9;
        float s1 = zb1[o], s2 = zb1[o];
        #pragma unroll
        for (int q = 0; q < 9; q++) { s1 += r9[q] * w[q]; s2 += rT9[q] * w[q]; }
        split_store(silu_f(s1), Ghi, Glo, (size_t)e * 256 + o);
        split_store(silu_f(s2), Ghi, Glo, (size_t)(E + e) * 256 + o);
    }
}

// ---------------- K4: 4 LayerNorms + product + final dot ----------------
__global__ __launch_bounds__(256) void final_kernel(
    const float* __restrict__ XIJ, const float* __restrict__ U,
    const float* __restrict__ XZX,
    const float* __restrict__ xg, const float* __restrict__ xb,
    const float* __restrict__ zg, const float* __restrict__ zb,
    const float* __restrict__ zxg, const float* __restrict__ zxb,
    const float* __restrict__ lw, const float* __restrict__ lb,
    float* __restrict__ out, int E) {
    int e = blockIdx.x;
    int t = threadIdx.x;
    const float* pxij = XIJ + (size_t)e * 768;
    const float* pu1  = U   + (size_t)e * 768;
    const float* pu2  = U   + (size_t)(E + e) * 768;
    const float* pxzx = XZX + (size_t)e * 768;

    __shared__ float red[8][8];
    __shared__ float stats[8];
    __shared__ float dred[8];

    float v0[3], v1[3], v2[3], v3[3];
    float s[8];
    #pragma unroll
    for (int q = 0; q < 8; q++) s[q] = 0.0f;
    #pragma unroll
    for (int k = 0; k < 3; k++) {
        int col = t + k * 256;
        float a = pxij[col], b = pu1[col], c = pu2[col], d = pxzx[col];
        v0[k] = a; v1[k] = b; v2[k] = c; v3[k] = d;
        s[0] += a; s[1] += a * a;
        s[2] += b; s[3] += b * b;
        s[4] += c; s[5] += c * c;
        s[6] += d; s[7] += d * d;
    }
    #pragma unroll
    for (int off = 16; off > 0; off >>= 1)
        #pragma unroll
        for (int q = 0; q < 8; q++)
            s[q] += __shfl_down_sync(0xffffffffu, s[q], off);
    int warp = t >> 5, lane = t & 31;
    if (lane == 0)
        #pragma unroll
        for (int q = 0; q < 8; q++) red[q][warp] = s[q];
    __syncthreads();
    if (t < 8) {
        float tot = 0.0f;
        #pragma unroll
        for (int w = 0; w < 8; w++) tot += red[t][w];
        stats[t] = tot;
    }
    __syncthreads();

    const float inv = 1.0f / 768.0f;
    const float eps = 1e-5f;
    float m0 = stats[0] * inv, r0 = rsqrtf(stats[1] * inv - m0 * m0 + eps);
    float m1 = stats[2] * inv, r1 = rsqrtf(stats[3] * inv - m1 * m1 + eps);
    float m2 = stats[4] * inv, r2 = rsqrtf(stats[5] * inv - m2 * m2 + eps);
    float m3 = stats[6] * inv, r3 = rsqrtf(stats[7] * inv - m3 * m3 + eps);

    float dot = 0.0f;
    #pragma unroll
    for (int k = 0; k < 3; k++) {
        int col = t + k * 256;
        float a  = (v0[k] - m0) * r0 * xg[col]  + xb[col];
        float b1 = (v1[k] - m1) * r1 * zg[col]  + zb[col];
        float b2 = (v2[k] - m2) * r2 * zg[col]  + zb[col];
        float c  = (v3[k] - m3) * r3 * zxg[col] + zxb[col];
        dot += a * (b1 + b2) * c * lw[col];
    }
    #pragma unroll
    for (int off = 16; off > 0; off >>= 1)
        dot += __shfl_down_sync(0xffffffffu, dot, off);
    if (lane == 0) dred[warp] = dot;
    __syncthreads();
    if (t == 0) {
        float tot = 0.0f;
        #pragma unroll
        for (int w = 0; w < 8; w++) tot += dred[w];
        out[e] = tot + lb[0];
    }
}

// ---------------- launch ----------------
extern "C" void kernel_launch(void* const* d_in, const int* in_sizes, int n_in,
                              void* d_out, int out_size) {
    const float* x   = (const float*)d_in[0];
    const float* Z   = (const float*)d_in[1];
    const int*   tar = (const int*)  d_in[3];
    const float* xij_w1 = (const float*)d_in[4];
    const float* xij_b1 = (const float*)d_in[5];
    const float* xij_w2 = (const float*)d_in[6];
    const float* xij_b2 = (const float*)d_in[7];
    const float* xij_ln_g = (const float*)d_in[8];
    const float* xij_ln_b = (const float*)d_in[9];
    const float* z_w1 = (const float*)d_in[10];
    const float* z_b1 = (const float*)d_in[11];
    const float* z_w2 = (const float*)d_in[12];
    const float* z_b2 = (const float*)d_in[13];
    const float* z_ln_g = (const float*)d_in[14];
    const float* z_ln_b = (const float*)d_in[15];
    const float* zc_w = (const float*)d_in[16];
    const float* zc_b = (const float*)d_in[17];
    const float* zx_w = (const float*)d_in[18];
    const float* zx_b = (const float*)d_in[19];
    const float* zx_ln_g = (const float*)d_in[20];
    const float* zx_ln_b = (const float*)d_in[21];
    const float* lin_w = (const float*)d_in[22];
    const float* lin_b = (const float*)d_in[23];

    int N = in_sizes[0] / 256;
    int E = in_sizes[3] / 2;
    float zx_coeff = (float)(1.0 / (sqrt((double)N) * 3840.0));

    float *ZXT, *XIJ, *U, *XZX;
    cudaGetSymbolAddress((void**)&ZXT, g_ZXT);
    cudaGetSymbolAddress((void**)&XIJ, g_XIJ);
    cudaGetSymbolAddress((void**)&U,   g_U);
    cudaGetSymbolAddress((void**)&XZX, g_XZX);

    __nv_bfloat16 *xh,*xl,*Zch,*Zcl,*Ph,*Pl,*ZZh,*ZZl,*Gh,*Gl,*Hh,*Hl,*Th,*Tl;
    __nv_bfloat16 *W1h,*W1l,*W2h,*W2l,*ZW2h,*ZW2l,*ZXWh,*ZXWl,*ZXTh,*ZXTl;
    cudaGetSymbolAddress((void**)&xh,  g_xh);  cudaGetSymbolAddress((void**)&xl,  g_xl);
    cudaGetSymbolAddress((void**)&Zch, g_Zch); cudaGetSymbolAddress((void**)&Zcl, g_Zcl);
    cudaGetSymbolAddress((void**)&Ph,  g_Ph);  cudaGetSymbolAddress((void**)&Pl,  g_Pl);
    cudaGetSymbolAddress((void**)&ZZh, g_ZZh); cudaGetSymbolAddress((void**)&ZZl, g_ZZl);
    cudaGetSymbolAddress((void**)&Gh,  g_Gh);  cudaGetSymbolAddress((void**)&Gl,  g_Gl);
    cudaGetSymbolAddress((void**)&Hh,  g_Hh);  cudaGetSymbolAddress((void**)&Hl,  g_Hl);
    cudaGetSymbolAddress((void**)&Th,  g_Th);  cudaGetSymbolAddress((void**)&Tl,  g_Tl);
    cudaGetSymbolAddress((void**)&W1h, g_W1h); cudaGetSymbolAddress((void**)&W1l, g_W1l);
    cudaGetSymbolAddress((void**)&W2h, g_W2h); cudaGetSymbolAddress((void**)&W2l, g_W2l);
    cudaGetSymbolAddress((void**)&ZW2h,g_ZW2h);cudaGetSymbolAddress((void**)&ZW2l,g_ZW2l);
    cudaGetSymbolAddress((void**)&ZXWh,g_ZXWh);cudaGetSymbolAddress((void**)&ZXWl,g_ZXWl);
    cudaGetSymbolAddress((void**)&ZXTh,g_ZXTh);cudaGetSymbolAddress((void**)&ZXTl,g_ZXTl);

    cudaFuncSetAttribute(gemm_mma<true,  true >, cudaFuncAttributeMaxDynamicSharedMemorySize, GEMM_SMEM);
    cudaFuncSetAttribute(gemm_mma<false, false>, cudaFuncAttributeMaxDynamicSharedMemorySize, GEMM_SMEM);
    cudaFuncSetAttribute(gemm_mma<true,  false>, cudaFuncAttributeMaxDynamicSharedMemorySize, GEMM_SMEM);
    cudaFuncSetAttribute(gemm_mma<false, true >, cudaFuncAttributeMaxDynamicSharedMemorySize, GEMM_SMEM);
    cudaFuncSetAttribute(gemm_tn_mma, cudaFuncAttributeMaxDynamicSharedMemorySize, TK_SMEM);

    // weight plane splits
    split_kernel<<<(65536 + 255) / 256, 256>>>(xij_w1, W1h, W1l, 65536);
    split_kernel<<<(196608 + 255) / 256, 256>>>(xij_w2, W2h, W2l, 196608);
    split_kernel<<<(196608 + 255) / 256, 256>>>(z_w2,  ZW2h, ZW2l, 196608);
    split_kernel<<<(196608 + 255) / 256, 256>>>(zx_w,  ZXWh, ZXWl, 196608);

    // zx node path (tensorized split-K)
    int NL = N * 128;
    split_kernel<<<(N * 256 + 255) / 256, 256>>>(x, xh, xl, N * 256);
    zc_kernel<<<(NL + 255) / 256, 256>>>(Z, zc_w, zc_b, Zch, Zcl, NL);
    cudaMemsetAsync(ZXT, 0, 256 * 384 * sizeof(float), 0);
    {
        int kChunk = 4000;
        int splits = (N + kChunk - 1) / kChunk;
        dim3 grid(3, 2, splits);
        gemm_tn_mma<<<grid, 256, TK_SMEM>>>(xh, xl, Zch, Zcl, ZXT, 256, 384, N, kChunk, zx_coeff);
    }
    split_kernel<<<(98304 + 255) / 256, 256>>>(ZXT, ZXTh, ZXTl, 98304);

    // edge prep
    edge_prep<<<E, 128>>>(x, Z, tar, z_w1, z_b1, Ph, Pl, ZZh, ZZl, Gh, Gl, E);

    // tensor-core edge GEMMs (HMMA, 256-row tiles)
    dim3 g256(2, E / 256), g768(6, E / 256), gU(6, 2 * E / 256);
    gemm_mma<true,  true ><<<g256, 256, GEMM_SMEM>>>(Ph, Pl, W1h, W1l, xij_b1,
                                                     nullptr, Hh, Hl, E, 256, 256);
    gemm_mma<false, false><<<g768, 256, GEMM_SMEM>>>(Hh, Hl, W2h, W2l, xij_b2,
                                                     XIJ, nullptr, nullptr, E, 768, 256);
    gemm_mma<true,  false><<<gU,   256, GEMM_SMEM>>>(Gh, Gl, ZW2h, ZW2l, z_b2,
                                                     U, nullptr, nullptr, 2 * E, 768, 256);
    gemm_mma<false, true ><<<g256, 256, GEMM_SMEM>>>(ZZh, ZZl, ZXTh, ZXTl, nullptr,
                                                     nullptr, Th, Tl, E, 256, 384);
    gemm_mma<false, false><<<g768, 256, GEMM_SMEM>>>(Th, Tl, ZXWh, ZXWl, zx_b,
                                                     XZX, nullptr, nullptr, E, 768, 256);

    final_kernel<<<E, 256>>>(XIJ, U, XZX,
                             xij_ln_g, xij_ln_b, z_ln_g, z_ln_b,
                             zx_ln_g, zx_ln_b, lin_w, lin_b,
                             (float*)d_out, E);
}

// round 7
// speedup vs baseline: 2.3488x; 1.1986x over previous
#include <cuda_runtime.h>
#include <cuda_fp16.h>
#include <math.h>
#include <stdint.h>

#define MAXN 100000
#define MAXE 131072

// ---------------- scratch (device globals; no allocation allowed) ----------------
__device__ __align__(128) float g_ZXT[256 * 384];            // fp32 accumulator
__device__ __align__(128) __half g_XIJ[(size_t)MAXE * 768];
__device__ __align__(128) __half g_U[(size_t)2 * MAXE * 768];   // U1 | U2
__device__ __align__(128) __half g_XZX[(size_t)MAXE * 768];

// fp16 hi/lo planes (A-side, exact) and single-plane weights (B-side)
__device__ __align__(128) __half g_xh [(size_t)MAXN * 256];
__device__ __align__(128) __half g_xl [(size_t)MAXN * 256];
__device__ __align__(128) __half g_Zc [(size_t)MAXN * 384];     // single fp16
__device__ __align__(128) __half g_Ph [(size_t)MAXE * 256];
__device__ __align__(128) __half g_Pl [(size_t)MAXE * 256];
__device__ __align__(128) __half g_ZZh[(size_t)MAXE * 384];
__device__ __align__(128) __half g_ZZl[(size_t)MAXE * 384];
__device__ __align__(128) __half g_Gh [(size_t)2 * MAXE * 256]; // G1 | G2
__device__ __align__(128) __half g_Gl [(size_t)2 * MAXE * 256];
__device__ __align__(128) __half g_Hh [(size_t)MAXE * 256];
__device__ __align__(128) __half g_Hl [(size_t)MAXE * 256];
__device__ __align__(128) __half g_Th [(size_t)MAXE * 256];
__device__ __align__(128) __half g_Tl [(size_t)MAXE * 256];
// weights, single fp16 plane
__device__ __align__(128) __half g_W1 [256 * 256];
__device__ __align__(128) __half g_W2 [768 * 256];
__device__ __align__(128) __half g_ZW2[768 * 256];
__device__ __align__(128) __half g_ZXW[768 * 256];
__device__ __align__(128) __half g_ZXTq[256 * 384];

__device__ __forceinline__ float silu_f(float v) { return v / (1.0f + __expf(-v)); }

__device__ __forceinline__ void split_store_h(float v,
        __half* __restrict__ hi, __half* __restrict__ lo, size_t i) {
    __half h = __float2half(v);
    hi[i] = h;
    lo[i] = __float2half(v - __half2float(h));
}

__device__ __forceinline__ uint32_t smem_u32(const void* p) {
    uint32_t a;
    asm("{ .reg .u64 t; cvta.to.shared.u64 t, %1; cvt.u32.u64 %0, t; }" : "=r"(a) : "l"(p));
    return a;
}

#define CP_ASYNC16(saddr, gptr) \
    asm volatile("cp.async.cg.shared.global [%0], [%1], 16;" :: "r"(saddr), "l"(gptr))
#define CP_COMMIT() asm volatile("cp.async.commit_group;")

__device__ __forceinline__ void ldm_x4(uint32_t addr, uint32_t& r0, uint32_t& r1,
                                       uint32_t& r2, uint32_t& r3) {
    asm volatile("ldmatrix.sync.aligned.m8n8.x4.shared.b16 {%0,%1,%2,%3}, [%4];"
                 : "=r"(r0), "=r"(r1), "=r"(r2), "=r"(r3) : "r"(addr));
}
__device__ __forceinline__ void ldm_x4t(uint32_t addr, uint32_t& r0, uint32_t& r1,
                                        uint32_t& r2, uint32_t& r3) {
    asm volatile("ldmatrix.sync.aligned.m8n8.x4.trans.shared.b16 {%0,%1,%2,%3}, [%4];"
                 : "=r"(r0), "=r"(r1), "=r"(r2), "=r"(r3) : "r"(addr));
}
__device__ __forceinline__ void mma_fp16(float* c, const uint32_t* a, const uint32_t* b) {
    asm volatile(
        "mma.sync.aligned.m16n8k16.row.col.f32.f16.f16.f32 "
        "{%0,%1,%2,%3}, {%4,%5,%6,%7}, {%8,%9}, {%0,%1,%2,%3};"
        : "+f"(c[0]), "+f"(c[1]), "+f"(c[2]), "+f"(c[3])
        : "r"(a[0]), "r"(a[1]), "r"(a[2]), "r"(a[3]), "r"(b[0]), "r"(b[1]));
}

// ================= HMMA GEMM: C[m,n] = act(sum_k A[m,k]*B[n,k] + bias[n]) ==========
// 256x128 CTA tile, BK=32, 8 warps (4x2), warp tile 64x64.
// A fp16 hi/lo (2 planes), B single fp16 -> 2 MMA passes (A_hi*B + A_lo*B).
static constexpr int OFF_AH = 0, OFF_AL = 20480, OFF_B = 40960;
static constexpr int BUF_B   = 51200;
static constexpr int GEMM_SMEM = 2 * BUF_B;  // 102400

template <bool SILU, bool SPLIT>
__global__ __launch_bounds__(256, 1) void gemm_mma(
    const __half* __restrict__ Ahi, const __half* __restrict__ Alo,
    const __half* __restrict__ B,
    const float* __restrict__ bias,
    __half* __restrict__ Cf,
    __half* __restrict__ Chi, __half* __restrict__ Clo,
    int M, int N, int K) {
    extern __shared__ char smem[];
    const uint32_t sb = smem_u32(smem);
    const int tid = threadIdx.x, wid = tid >> 5, lane = tid & 31;
    const int col0 = blockIdx.x * 128;
    const int row0 = blockIdx.y * 256;
    const int wm = wid & 3, wn = wid >> 2;

    const int ldr = tid >> 2, ldc = tid & 3;

    auto load_chunk = [&](int i) {
        const uint32_t bufb = sb + (i & 1) * BUF_B;
        const int k0 = i * 32;
        #pragma unroll
        for (int g = 0; g < 4; g++) {
            int r = ldr + g * 64;
            CP_ASYNC16(bufb + OFF_AH + r * 80 + ldc * 16,
                       Ahi + (size_t)(row0 + r) * K + k0 + ldc * 8);
            CP_ASYNC16(bufb + OFF_AL + r * 80 + ldc * 16,
                       Alo + (size_t)(row0 + r) * K + k0 + ldc * 8);
        }
        #pragma unroll
        for (int g = 0; g < 2; g++) {
            int r = ldr + g * 64;
            CP_ASYNC16(bufb + OFF_B + r * 80 + ldc * 16,
                       B + (size_t)(col0 + r) * K + k0 + ldc * 8);
        }
        CP_COMMIT();
    };

    float acc[4][8][4];
    #pragma unroll
    for (int i = 0; i < 4; i++)
        #pragma unroll
        for (int j = 0; j < 8; j++)
            #pragma unroll
            for (int q = 0; q < 4; q++) acc[i][j][q] = 0.0f;

    const int rowA = wm * 64 + (lane & 15);
    const int kparA = (lane >> 4) * 8;
    const int rowB = wn * 64 + (lane & 7) + ((lane >> 4) << 3);
    const int kparB = ((lane >> 3) & 1) * 8;

    const int nCh = K >> 5;
    load_chunk(0);

    for (int i = 0; i < nCh; i++) {
        if (i + 1 < nCh) {
            load_chunk(i + 1);
            asm volatile("cp.async.wait_group 1;");
        } else {
            asm volatile("cp.async.wait_group 0;");
        }
        __syncthreads();

        const uint32_t bufb = sb + (i & 1) * BUF_B;
        #pragma unroll
        for (int ks = 0; ks < 2; ks++) {
            uint32_t ah[4][4], al[4][4];
            #pragma unroll
            for (int mf = 0; mf < 4; mf++) {
                uint32_t addrH = bufb + OFF_AH +
                    (uint32_t)(rowA + mf * 16) * 80 + (uint32_t)(kparA + ks * 16) * 2;
                ldm_x4(addrH, ah[mf][0], ah[mf][1], ah[mf][2], ah[mf][3]);
                ldm_x4(addrH + (OFF_AL - OFF_AH),
                       al[mf][0], al[mf][1], al[mf][2], al[mf][3]);
            }
            #pragma unroll
            for (int nf2 = 0; nf2 < 4; nf2++) {
                uint32_t bh[2][2];
                uint32_t addrB = bufb + OFF_B +
                    (uint32_t)(rowB + nf2 * 16) * 80 + (uint32_t)(kparB + ks * 16) * 2;
                ldm_x4(addrB, bh[0][0], bh[0][1], bh[1][0], bh[1][1]);
                // pass-major: 8 independent accumulators between reuses
                #pragma unroll
                for (int mf = 0; mf < 4; mf++)
                    #pragma unroll
                    for (int j = 0; j < 2; j++)
                        mma_fp16(acc[mf][nf2 * 2 + j], ah[mf], bh[j]);   // hi*B
                #pragma unroll
                for (int mf = 0; mf < 4; mf++)
                    #pragma unroll
                    for (int j = 0; j < 2; j++)
                        mma_fp16(acc[mf][nf2 * 2 + j], al[mf], bh[j]);   // lo*B
            }
        }
        __syncthreads();
    }

    const int qrow = lane >> 2, qcol = (lane & 3) * 2;
    #pragma unroll
    for (int nf = 0; nf < 8; nf++) {
        const int col = col0 + wn * 64 + nf * 8 + qcol;
        float b0 = bias ? bias[col] : 0.0f;
        float b1 = bias ? bias[col + 1] : 0.0f;
        #pragma unroll
        for (int mf = 0; mf < 4; mf++) {
            #pragma unroll
            for (int h = 0; h < 2; h++) {
                const int row = row0 + wm * 64 + mf * 16 + qrow + h * 8;
                float v0 = acc[mf][nf][h * 2 + 0] + b0;
                float v1 = acc[mf][nf][h * 2 + 1] + b1;
                if (SILU) { v0 = silu_f(v0); v1 = silu_f(v1); }
                size_t gi = (size_t)row * N + col;
                if (SPLIT) {
                    __half h0 = __float2half(v0);
                    __half h1 = __float2half(v1);
                    *reinterpret_cast<__half2*>(Chi + gi) = __halves2half2(h0, h1);
                    *reinterpret_cast<__half2*>(Clo + gi) = __halves2half2(
                        __float2half(v0 - __half2float(h0)),
                        __float2half(v1 - __half2float(h1)));
                } else {
                    *reinterpret_cast<__half2*>(Cf + gi) =
                        __halves2half2(__float2half(v0), __float2half(v1));
                }
            }
        }
    }
}

// ============ HMMA split-K TN GEMM: C[m,n] += s * sum_k A[k,m]*B[k,n] =============
// A = x hi/lo [Ktot,256], B = Zc single [Ktot,384]; node(k)-major -> ldmatrix.trans
static constexpr int TK_PITCH = 272;
static constexpr int TK_PLANE = 32 * TK_PITCH;      // 8704
static constexpr int TK_BUF   = 3 * TK_PLANE;       // 26112
static constexpr int TK_SMEM  = 2 * TK_BUF;         // 52224

__global__ __launch_bounds__(256, 1) void gemm_tn_mma(
    const __half* __restrict__ Ahi, const __half* __restrict__ Alo,
    const __half* __restrict__ B,
    float* __restrict__ C, int Mc, int Nc, int Ktot, int kChunk, float scale) {
    extern __shared__ char smem[];
    const uint32_t sb = smem_u32(smem);
    const int tid = threadIdx.x, wid = tid >> 5, lane = tid & 31;
    const int col0 = blockIdx.x * 128;
    const int row0 = blockIdx.y * 128;
    const int n0 = blockIdx.z * kChunk;
    const int nEnd = min(n0 + kChunk, Ktot);
    const int wm = wid >> 2, wn = wid & 3;

    const __half* planes[3] = { Ahi, Alo, B };
    const int baseCol[3] = { row0, row0, col0 };
    const int strideK[3] = { Mc, Mc, Nc };

    const int lr0 = tid >> 4, lc0 = tid & 15;
    const int lr1 = lr0 + 16;

    auto load_chunk = [&](int i, int k0) {
        const uint32_t bufb = sb + (i & 1) * TK_BUF;
        #pragma unroll
        for (int p = 0; p < 3; p++) {
            const __half* src = planes[p];
            #pragma unroll
            for (int rep = 0; rep < 2; rep++) {
                int r = rep ? lr1 : lr0;
                int node = k0 + r;
                uint32_t sa = bufb + p * TK_PLANE + r * TK_PITCH + lc0 * 16;
                if (node < nEnd) {
                    CP_ASYNC16(sa, src + (size_t)node * strideK[p] + baseCol[p] + lc0 * 8);
                } else {
                    *reinterpret_cast<uint4*>(smem + (sa - sb)) = make_uint4(0, 0, 0, 0);
                }
            }
        }
        CP_COMMIT();
    };

    float acc[4][4][4];
    #pragma unroll
    for (int i = 0; i < 4; i++)
        #pragma unroll
        for (int j = 0; j < 4; j++)
            #pragma unroll
            for (int q = 0; q < 4; q++) acc[i][j][q] = 0.0f;

    const int krA = (lane & 7) + ((lane >> 4) << 3);
    const int mcA = ((lane >> 3) & 1) * 8;
    const int krB = (lane & 7) + (((lane >> 3) & 1) << 3);
    const int ncB = (lane >> 4) * 8;

    const int nCh = (nEnd - n0 + 31) >> 5;
    load_chunk(0, n0);

    for (int i = 0; i < nCh; i++) {
        const int k0 = n0 + i * 32;
        if (i + 1 < nCh) {
            load_chunk(i + 1, k0 + 32);
            asm volatile("cp.async.wait_group 1;");
        } else {
            asm volatile("cp.async.wait_group 0;");
        }
        __syncthreads();

        const uint32_t bufb = sb + (i & 1) * TK_BUF;
        #pragma unroll
        for (int ks = 0; ks < 2; ks++) {
            uint32_t bh[4][2];
            #pragma unroll
            for (int nf2 = 0; nf2 < 2; nf2++) {
                uint32_t aH = bufb + 2 * TK_PLANE +
                    (uint32_t)(krB + ks * 16) * TK_PITCH +
                    (uint32_t)(wn * 32 + nf2 * 16 + ncB) * 2;
                ldm_x4t(aH, bh[nf2 * 2][0], bh[nf2 * 2][1],
                            bh[nf2 * 2 + 1][0], bh[nf2 * 2 + 1][1]);
            }
            uint32_t ah[4][4], al[4][4];
            #pragma unroll
            for (int mf = 0; mf < 4; mf++) {
                uint32_t aH = bufb +
                    (uint32_t)(krA + ks * 16) * TK_PITCH +
                    (uint32_t)(wm * 64 + mf * 16 + mcA) * 2;
                ldm_x4t(aH, ah[mf][0], ah[mf][1], ah[mf][2], ah[mf][3]);
                ldm_x4t(aH + TK_PLANE, al[mf][0], al[mf][1], al[mf][2], al[mf][3]);
            }
            #pragma unroll
            for (int mf = 0; mf < 4; mf++)
                #pragma unroll
                for (int nf = 0; nf < 4; nf++)
                    mma_fp16(acc[mf][nf], ah[mf], bh[nf]);
            #pragma unroll
            for (int mf = 0; mf < 4; mf++)
                #pragma unroll
                for (int nf = 0; nf < 4; nf++)
                    mma_fp16(acc[mf][nf], al[mf], bh[nf]);
        }
        __syncthreads();
    }

    const int qrow = lane >> 2, qcol = (lane & 3) * 2;
    #pragma unroll
    for (int mf = 0; mf < 4; mf++) {
        #pragma unroll
        for (int nf = 0; nf < 4; nf++) {
            #pragma unroll
            for (int h = 0; h < 2; h++) {
                const int row = row0 + wm * 64 + mf * 16 + qrow + h * 8;
                const int col = col0 + wn * 32 + nf * 8 + qcol;
                atomicAdd(&C[(size_t)row * Nc + col], acc[mf][nf][h * 2 + 0] * scale);
                atomicAdd(&C[(size_t)row * Nc + col + 1], acc[mf][nf][h * 2 + 1] * scale);
            }
        }
    }
}

// ---------------- fp32 -> fp16 hi/lo split ----------------
__global__ void split_kernel(const float* __restrict__ src,
                             __half* __restrict__ hi,
                             __half* __restrict__ lo, int n) {
    int i = blockIdx.x * 256 + threadIdx.x;
    if (i < n) split_store_h(src[i], hi, lo, i);
}
// ---------------- fp32 -> fp16 single convert ----------------
__global__ void convert_kernel(const float* __restrict__ src,
                               __half* __restrict__ dst, int n) {
    int i = blockIdx.x * 256 + threadIdx.x;
    if (i < n) dst[i] = __float2half(src[i]);
}

// ---------------- K0: Zc (emits single fp16 plane) ----------------
__global__ void zc_kernel(const float* __restrict__ Z,
                          const float* __restrict__ zcw,
                          const float* __restrict__ zcb,
                          __half* __restrict__ Zc, int NL) {
    int idx = blockIdx.x * 256 + threadIdx.x;
    if (idx >= NL) return;
    int n = idx >> 7, l = idx & 127;
    size_t base = (size_t)n * 384 + l;
    float z0 = Z[base], z1 = Z[base + 128], z2 = Z[base + 256];
    #pragma unroll
    for (int c = 0; c < 3; c++) {
        float v = zcw[c * 3 + 0] * z0 + zcw[c * 3 + 1] * z1 + zcw[c * 3 + 2] * z2 + zcb[c];
        Zc[base + (size_t)c * 128] = __float2half(v);
    }
}

// ---------------- K2: per-edge prep (emits fp16 hi/lo planes) ----------------
__global__ __launch_bounds__(128) void edge_prep(
    const float* __restrict__ x, const float* __restrict__ Z,
    const int* __restrict__ tar,
    const float* __restrict__ zw1, const float* __restrict__ zb1,
    __half* __restrict__ Phi, __half* __restrict__ Plo,
    __half* __restrict__ ZZhi, __half* __restrict__ ZZlo,
    __half* __restrict__ Ghi, __half* __restrict__ Glo, int E) {
    int e = blockIdx.x;
    int t = threadIdx.x;
    int src = tar[e], dst = tar[E + e];

    __shared__ float sZi[384], sZj[384];
    __shared__ float red[9][4];
    __shared__ float r9[9], rT9[9];

    const float* xs = x + (size_t)src * 256;
    const float* xd = x + (size_t)dst * 256;
    split_store_h(xs[t] * xd[t],             Phi, Plo, (size_t)e * 256 + t);
    split_store_h(xs[t + 128] * xd[t + 128], Phi, Plo, (size_t)e * 256 + t + 128);

    const float* Zi = Z + (size_t)src * 384;
    const float* Zj = Z + (size_t)dst * 384;
    for (int i = t; i < 384; i += 128) { sZi[i] = Zi[i]; sZj[i] = Zj[i]; }
    __syncthreads();

    for (int i = t; i < 384; i += 128)
        split_store_h(sZi[i] * sZj[i], ZZhi, ZZlo, (size_t)e * 384 + i);

    float loc[9];
    #pragma unroll
    for (int c = 0; c < 3; c++)
        #pragma unroll
        for (int d = 0; d < 3; d++)
            loc[c * 3 + d] = sZi[c * 128 + t] * sZj[d * 128 + t];
    #pragma unroll
    for (int off = 16; off > 0; off >>= 1)
        #pragma unroll
        for (int q = 0; q < 9; q++)
            loc[q] += __shfl_down_sync(0xffffffffu, loc[q], off);
    int warp = t >> 5, lane = t & 31;
    if (lane == 0)
        #pragma unroll
        for (int q = 0; q < 9; q++) red[q][warp] = loc[q];
    __syncthreads();
    if (t < 9) r9[t] = (red[t][0] + red[t][1] + red[t][2] + red[t][3]) * (1.0f / 128.0f);
    __syncthreads();
    if (t < 9) { int c = t / 3, d = t % 3; rT9[t] = r9[d * 3 + c]; }
    __syncthreads();

    #pragma unroll
    for (int rep = 0; rep < 2; rep++) {
        int o = t + rep * 128;
        const float* w = zw1 + (size_t)o * 9;
        float s1 = zb1[o], s2 = zb1[o];
        #pragma unroll
        for (int q = 0; q < 9; q++) { s1 += r9[q] * w[q]; s2 += rT9[q] * w[q]; }
        split_store_h(silu_f(s1), Ghi, Glo, (size_t)e * 256 + o);
        split_store_h(silu_f(s2), Ghi, Glo, (size_t)(E + e) * 256 + o);
    }
}

// ---------------- K4: 4 LayerNorms + product + final dot ----------------
__global__ __launch_bounds__(256) void final_kernel(
    const __half* __restrict__ XIJ, const __half* __restrict__ U,
    const __half* __restrict__ XZX,
    const float* __restrict__ xg, const float* __restrict__ xb,
    const float* __restrict__ zg, const float* __restrict__ zb,
    const float* __restrict__ zxg, const float* __restrict__ zxb,
    const float* __restrict__ lw, const float* __restrict__ lb,
    float* __restrict__ out, int E) {
    int e = blockIdx.x;
    int t = threadIdx.x;
    const __half* pxij = XIJ + (size_t)e * 768;
    const __half* pu1  = U   + (size_t)e * 768;
    const __half* pu2  = U   + (size_t)(E + e) * 768;
    const __half* pxzx = XZX + (size_t)e * 768;

    __shared__ float red[8][8];
    __shared__ float stats[8];
    __shared__ float dred[8];

    float v0[3], v1[3], v2[3], v3[3];
    float s[8];
    #pragma unroll
    for (int q = 0; q < 8; q++) s[q] = 0.0f;
    #pragma unroll
    for (int k = 0; k < 3; k++) {
        int col = t + k * 256;
        float a = __half2float(pxij[col]), b = __half2float(pu1[col]);
        float c = __half2float(pu2[col]),  d = __half2float(pxzx[col]);
        v0[k] = a; v1[k] = b; v2[k] = c; v3[k] = d;
        s[0] += a; s[1] += a * a;
        s[2] += b; s[3] += b * b;
        s[4] += c; s[5] += c * c;
        s[6] += d; s[7] += d * d;
    }
    #pragma unroll
    for (int off = 16; off > 0; off >>= 1)
        #pragma unroll
        for (int q = 0; q < 8; q++)
            s[q] += __shfl_down_sync(0xffffffffu, s[q], off);
    int warp = t >> 5, lane = t & 31;
    if (lane == 0)
        #pragma unroll
        for (int q = 0; q < 8; q++) red[q][warp] = s[q];
    __syncthreads();
    if (t < 8) {
        float tot = 0.0f;
        #pragma unroll
        for (int w = 0; w < 8; w++) tot += red[t][w];
        stats[t] = tot;
    }
    __syncthreads();

    const float inv = 1.0f / 768.0f;
    const float eps = 1e-5f;
    float m0 = stats[0] * inv, r0 = rsqrtf(stats[1] * inv - m0 * m0 + eps);
    float m1 = stats[2] * inv, r1 = rsqrtf(stats[3] * inv - m1 * m1 + eps);
    float m2 = stats[4] * inv, r2 = rsqrtf(stats[5] * inv - m2 * m2 + eps);
    float m3 = stats[6] * inv, r3 = rsqrtf(stats[7] * inv - m3 * m3 + eps);

    float dot = 0.0f;
    #pragma unroll
    for (int k = 0; k < 3; k++) {
        int col = t + k * 256;
        float a  = (v0[k] - m0) * r0 * xg[col]  + xb[col];
        float b1 = (v1[k] - m1) * r1 * zg[col]  + zb[col];
        float b2 = (v2[k] - m2) * r2 * zg[col]  + zb[col];
        float c  = (v3[k] - m3) * r3 * zxg[col] + zxb[col];
        dot += a * (b1 + b2) * c * lw[col];
    }
    #pragma unroll
    for (int off = 16; off > 0; off >>= 1)
        dot += __shfl_down_sync(0xffffffffu, dot, off);
    if (lane == 0) dred[warp] = dot;
    __syncthreads();
    if (t == 0) {
        float tot = 0.0f;
        #pragma unroll
        for (int w = 0; w < 8; w++) tot += dred[w];
        out[e] = tot + lb[0];
    }
}

// ---------------- launch ----------------
extern "C" void kernel_launch(void* const* d_in, const int* in_sizes, int n_in,
                              void* d_out, int out_size) {
    const float* x   = (const float*)d_in[0];
    const float* Z   = (const float*)d_in[1];
    const int*   tar = (const int*)  d_in[3];
    const float* xij_w1 = (const float*)d_in[4];
    const float* xij_b1 = (const float*)d_in[5];
    const float* xij_w2 = (const float*)d_in[6];
    const float* xij_b2 = (const float*)d_in[7];
    const float* xij_ln_g = (const float*)d_in[8];
    const float* xij_ln_b = (const float*)d_in[9];
    const float* z_w1 = (const float*)d_in[10];
    const float* z_b1 = (const float*)d_in[11];
    const float* z_w2 = (const float*)d_in[12];
    const float* z_b2 = (const float*)d_in[13];
    const float* z_ln_g = (const float*)d_in[14];
    const float* z_ln_b = (const float*)d_in[15];
    const float* zc_w = (const float*)d_in[16];
    const float* zc_b = (const float*)d_in[17];
    const float* zx_w = (const float*)d_in[18];
    const float* zx_b = (const float*)d_in[19];
    const float* zx_ln_g = (const float*)d_in[20];
    const float* zx_ln_b = (const float*)d_in[21];
    const float* lin_w = (const float*)d_in[22];
    const float* lin_b = (const float*)d_in[23];

    int N = in_sizes[0] / 256;
    int E = in_sizes[3] / 2;
    float zx_coeff = (float)(1.0 / (sqrt((double)N) * 3840.0));

    float* ZXT;
    cudaGetSymbolAddress((void**)&ZXT, g_ZXT);
    __half *XIJ, *U, *XZX;
    cudaGetSymbolAddress((void**)&XIJ, g_XIJ);
    cudaGetSymbolAddress((void**)&U,   g_U);
    cudaGetSymbolAddress((void**)&XZX, g_XZX);

    __half *xh,*xl,*Zc,*Ph,*Pl,*ZZh,*ZZl,*Gh,*Gl,*Hh,*Hl,*Th,*Tl;
    __half *W1,*W2,*ZW2,*ZXW,*ZXTq;
    cudaGetSymbolAddress((void**)&xh,  g_xh);  cudaGetSymbolAddress((void**)&xl,  g_xl);
    cudaGetSymbolAddress((void**)&Zc,  g_Zc);
    cudaGetSymbolAddress((void**)&Ph,  g_Ph);  cudaGetSymbolAddress((void**)&Pl,  g_Pl);
    cudaGetSymbolAddress((void**)&ZZh, g_ZZh); cudaGetSymbolAddress((void**)&ZZl, g_ZZl);
    cudaGetSymbolAddress((void**)&Gh,  g_Gh);  cudaGetSymbolAddress((void**)&Gl,  g_Gl);
    cudaGetSymbolAddress((void**)&Hh,  g_Hh);  cudaGetSymbolAddress((void**)&Hl,  g_Hl);
    cudaGetSymbolAddress((void**)&Th,  g_Th);  cudaGetSymbolAddress((void**)&Tl,  g_Tl);
    cudaGetSymbolAddress((void**)&W1,  g_W1);  cudaGetSymbolAddress((void**)&W2,  g_W2);
    cudaGetSymbolAddress((void**)&ZW2, g_ZW2); cudaGetSymbolAddress((void**)&ZXW, g_ZXW);
    cudaGetSymbolAddress((void**)&ZXTq,g_ZXTq);

    cudaFuncSetAttribute(gemm_mma<true,  true >, cudaFuncAttributeMaxDynamicSharedMemorySize, GEMM_SMEM);
    cudaFuncSetAttribute(gemm_mma<false, false>, cudaFuncAttributeMaxDynamicSharedMemorySize, GEMM_SMEM);
    cudaFuncSetAttribute(gemm_mma<true,  false>, cudaFuncAttributeMaxDynamicSharedMemorySize, GEMM_SMEM);
    cudaFuncSetAttribute(gemm_mma<false, true >, cudaFuncAttributeMaxDynamicSharedMemorySize, GEMM_SMEM);
    cudaFuncSetAttribute(gemm_tn_mma, cudaFuncAttributeMaxDynamicSharedMemorySize, TK_SMEM);

    // weight converts (single fp16 plane)
    convert_kernel<<<(65536 + 255) / 256, 256>>>(xij_w1, W1, 65536);
    convert_kernel<<<(196608 + 255) / 256, 256>>>(xij_w2, W2, 196608);
    convert_kernel<<<(196608 + 255) / 256, 256>>>(z_w2,  ZW2, 196608);
    convert_kernel<<<(196608 + 255) / 256, 256>>>(zx_w,  ZXW, 196608);

    // zx node path (tensorized split-K)
    int NL = N * 128;
    split_kernel<<<(N * 256 + 255) / 256, 256>>>(x, xh, xl, N * 256);
    zc_kernel<<<(NL + 255) / 256, 256>>>(Z, zc_w, zc_b, Zc, NL);
    cudaMemsetAsync(ZXT, 0, 256 * 384 * sizeof(float), 0);
    {
        int kChunk = 4000;
        int splits = (N + kChunk - 1) / kChunk;
        dim3 grid(3, 2, splits);
        gemm_tn_mma<<<grid, 256, TK_SMEM>>>(xh, xl, Zc, ZXT, 256, 384, N, kChunk, zx_coeff);
    }
    convert_kernel<<<(98304 + 255) / 256, 256>>>(ZXT, ZXTq, 98304);

    // edge prep
    edge_prep<<<E, 128>>>(x, Z, tar, z_w1, z_b1, Ph, Pl, ZZh, ZZl, Gh, Gl, E);

    // tensor-core edge GEMMs (HMMA fp16, 2-pass)
    dim3 g256(2, E / 256), g768(6, E / 256), gU(6, 2 * E / 256);
    gemm_mma<true,  true ><<<g256, 256, GEMM_SMEM>>>(Ph, Pl, W1, xij_b1,
                                                     nullptr, Hh, Hl, E, 256, 256);
    gemm_mma<false, false><<<g768, 256, GEMM_SMEM>>>(Hh, Hl, W2, xij_b2,
                                                     XIJ, nullptr, nullptr, E, 768, 256);
    gemm_mma<true,  false><<<gU,   256, GEMM_SMEM>>>(Gh, Gl, ZW2, z_b2,
                                                     U, nullptr, nullptr, 2 * E, 768, 256);
    gemm_mma<false, true ><<<g256, 256, GEMM_SMEM>>>(ZZh, ZZl, ZXTq, nullptr,
                                                     nullptr, Th, Tl, E, 256, 384);
    gemm_mma<false, false><<<g768, 256, GEMM_SMEM>>>(Th, Tl, ZXW, zx_b,
                                                     XZX, nullptr, nullptr, E, 768, 256);

    final_kernel<<<E, 256>>>(XIJ, U, XZX,
                             xij_ln_g, xij_ln_b, z_ln_g, z_ln_b,
                             zx_ln_g, zx_ln_b, lin_w, lin_b,
                             (float*)d_out, E);
}

// round 8
// speedup vs baseline: 2.6272x; 1.1185x over previous
#include <cuda_runtime.h>
#include <cuda_fp16.h>
#include <math.h>
#include <stdint.h>

#define MAXN 100000
#define MAXE 131072

// ---------------- scratch (device globals; no allocation allowed) ----------------
__device__ __align__(128) float g_ZXT[256 * 384];
__device__ __align__(128) float g_XIJ[(size_t)MAXE * 768];
__device__ __align__(128) float g_U[(size_t)2 * MAXE * 768];   // U1 | U2 (fp32)
__device__ __align__(128) float g_XZX[(size_t)MAXE * 768];

// fp16 planes
__device__ __align__(128) __half g_xh [(size_t)MAXN * 256];
__device__ __align__(128) __half g_xl [(size_t)MAXN * 256];
__device__ __align__(128) __half g_Zc [(size_t)MAXN * 384];
__device__ __align__(128) __half g_Ph [(size_t)MAXE * 256];     // single plane
__device__ __align__(128) __half g_ZZh[(size_t)MAXE * 384];     // single plane
__device__ __align__(128) __half g_Gh [(size_t)2 * MAXE * 256]; // single plane, G1|G2
__device__ __align__(128) __half g_Hh [(size_t)MAXE * 256];     // hi/lo (exact)
__device__ __align__(128) __half g_Hl [(size_t)MAXE * 256];
__device__ __align__(128) __half g_Th [(size_t)MAXE * 256];     // hi/lo (exact)
__device__ __align__(128) __half g_Tl [(size_t)MAXE * 256];
// weights, single fp16 plane
__device__ __align__(128) __half g_W1 [256 * 256];
__device__ __align__(128) __half g_W2 [768 * 256];
__device__ __align__(128) __half g_ZW2[768 * 256];
__device__ __align__(128) __half g_ZXW[768 * 256];
__device__ __align__(128) __half g_ZXTq[256 * 384];

__device__ __forceinline__ float silu_f(float v) { return v / (1.0f + __expf(-v)); }

__device__ __forceinline__ void split_store_h(float v,
        __half* __restrict__ hi, __half* __restrict__ lo, size_t i) {
    __half h = __float2half(v);
    hi[i] = h;
    lo[i] = __float2half(v - __half2float(h));
}

__device__ __forceinline__ uint32_t smem_u32(const void* p) {
    uint32_t a;
    asm("{ .reg .u64 t; cvta.to.shared.u64 t, %1; cvt.u32.u64 %0, t; }" : "=r"(a) : "l"(p));
    return a;
}

#define CP_ASYNC16(saddr, gptr) \
    asm volatile("cp.async.cg.shared.global [%0], [%1], 16;" :: "r"(saddr), "l"(gptr))
#define CP_COMMIT() asm volatile("cp.async.commit_group;")

__device__ __forceinline__ void ldm_x4(uint32_t addr, uint32_t& r0, uint32_t& r1,
                                       uint32_t& r2, uint32_t& r3) {
    asm volatile("ldmatrix.sync.aligned.m8n8.x4.shared.b16 {%0,%1,%2,%3}, [%4];"
                 : "=r"(r0), "=r"(r1), "=r"(r2), "=r"(r3) : "r"(addr));
}
__device__ __forceinline__ void ldm_x4t(uint32_t addr, uint32_t& r0, uint32_t& r1,
                                        uint32_t& r2, uint32_t& r3) {
    asm volatile("ldmatrix.sync.aligned.m8n8.x4.trans.shared.b16 {%0,%1,%2,%3}, [%4];"
                 : "=r"(r0), "=r"(r1), "=r"(r2), "=r"(r3) : "r"(addr));
}
__device__ __forceinline__ void mma_fp16(float* c, const uint32_t* a, const uint32_t* b) {
    asm volatile(
        "mma.sync.aligned.m16n8k16.row.col.f32.f16.f16.f32 "
        "{%0,%1,%2,%3}, {%4,%5,%6,%7}, {%8,%9}, {%0,%1,%2,%3};"
        : "+f"(c[0]), "+f"(c[1]), "+f"(c[2]), "+f"(c[3])
        : "r"(a[0]), "r"(a[1]), "r"(a[2]), "r"(a[3]), "r"(b[0]), "r"(b[1]));
}

// ================= HMMA GEMM: C[m,n] = act(sum_k A[m,k]*B[n,k] + bias[n]) ==========
// 256x128 CTA tile, BK=32, 8 warps (4x2), warp tile 64x64.
// LO: A has hi+lo planes -> 2 MMA passes; else single plane -> 1 pass.
// SPLIT: output written as fp16 hi/lo planes; else fp32.
template <bool LO, bool SILU, bool SPLIT>
__global__ __launch_bounds__(256, 1) void gemm_mma(
    const __half* __restrict__ Ahi, const __half* __restrict__ Alo,
    const __half* __restrict__ B,
    const float* __restrict__ bias,
    float* __restrict__ Cf,
    __half* __restrict__ Chi, __half* __restrict__ Clo,
    int M, int N, int K) {
    constexpr int OFF_AL = 20480;
    constexpr int OFF_B  = LO ? 40960 : 20480;
    constexpr int BUF    = LO ? 51200 : 30720;
    extern __shared__ char smem[];
    const uint32_t sb = smem_u32(smem);
    const int tid = threadIdx.x, wid = tid >> 5, lane = tid & 31;
    const int col0 = blockIdx.x * 128;
    const int row0 = blockIdx.y * 256;
    const int wm = wid & 3, wn = wid >> 2;

    const int ldr = tid >> 2, ldc = tid & 3;

    auto load_chunk = [&](int i) {
        const uint32_t bufb = sb + (i & 1) * BUF;
        const int k0 = i * 32;
        #pragma unroll
        for (int g = 0; g < 4; g++) {
            int r = ldr + g * 64;
            CP_ASYNC16(bufb + r * 80 + ldc * 16,
                       Ahi + (size_t)(row0 + r) * K + k0 + ldc * 8);
            if (LO)
                CP_ASYNC16(bufb + OFF_AL + r * 80 + ldc * 16,
                           Alo + (size_t)(row0 + r) * K + k0 + ldc * 8);
        }
        #pragma unroll
        for (int g = 0; g < 2; g++) {
            int r = ldr + g * 64;
            CP_ASYNC16(bufb + OFF_B + r * 80 + ldc * 16,
                       B + (size_t)(col0 + r) * K + k0 + ldc * 8);
        }
        CP_COMMIT();
    };

    float acc[4][8][4];
    #pragma unroll
    for (int i = 0; i < 4; i++)
        #pragma unroll
        for (int j = 0; j < 8; j++)
            #pragma unroll
            for (int q = 0; q < 4; q++) acc[i][j][q] = 0.0f;

    const int rowA = wm * 64 + (lane & 15);
    const int kparA = (lane >> 4) * 8;
    const int rowB = wn * 64 + (lane & 7) + ((lane >> 4) << 3);
    const int kparB = ((lane >> 3) & 1) * 8;

    const int nCh = K >> 5;
    load_chunk(0);

    for (int i = 0; i < nCh; i++) {
        if (i + 1 < nCh) {
            load_chunk(i + 1);
            asm volatile("cp.async.wait_group 1;");
        } else {
            asm volatile("cp.async.wait_group 0;");
        }
        __syncthreads();

        const uint32_t bufb = sb + (i & 1) * BUF;
        #pragma unroll
        for (int ks = 0; ks < 2; ks++) {
            uint32_t ah[4][4], al[4][4];
            #pragma unroll
            for (int mf = 0; mf < 4; mf++) {
                uint32_t addrH = bufb +
                    (uint32_t)(rowA + mf * 16) * 80 + (uint32_t)(kparA + ks * 16) * 2;
                ldm_x4(addrH, ah[mf][0], ah[mf][1], ah[mf][2], ah[mf][3]);
                if (LO)
                    ldm_x4(addrH + OFF_AL,
                           al[mf][0], al[mf][1], al[mf][2], al[mf][3]);
            }
            #pragma unroll
            for (int nf2 = 0; nf2 < 4; nf2++) {
                uint32_t bh[2][2];
                uint32_t addrB = bufb + OFF_B +
                    (uint32_t)(rowB + nf2 * 16) * 80 + (uint32_t)(kparB + ks * 16) * 2;
                ldm_x4(addrB, bh[0][0], bh[0][1], bh[1][0], bh[1][1]);
                #pragma unroll
                for (int mf = 0; mf < 4; mf++)
                    #pragma unroll
                    for (int j = 0; j < 2; j++)
                        mma_fp16(acc[mf][nf2 * 2 + j], ah[mf], bh[j]);   // hi*B
                if (LO) {
                    #pragma unroll
                    for (int mf = 0; mf < 4; mf++)
                        #pragma unroll
                        for (int j = 0; j < 2; j++)
                            mma_fp16(acc[mf][nf2 * 2 + j], al[mf], bh[j]); // lo*B
                }
            }
        }
        __syncthreads();
    }

    const int qrow = lane >> 2, qcol = (lane & 3) * 2;
    #pragma unroll
    for (int nf = 0; nf < 8; nf++) {
        const int col = col0 + wn * 64 + nf * 8 + qcol;
        float b0 = bias ? bias[col] : 0.0f;
        float b1 = bias ? bias[col + 1] : 0.0f;
        #pragma unroll
        for (int mf = 0; mf < 4; mf++) {
            #pragma unroll
            for (int h = 0; h < 2; h++) {
                const int row = row0 + wm * 64 + mf * 16 + qrow + h * 8;
                float v0 = acc[mf][nf][h * 2 + 0] + b0;
                float v1 = acc[mf][nf][h * 2 + 1] + b1;
                if (SILU) { v0 = silu_f(v0); v1 = silu_f(v1); }
                size_t gi = (size_t)row * N + col;
                if (SPLIT) {
                    __half h0 = __float2half(v0);
                    __half h1 = __float2half(v1);
                    *reinterpret_cast<__half2*>(Chi + gi) = __halves2half2(h0, h1);
                    *reinterpret_cast<__half2*>(Clo + gi) = __halves2half2(
                        __float2half(v0 - __half2float(h0)),
                        __float2half(v1 - __half2float(h1)));
                } else {
                    *reinterpret_cast<float2*>(Cf + gi) = make_float2(v0, v1);
                }
            }
        }
    }
}

// ============ HMMA split-K TN GEMM: C[m,n] += s * sum_k A[k,m]*B[k,n] =============
static constexpr int TK_PITCH = 272;
static constexpr int TK_PLANE = 32 * TK_PITCH;
static constexpr int TK_BUF   = 3 * TK_PLANE;
static constexpr int TK_SMEM  = 2 * TK_BUF;

__global__ __launch_bounds__(256, 1) void gemm_tn_mma(
    const __half* __restrict__ Ahi, const __half* __restrict__ Alo,
    const __half* __restrict__ B,
    float* __restrict__ C, int Mc, int Nc, int Ktot, int kChunk, float scale) {
    extern __shared__ char smem[];
    const uint32_t sb = smem_u32(smem);
    const int tid = threadIdx.x, wid = tid >> 5, lane = tid & 31;
    const int col0 = blockIdx.x * 128;
    const int row0 = blockIdx.y * 128;
    const int n0 = blockIdx.z * kChunk;
    const int nEnd = min(n0 + kChunk, Ktot);
    const int wm = wid >> 2, wn = wid & 3;

    const __half* planes[3] = { Ahi, Alo, B };
    const int baseCol[3] = { row0, row0, col0 };
    const int strideK[3] = { Mc, Mc, Nc };

    const int lr0 = tid >> 4, lc0 = tid & 15;
    const int lr1 = lr0 + 16;

    auto load_chunk = [&](int i, int k0) {
        const uint32_t bufb = sb + (i & 1) * TK_BUF;
        #pragma unroll
        for (int p = 0; p < 3; p++) {
            const __half* src = planes[p];
            #pragma unroll
            for (int rep = 0; rep < 2; rep++) {
                int r = rep ? lr1 : lr0;
                int node = k0 + r;
                uint32_t sa = bufb + p * TK_PLANE + r * TK_PITCH + lc0 * 16;
                if (node < nEnd) {
                    CP_ASYNC16(sa, src + (size_t)node * strideK[p] + baseCol[p] + lc0 * 8);
                } else {
                    *reinterpret_cast<uint4*>(smem + (sa - sb)) = make_uint4(0, 0, 0, 0);
                }
            }
        }
        CP_COMMIT();
    };

    float acc[4][4][4];
    #pragma unroll
    for (int i = 0; i < 4; i++)
        #pragma unroll
        for (int j = 0; j < 4; j++)
            #pragma unroll
            for (int q = 0; q < 4; q++) acc[i][j][q] = 0.0f;

    const int krA = (lane & 7) + ((lane >> 4) << 3);
    const int mcA = ((lane >> 3) & 1) * 8;
    const int krB = (lane & 7) + (((lane >> 3) & 1) << 3);
    const int ncB = (lane >> 4) * 8;

    const int nCh = (nEnd - n0 + 31) >> 5;
    load_chunk(0, n0);

    for (int i = 0; i < nCh; i++) {
        const int k0 = n0 + i * 32;
        if (i + 1 < nCh) {
            load_chunk(i + 1, k0 + 32);
            asm volatile("cp.async.wait_group 1;");
        } else {
            asm volatile("cp.async.wait_group 0;");
        }
        __syncthreads();

        const uint32_t bufb = sb + (i & 1) * TK_BUF;
        #pragma unroll
        for (int ks = 0; ks < 2; ks++) {
            uint32_t bh[4][2];
            #pragma unroll
            for (int nf2 = 0; nf2 < 2; nf2++) {
                uint32_t aH = bufb + 2 * TK_PLANE +
                    (uint32_t)(krB + ks * 16) * TK_PITCH +
                    (uint32_t)(wn * 32 + nf2 * 16 + ncB) * 2;
                ldm_x4t(aH, bh[nf2 * 2][0], bh[nf2 * 2][1],
                            bh[nf2 * 2 + 1][0], bh[nf2 * 2 + 1][1]);
            }
            uint32_t ah[4][4], al[4][4];
            #pragma unroll
            for (int mf = 0; mf < 4; mf++) {
                uint32_t aH = bufb +
                    (uint32_t)(krA + ks * 16) * TK_PITCH +
                    (uint32_t)(wm * 64 + mf * 16 + mcA) * 2;
                ldm_x4t(aH, ah[mf][0], ah[mf][1], ah[mf][2], ah[mf][3]);
                ldm_x4t(aH + TK_PLANE, al[mf][0], al[mf][1], al[mf][2], al[mf][3]);
            }
            #pragma unroll
            for (int mf = 0; mf < 4; mf++)
                #pragma unroll
                for (int nf = 0; nf < 4; nf++)
                    mma_fp16(acc[mf][nf], ah[mf], bh[nf]);
            #pragma unroll
            for (int mf = 0; mf < 4; mf++)
                #pragma unroll
                for (int nf = 0; nf < 4; nf++)
                    mma_fp16(acc[mf][nf], al[mf], bh[nf]);
        }
        __syncthreads();
    }

    const int qrow = lane >> 2, qcol = (lane & 3) * 2;
    #pragma unroll
    for (int mf = 0; mf < 4; mf++) {
        #pragma unroll
        for (int nf = 0; nf < 4; nf++) {
            #pragma unroll
            for (int h = 0; h < 2; h++) {
                const int row = row0 + wm * 64 + mf * 16 + qrow + h * 8;
                const int col = col0 + wn * 32 + nf * 8 + qcol;
                atomicAdd(&C[(size_t)row * Nc + col], acc[mf][nf][h * 2 + 0] * scale);
                atomicAdd(&C[(size_t)row * Nc + col + 1], acc[mf][nf][h * 2 + 1] * scale);
            }
        }
    }
}

// ---------------- fp32 -> fp16 hi/lo split ----------------
__global__ void split_kernel(const float* __restrict__ src,
                             __half* __restrict__ hi,
                             __half* __restrict__ lo, int n) {
    int i = blockIdx.x * 256 + threadIdx.x;
    if (i < n) split_store_h(src[i], hi, lo, i);
}
// ---------------- fp32 -> fp16 single convert ----------------
__global__ void convert_kernel(const float* __restrict__ src,
                               __half* __restrict__ dst, int n) {
    int i = blockIdx.x * 256 + threadIdx.x;
    if (i < n) dst[i] = __float2half(src[i]);
}

// ---------------- K0: Zc (single fp16 plane) ----------------
__global__ void zc_kernel(const float* __restrict__ Z,
                          const float* __restrict__ zcw,
                          const float* __restrict__ zcb,
                          __half* __restrict__ Zc, int NL) {
    int idx = blockIdx.x * 256 + threadIdx.x;
    if (idx >= NL) return;
    int n = idx >> 7, l = idx & 127;
    size_t base = (size_t)n * 384 + l;
    float z0 = Z[base], z1 = Z[base + 128], z2 = Z[base + 256];
    #pragma unroll
    for (int c = 0; c < 3; c++) {
        float v = zcw[c * 3 + 0] * z0 + zcw[c * 3 + 1] * z1 + zcw[c * 3 + 2] * z2 + zcb[c];
        Zc[base + (size_t)c * 128] = __float2half(v);
    }
}

// ---------------- K2: per-edge prep (single fp16 planes) ----------------
__global__ __launch_bounds__(128) void edge_prep(
    const float* __restrict__ x, const float* __restrict__ Z,
    const int* __restrict__ tar,
    const float* __restrict__ zw1, const float* __restrict__ zb1,
    __half* __restrict__ Ph, __half* __restrict__ ZZh,
    __half* __restrict__ Gh, int E) {
    int e = blockIdx.x;
    int t = threadIdx.x;
    int src = tar[e], dst = tar[E + e];

    __shared__ float sZi[384], sZj[384];
    __shared__ float red[9][4];
    __shared__ float r9[9], rT9[9];

    const float* xs = x + (size_t)src * 256;
    const float* xd = x + (size_t)dst * 256;
    Ph[(size_t)e * 256 + t]       = __float2half(xs[t] * xd[t]);
    Ph[(size_t)e * 256 + t + 128] = __float2half(xs[t + 128] * xd[t + 128]);

    const float* Zi = Z + (size_t)src * 384;
    const float* Zj = Z + (size_t)dst * 384;
    for (int i = t; i < 384; i += 128) { sZi[i] = Zi[i]; sZj[i] = Zj[i]; }
    __syncthreads();

    for (int i = t; i < 384; i += 128)
        ZZh[(size_t)e * 384 + i] = __float2half(sZi[i] * sZj[i]);

    float loc[9];
    #pragma unroll
    for (int c = 0; c < 3; c++)
        #pragma unroll
        for (int d = 0; d < 3; d++)
            loc[c * 3 + d] = sZi[c * 128 + t] * sZj[d * 128 + t];
    #pragma unroll
    for (int off = 16; off > 0; off >>= 1)
        #pragma unroll
        for (int q = 0; q < 9; q++)
            loc[q] += __shfl_down_sync(0xffffffffu, loc[q], off);
    int warp = t >> 5, lane = t & 31;
    if (lane == 0)
        #pragma unroll
        for (int q = 0; q < 9; q++) red[q][warp] = loc[q];
    __syncthreads();
    if (t < 9) r9[t] = (red[t][0] + red[t][1] + red[t][2] + red[t][3]) * (1.0f / 128.0f);
    __syncthreads();
    if (t < 9) { int c = t / 3, d = t % 3; rT9[t] = r9[d * 3 + c]; }
    __syncthreads();

    #pragma unroll
    for (int rep = 0; rep < 2; rep++) {
        int o = t + rep * 128;
        const float* w = zw1 + (size_t)o * 9;
        float s1 = zb1[o], s2 = zb1[o];
        #pragma unroll
        for (int q = 0; q < 9; q++) { s1 += r9[q] * w[q]; s2 += rT9[q] * w[q]; }
        Gh[(size_t)e * 256 + o]       = __float2half(silu_f(s1));
        Gh[(size_t)(E + e) * 256 + o] = __float2half(silu_f(s2));
    }
}

// ---------------- K4: 4 LayerNorms + product + final dot (fp32 inputs) ----------------
__global__ __launch_bounds__(256) void final_kernel(
    const float* __restrict__ XIJ, const float* __restrict__ U,
    const float* __restrict__ XZX,
    const float* __restrict__ xg, const float* __restrict__ xb,
    const float* __restrict__ zg, const float* __restrict__ zb,
    const float* __restrict__ zxg, const float* __restrict__ zxb,
    const float* __restrict__ lw, const float* __restrict__ lb,
    float* __restrict__ out, int E) {
    int e = blockIdx.x;
    int t = threadIdx.x;
    const float* pxij = XIJ + (size_t)e * 768;
    const float* pu1  = U   + (size_t)e * 768;
    const float* pu2  = U   + (size_t)(E + e) * 768;
    const float* pxzx = XZX + (size_t)e * 768;

    __shared__ float red[8][8];
    __shared__ float stats[8];
    __shared__ float dred[8];

    float v0[3], v1[3], v2[3], v3[3];
    float s[8];
    #pragma unroll
    for (int q = 0; q < 8; q++) s[q] = 0.0f;
    #pragma unroll
    for (int k = 0; k < 3; k++) {
        int col = t + k * 256;
        float a = pxij[col], b = pu1[col], c = pu2[col], d = pxzx[col];
        v0[k] = a; v1[k] = b; v2[k] = c; v3[k] = d;
        s[0] += a; s[1] += a * a;
        s[2] += b; s[3] += b * b;
        s[4] += c; s[5] += c * c;
        s[6] += d; s[7] += d * d;
    }
    #pragma unroll
    for (int off = 16; off > 0; off >>= 1)
        #pragma unroll
        for (int q = 0; q < 8; q++)
            s[q] += __shfl_down_sync(0xffffffffu, s[q], off);
    int warp = t >> 5, lane = t & 31;
    if (lane == 0)
        #pragma unroll
        for (int q = 0; q < 8; q++) red[q][warp] = s[q];
    __syncthreads();
    if (t < 8) {
        float tot = 0.0f;
        #pragma unroll
        for (int w = 0; w < 8; w++) tot += red[t][w];
        stats[t] = tot;
    }
    __syncthreads();

    const float inv = 1.0f / 768.0f;
    const float eps = 1e-5f;
    float m0 = stats[0] * inv, r0 = rsqrtf(stats[1] * inv - m0 * m0 + eps);
    float m1 = stats[2] * inv, r1 = rsqrtf(stats[3] * inv - m1 * m1 + eps);
    float m2 = stats[4] * inv, r2 = rsqrtf(stats[5] * inv - m2 * m2 + eps);
    float m3 = stats[6] * inv, r3 = rsqrtf(stats[7] * inv - m3 * m3 + eps);

    float dot = 0.0f;
    #pragma unroll
    for (int k = 0; k < 3; k++) {
        int col = t + k * 256;
        float a  = (v0[k] - m0) * r0 * xg[col]  + xb[col];
        float b1 = (v1[k] - m1) * r1 * zg[col]  + zb[col];
        float b2 = (v2[k] - m2) * r2 * zg[col]  + zb[col];
        float c  = (v3[k] - m3) * r3 * zxg[col] + zxb[col];
        dot += a * (b1 + b2) * c * lw[col];
    }
    #pragma unroll
    for (int off = 16; off > 0; off >>= 1)
        dot += __shfl_down_sync(0xffffffffu, dot, off);
    if (lane == 0) dred[warp] = dot;
    __syncthreads();
    if (t == 0) {
        float tot = 0.0f;
        #pragma unroll
        for (int w = 0; w < 8; w++) tot += dred[w];
        out[e] = tot + lb[0];
    }
}

// ---------------- launch ----------------
extern "C" void kernel_launch(void* const* d_in, const int* in_sizes, int n_in,
                              void* d_out, int out_size) {
    const float* x   = (const float*)d_in[0];
    const float* Z   = (const float*)d_in[1];
    const int*   tar = (const int*)  d_in[3];
    const float* xij_w1 = (const float*)d_in[4];
    const float* xij_b1 = (const float*)d_in[5];
    const float* xij_w2 = (const float*)d_in[6];
    const float* xij_b2 = (const float*)d_in[7];
    const float* xij_ln_g = (const float*)d_in[8];
    const float* xij_ln_b = (const float*)d_in[9];
    const float* z_w1 = (const float*)d_in[10];
    const float* z_b1 = (const float*)d_in[11];
    const float* z_w2 = (const float*)d_in[12];
    const float* z_b2 = (const float*)d_in[13];
    const float* z_ln_g = (const float*)d_in[14];
    const float* z_ln_b = (const float*)d_in[15];
    const float* zc_w = (const float*)d_in[16];
    const float* zc_b = (const float*)d_in[17];
    const float* zx_w = (const float*)d_in[18];
    const float* zx_b = (const float*)d_in[19];
    const float* zx_ln_g = (const float*)d_in[20];
    const float* zx_ln_b = (const float*)d_in[21];
    const float* lin_w = (const float*)d_in[22];
    const float* lin_b = (const float*)d_in[23];

    int N = in_sizes[0] / 256;
    int E = in_sizes[3] / 2;
    float zx_coeff = (float)(1.0 / (sqrt((double)N) * 3840.0));

    float *ZXT, *XIJ, *U, *XZX;
    cudaGetSymbolAddress((void**)&ZXT, g_ZXT);
    cudaGetSymbolAddress((void**)&XIJ, g_XIJ);
    cudaGetSymbolAddress((void**)&U,   g_U);
    cudaGetSymbolAddress((void**)&XZX, g_XZX);

    __half *xh,*xl,*Zc,*Ph,*ZZh,*Gh,*Hh,*Hl,*Th,*Tl;
    __half *W1,*W2,*ZW2,*ZXW,*ZXTq;
    cudaGetSymbolAddress((void**)&xh,  g_xh);  cudaGetSymbolAddress((void**)&xl,  g_xl);
    cudaGetSymbolAddress((void**)&Zc,  g_Zc);
    cudaGetSymbolAddress((void**)&Ph,  g_Ph);
    cudaGetSymbolAddress((void**)&ZZh, g_ZZh);
    cudaGetSymbolAddress((void**)&Gh,  g_Gh);
    cudaGetSymbolAddress((void**)&Hh,  g_Hh);  cudaGetSymbolAddress((void**)&Hl,  g_Hl);
    cudaGetSymbolAddress((void**)&Th,  g_Th);  cudaGetSymbolAddress((void**)&Tl,  g_Tl);
    cudaGetSymbolAddress((void**)&W1,  g_W1);  cudaGetSymbolAddress((void**)&W2,  g_W2);
    cudaGetSymbolAddress((void**)&ZW2, g_ZW2); cudaGetSymbolAddress((void**)&ZXW, g_ZXW);
    cudaGetSymbolAddress((void**)&ZXTq,g_ZXTq);

    constexpr int SM_2P = 2 * 51200;   // LO=true
    constexpr int SM_1P = 2 * 30720;   // LO=false
    cudaFuncSetAttribute(gemm_mma<false, true,  true >, cudaFuncAttributeMaxDynamicSharedMemorySize, SM_1P);
    cudaFuncSetAttribute(gemm_mma<true,  false, false>, cudaFuncAttributeMaxDynamicSharedMemorySize, SM_2P);
    cudaFuncSetAttribute(gemm_mma<false, true,  false>, cudaFuncAttributeMaxDynamicSharedMemorySize, SM_1P);
    cudaFuncSetAttribute(gemm_mma<false, false, true >, cudaFuncAttributeMaxDynamicSharedMemorySize, SM_1P);
    cudaFuncSetAttribute(gemm_tn_mma, cudaFuncAttributeMaxDynamicSharedMemorySize, TK_SMEM);

    // weight converts (single fp16 plane)
    convert_kernel<<<(65536 + 255) / 256, 256>>>(xij_w1, W1, 65536);
    convert_kernel<<<(196608 + 255) / 256, 256>>>(xij_w2, W2, 196608);
    convert_kernel<<<(196608 + 255) / 256, 256>>>(z_w2,  ZW2, 196608);
    convert_kernel<<<(196608 + 255) / 256, 256>>>(zx_w,  ZXW, 196608);

    // zx node path (tensorized split-K, x kept hi/lo for accuracy)
    int NL = N * 128;
    split_kernel<<<(N * 256 + 255) / 256, 256>>>(x, xh, xl, N * 256);
    zc_kernel<<<(NL + 255) / 256, 256>>>(Z, zc_w, zc_b, Zc, NL);
    cudaMemsetAsync(ZXT, 0, 256 * 384 * sizeof(float), 0);
    {
        int kChunk = 4000;
        int splits = (N + kChunk - 1) / kChunk;
        dim3 grid(3, 2, splits);
        gemm_tn_mma<<<grid, 256, TK_SMEM>>>(xh, xl, Zc, ZXT, 256, 384, N, kChunk, zx_coeff);
    }
    convert_kernel<<<(98304 + 255) / 256, 256>>>(ZXT, ZXTq, 98304);

    // edge prep (single-plane outputs)
    edge_prep<<<E, 128>>>(x, Z, tar, z_w1, z_b1, Ph, ZZh, Gh, E);

    // edge GEMMs: error-budgeted pass allocation
    dim3 g256(2, E / 256), g768(6, E / 256), gU(6, 2 * E / 256);
    // H = silu(P @ W1^T + b1), 1-pass, split output (exact storage)
    gemm_mma<false, true,  true ><<<g256, 256, SM_1P>>>(Ph, nullptr, W1, xij_b1,
                                                        nullptr, Hh, Hl, E, 256, 256);
    // XIJ = H @ W2^T + b2, 2-pass (H exact), fp32 out
    gemm_mma<true,  false, false><<<g768, 256, SM_2P>>>(Hh, Hl, W2, xij_b2,
                                                        XIJ, nullptr, nullptr, E, 768, 256);
    // U = silu(G @ ZW2^T + b), 1-pass, fp32 out
    gemm_mma<false, true,  false><<<gU,   256, SM_1P>>>(Gh, nullptr, ZW2, z_b2,
                                                        U, nullptr, nullptr, 2 * E, 768, 256);
    // T = ZZ @ ZXT^T, 1-pass, split output (exact storage)
    gemm_mma<false, false, true ><<<g256, 256, SM_1P>>>(ZZh, nullptr, ZXTq, nullptr,
                                                        nullptr, Th, Tl, E, 256, 384);
    // XZX = T @ ZXW^T + b, 2-pass (T exact), fp32 out
    gemm_mma<true,  false, false><<<g768, 256, SM_2P>>>(Th, Tl, ZXW, zx_b,
                                                        XZX, nullptr, nullptr, E, 768, 256);

    final_kernel<<<E, 256>>>(XIJ, U, XZX,
                             xij_ln_g, xij_ln_b, z_ln_g, z_ln_b,
                             zx_ln_g, zx_ln_b, lin_w, lin_b,
                             (float*)d_out, E);
}

// round 9
// speedup vs baseline: 3.0125x; 1.1467x over previous
#include <cuda_runtime.h>
#include <cuda_fp16.h>
#include <math.h>
#include <stdint.h>

#define MAXN 100000
#define MAXE 131072

// ---------------- scratch (device globals; no allocation allowed) ----------------
__device__ __align__(128) float  g_ZXT[256 * 384];
__device__ __align__(128) __half g_XIJ[(size_t)MAXE * 768];
__device__ __align__(128) __half g_U[(size_t)2 * MAXE * 768];   // U1 | U2
__device__ __align__(128) __half g_XZX[(size_t)MAXE * 768];

// fp16 planes
__device__ __align__(128) __half g_xh [(size_t)MAXN * 256];
__device__ __align__(128) __half g_xl [(size_t)MAXN * 256];
__device__ __align__(128) __half g_Zc [(size_t)MAXN * 384];
__device__ __align__(128) __half g_Ph [(size_t)MAXE * 256];
__device__ __align__(128) __half g_ZZh[(size_t)MAXE * 384];
__device__ __align__(128) __half g_Gh [(size_t)2 * MAXE * 256]; // G1|G2
__device__ __align__(128) __half g_Hh [(size_t)MAXE * 256];
__device__ __align__(128) __half g_Th [(size_t)MAXE * 256];
// weights, single fp16 plane
__device__ __align__(128) __half g_W1 [256 * 256];
__device__ __align__(128) __half g_W2 [768 * 256];
__device__ __align__(128) __half g_ZW2[768 * 256];
__device__ __align__(128) __half g_ZXW[768 * 256];
__device__ __align__(128) __half g_ZXTq[256 * 384];

__device__ __forceinline__ float silu_f(float v) { return v / (1.0f + __expf(-v)); }

__device__ __forceinline__ void split_store_h(float v,
        __half* __restrict__ hi, __half* __restrict__ lo, size_t i) {
    __half h = __float2half(v);
    hi[i] = h;
    lo[i] = __float2half(v - __half2float(h));
}

__device__ __forceinline__ uint32_t smem_u32(const void* p) {
    uint32_t a;
    asm("{ .reg .u64 t; cvta.to.shared.u64 t, %1; cvt.u32.u64 %0, t; }" : "=r"(a) : "l"(p));
    return a;
}

#define CP_ASYNC16(saddr, gptr) \
    asm volatile("cp.async.cg.shared.global [%0], [%1], 16;" :: "r"(saddr), "l"(gptr))
#define CP_COMMIT() asm volatile("cp.async.commit_group;")

__device__ __forceinline__ void ldm_x4(uint32_t addr, uint32_t& r0, uint32_t& r1,
                                       uint32_t& r2, uint32_t& r3) {
    asm volatile("ldmatrix.sync.aligned.m8n8.x4.shared.b16 {%0,%1,%2,%3}, [%4];"
                 : "=r"(r0), "=r"(r1), "=r"(r2), "=r"(r3) : "r"(addr));
}
__device__ __forceinline__ void ldm_x4t(uint32_t addr, uint32_t& r0, uint32_t& r1,
                                        uint32_t& r2, uint32_t& r3) {
    asm volatile("ldmatrix.sync.aligned.m8n8.x4.trans.shared.b16 {%0,%1,%2,%3}, [%4];"
                 : "=r"(r0), "=r"(r1), "=r"(r2), "=r"(r3) : "r"(addr));
}
__device__ __forceinline__ void mma_fp16(float* c, const uint32_t* a, const uint32_t* b) {
    asm volatile(
        "mma.sync.aligned.m16n8k16.row.col.f32.f16.f16.f32 "
        "{%0,%1,%2,%3}, {%4,%5,%6,%7}, {%8,%9}, {%0,%1,%2,%3};"
        : "+f"(c[0]), "+f"(c[1]), "+f"(c[2]), "+f"(c[3])
        : "r"(a[0]), "r"(a[1]), "r"(a[2]), "r"(a[3]), "r"(b[0]), "r"(b[1]));
}

// ========= HMMA GEMM (1-pass): C[m,n] = act(sum_k A[m,k]*B[n,k] + bias[n]) =========
// 256x128 CTA tile, BK=32, 8 warps (4x2), warp tile 64x64, fp16 in/out.
static constexpr int OFF_B = 20480;     // A: 256*80
static constexpr int BUF   = 30720;     // + B: 128*80
static constexpr int GEMM_SMEM = 2 * BUF;  // 61440

template <bool SILU>
__global__ __launch_bounds__(256, 1) void gemm_mma(
    const __half* __restrict__ A, const __half* __restrict__ B,
    const float* __restrict__ bias,
    __half* __restrict__ C,
    int M, int N, int K) {
    extern __shared__ char smem[];
    const uint32_t sb = smem_u32(smem);
    const int tid = threadIdx.x, wid = tid >> 5, lane = tid & 31;
    const int col0 = blockIdx.x * 128;
    const int row0 = blockIdx.y * 256;
    const int wm = wid & 3, wn = wid >> 2;

    const int ldr = tid >> 2, ldc = tid & 3;

    auto load_chunk = [&](int i) {
        const uint32_t bufb = sb + (i & 1) * BUF;
        const int k0 = i * 32;
        #pragma unroll
        for (int g = 0; g < 4; g++) {
            int r = ldr + g * 64;
            CP_ASYNC16(bufb + r * 80 + ldc * 16,
                       A + (size_t)(row0 + r) * K + k0 + ldc * 8);
        }
        #pragma unroll
        for (int g = 0; g < 2; g++) {
            int r = ldr + g * 64;
            CP_ASYNC16(bufb + OFF_B + r * 80 + ldc * 16,
                       B + (size_t)(col0 + r) * K + k0 + ldc * 8);
        }
        CP_COMMIT();
    };

    float acc[4][8][4];
    #pragma unroll
    for (int i = 0; i < 4; i++)
        #pragma unroll
        for (int j = 0; j < 8; j++)
            #pragma unroll
            for (int q = 0; q < 4; q++) acc[i][j][q] = 0.0f;

    const int rowA = wm * 64 + (lane & 15);
    const int kparA = (lane >> 4) * 8;
    const int rowB = wn * 64 + (lane & 7) + ((lane >> 4) << 3);
    const int kparB = ((lane >> 3) & 1) * 8;

    const int nCh = K >> 5;
    load_chunk(0);

    for (int i = 0; i < nCh; i++) {
        if (i + 1 < nCh) {
            load_chunk(i + 1);
            asm volatile("cp.async.wait_group 1;");
        } else {
            asm volatile("cp.async.wait_group 0;");
        }
        __syncthreads();

        const uint32_t bufb = sb + (i & 1) * BUF;
        #pragma unroll
        for (int ks = 0; ks < 2; ks++) {
            uint32_t ah[4][4];
            #pragma unroll
            for (int mf = 0; mf < 4; mf++) {
                uint32_t addrA = bufb +
                    (uint32_t)(rowA + mf * 16) * 80 + (uint32_t)(kparA + ks * 16) * 2;
                ldm_x4(addrA, ah[mf][0], ah[mf][1], ah[mf][2], ah[mf][3]);
            }
            #pragma unroll
            for (int nf2 = 0; nf2 < 4; nf2++) {
                uint32_t bh[2][2];
                uint32_t addrB = bufb + OFF_B +
                    (uint32_t)(rowB + nf2 * 16) * 80 + (uint32_t)(kparB + ks * 16) * 2;
                ldm_x4(addrB, bh[0][0], bh[0][1], bh[1][0], bh[1][1]);
                #pragma unroll
                for (int mf = 0; mf < 4; mf++)
                    #pragma unroll
                    for (int j = 0; j < 2; j++)
                        mma_fp16(acc[mf][nf2 * 2 + j], ah[mf], bh[j]);
            }
        }
        __syncthreads();
    }

    const int qrow = lane >> 2, qcol = (lane & 3) * 2;
    #pragma unroll
    for (int nf = 0; nf < 8; nf++) {
        const int col = col0 + wn * 64 + nf * 8 + qcol;
        float b0 = bias ? bias[col] : 0.0f;
        float b1 = bias ? bias[col + 1] : 0.0f;
        #pragma unroll
        for (int mf = 0; mf < 4; mf++) {
            #pragma unroll
            for (int h = 0; h < 2; h++) {
                const int row = row0 + wm * 64 + mf * 16 + qrow + h * 8;
                float v0 = acc[mf][nf][h * 2 + 0] + b0;
                float v1 = acc[mf][nf][h * 2 + 1] + b1;
                if (SILU) { v0 = silu_f(v0); v1 = silu_f(v1); }
                *reinterpret_cast<__half2*>(C + (size_t)row * N + col) =
                    __halves2half2(__float2half(v0), __float2half(v1));
            }
        }
    }
}

// ============ HMMA split-K TN GEMM: C[m,n] += s * sum_k A[k,m]*B[k,n] =============
// A = x hi/lo (2-pass, accuracy), B = Zc single; node(k)-major -> ldmatrix.trans
static constexpr int TK_PITCH = 272;
static constexpr int TK_PLANE = 32 * TK_PITCH;
static constexpr int TK_BUF   = 3 * TK_PLANE;
static constexpr int TK_SMEM  = 2 * TK_BUF;

__global__ __launch_bounds__(256, 1) void gemm_tn_mma(
    const __half* __restrict__ Ahi, const __half* __restrict__ Alo,
    const __half* __restrict__ B,
    float* __restrict__ C, int Mc, int Nc, int Ktot, int kChunk, float scale) {
    extern __shared__ char smem[];
    const uint32_t sb = smem_u32(smem);
    const int tid = threadIdx.x, wid = tid >> 5, lane = tid & 31;
    const int col0 = blockIdx.x * 128;
    const int row0 = blockIdx.y * 128;
    const int n0 = blockIdx.z * kChunk;
    const int nEnd = min(n0 + kChunk, Ktot);
    const int wm = wid >> 2, wn = wid & 3;

    const __half* planes[3] = { Ahi, Alo, B };
    const int baseCol[3] = { row0, row0, col0 };
    const int strideK[3] = { Mc, Mc, Nc };

    const int lr0 = tid >> 4, lc0 = tid & 15;
    const int lr1 = lr0 + 16;

    auto load_chunk = [&](int i, int k0) {
        const uint32_t bufb = sb + (i & 1) * TK_BUF;
        #pragma unroll
        for (int p = 0; p < 3; p++) {
            const __half* src = planes[p];
            #pragma unroll
            for (int rep = 0; rep < 2; rep++) {
                int r = rep ? lr1 : lr0;
                int node = k0 + r;
                uint32_t sa = bufb + p * TK_PLANE + r * TK_PITCH + lc0 * 16;
                if (node < nEnd) {
                    CP_ASYNC16(sa, src + (size_t)node * strideK[p] + baseCol[p] + lc0 * 8);
                } else {
                    *reinterpret_cast<uint4*>(smem + (sa - sb)) = make_uint4(0, 0, 0, 0);
                }
            }
        }
        CP_COMMIT();
    };

    float acc[4][4][4];
    #pragma unroll
    for (int i = 0; i < 4; i++)
        #pragma unroll
        for (int j = 0; j < 4; j++)
            #pragma unroll
            for (int q = 0; q < 4; q++) acc[i][j][q] = 0.0f;

    const int krA = (lane & 7) + ((lane >> 4) << 3);
    const int mcA = ((lane >> 3) & 1) * 8;
    const int krB = (lane & 7) + (((lane >> 3) & 1) << 3);
    const int ncB = (lane >> 4) * 8;

    const int nCh = (nEnd - n0 + 31) >> 5;
    load_chunk(0, n0);

    for (int i = 0; i < nCh; i++) {
        const int k0 = n0 + i * 32;
        if (i + 1 < nCh) {
            load_chunk(i + 1, k0 + 32);
            asm volatile("cp.async.wait_group 1;");
        } else {
            asm volatile("cp.async.wait_group 0;");
        }
        __syncthreads();

        const uint32_t bufb = sb + (i & 1) * TK_BUF;
        #pragma unroll
        for (int ks = 0; ks < 2; ks++) {
            uint32_t bh[4][2];
            #pragma unroll
            for (int nf2 = 0; nf2 < 2; nf2++) {
                uint32_t aH = bufb + 2 * TK_PLANE +
                    (uint32_t)(krB + ks * 16) * TK_PITCH +
                    (uint32_t)(wn * 32 + nf2 * 16 + ncB) * 2;
                ldm_x4t(aH, bh[nf2 * 2][0], bh[nf2 * 2][1],
                            bh[nf2 * 2 + 1][0], bh[nf2 * 2 + 1][1]);
            }
            uint32_t ah[4][4], al[4][4];
            #pragma unroll
            for (int mf = 0; mf < 4; mf++) {
                uint32_t aH = bufb +
                    (uint32_t)(krA + ks * 16) * TK_PITCH +
                    (uint32_t)(wm * 64 + mf * 16 + mcA) * 2;
                ldm_x4t(aH, ah[mf][0], ah[mf][1], ah[mf][2], ah[mf][3]);
                ldm_x4t(aH + TK_PLANE, al[mf][0], al[mf][1], al[mf][2], al[mf][3]);
            }
            #pragma unroll
            for (int mf = 0; mf < 4; mf++)
                #pragma unroll
                for (int nf = 0; nf < 4; nf++)
                    mma_fp16(acc[mf][nf], ah[mf], bh[nf]);
            #pragma unroll
            for (int mf = 0; mf < 4; mf++)
                #pragma unroll
                for (int nf = 0; nf < 4; nf++)
                    mma_fp16(acc[mf][nf], al[mf], bh[nf]);
        }
        __syncthreads();
    }

    const int qrow = lane >> 2, qcol = (lane & 3) * 2;
    #pragma unroll
    for (int mf = 0; mf < 4; mf++) {
        #pragma unroll
        for (int nf = 0; nf < 4; nf++) {
            #pragma unroll
            for (int h = 0; h < 2; h++) {
                const int row = row0 + wm * 64 + mf * 16 + qrow + h * 8;
                const int col = col0 + wn * 32 + nf * 8 + qcol;
                atomicAdd(&C[(size_t)row * Nc + col], acc[mf][nf][h * 2 + 0] * scale);
                atomicAdd(&C[(size_t)row * Nc + col + 1], acc[mf][nf][h * 2 + 1] * scale);
            }
        }
    }
}

// ---------------- fp32 -> fp16 hi/lo split ----------------
__global__ void split_kernel(const float* __restrict__ src,
                             __half* __restrict__ hi,
                             __half* __restrict__ lo, int n) {
    int i = blockIdx.x * 256 + threadIdx.x;
    if (i < n) split_store_h(src[i], hi, lo, i);
}
// ---------------- fp32 -> fp16 convert ----------------
__global__ void convert_kernel(const float* __restrict__ src,
                               __half* __restrict__ dst, int n) {
    int i = blockIdx.x * 256 + threadIdx.x;
    if (i < n) dst[i] = __float2half(src[i]);
}

// ---------------- K0: Zc (single fp16 plane) ----------------
__global__ void zc_kernel(const float* __restrict__ Z,
                          const float* __restrict__ zcw,
                          const float* __restrict__ zcb,
                          __half* __restrict__ Zc, int NL) {
    int idx = blockIdx.x * 256 + threadIdx.x;
    if (idx >= NL) return;
    int n = idx >> 7, l = idx & 127;
    size_t base = (size_t)n * 384 + l;
    float z0 = Z[base], z1 = Z[base + 128], z2 = Z[base + 256];
    #pragma unroll
    for (int c = 0; c < 3; c++) {
        float v = zcw[c * 3 + 0] * z0 + zcw[c * 3 + 1] * z1 + zcw[c * 3 + 2] * z2 + zcb[c];
        Zc[base + (size_t)c * 128] = __float2half(v);
    }
}

// ---------------- K2: per-edge prep (single fp16 planes) ----------------
__global__ __launch_bounds__(128) void edge_prep(
    const float* __restrict__ x, const float* __restrict__ Z,
    const int* __restrict__ tar,
    const float* __restrict__ zw1, const float* __restrict__ zb1,
    __half* __restrict__ Ph, __half* __restrict__ ZZh,
    __half* __restrict__ Gh, int E) {
    int e = blockIdx.x;
    int t = threadIdx.x;
    int src = tar[e], dst = tar[E + e];

    __shared__ float sZi[384], sZj[384];
    __shared__ float red[9][4];
    __shared__ float r9[9], rT9[9];

    const float* xs = x + (size_t)src * 256;
    const float* xd = x + (size_t)dst * 256;
    Ph[(size_t)e * 256 + t]       = __float2half(xs[t] * xd[t]);
    Ph[(size_t)e * 256 + t + 128] = __float2half(xs[t + 128] * xd[t + 128]);

    const float* Zi = Z + (size_t)src * 384;
    const float* Zj = Z + (size_t)dst * 384;
    for (int i = t; i < 384; i += 128) { sZi[i] = Zi[i]; sZj[i] = Zj[i]; }
    __syncthreads();

    for (int i = t; i < 384; i += 128)
        ZZh[(size_t)e * 384 + i] = __float2half(sZi[i] * sZj[i]);

    float loc[9];
    #pragma unroll
    for (int c = 0; c < 3; c++)
        #pragma unroll
        for (int d = 0; d < 3; d++)
            loc[c * 3 + d] = sZi[c * 128 + t] * sZj[d * 128 + t];
    #pragma unroll
    for (int off = 16; off > 0; off >>= 1)
        #pragma unroll
        for (int q = 0; q < 9; q++)
            loc[q] += __shfl_down_sync(0xffffffffu, loc[q], off);
    int warp = t >> 5, lane = t & 31;
    if (lane == 0)
        #pragma unroll
        for (int q = 0; q < 9; q++) red[q][warp] = loc[q];
    __syncthreads();
    if (t < 9) r9[t] = (red[t][0] + red[t][1] + red[t][2] + red[t][3]) * (1.0f / 128.0f);
    __syncthreads();
    if (t < 9) { int c = t / 3, d = t % 3; rT9[t] = r9[d * 3 + c]; }
    __syncthreads();

    #pragma unroll
    for (int rep = 0; rep < 2; rep++) {
        int o = t + rep * 128;
        const float* w = zw1 + (size_t)o * 9;
        float s1 = zb1[o], s2 = zb1[o];
        #pragma unroll
        for (int q = 0; q < 9; q++) { s1 += r9[q] * w[q]; s2 += rT9[q] * w[q]; }
        Gh[(size_t)e * 256 + o]       = __float2half(silu_f(s1));
        Gh[(size_t)(E + e) * 256 + o] = __float2half(silu_f(s2));
    }
}

// ---------------- K4: 4 LayerNorms + product + final dot (fp16 inputs) ----------------
__global__ __launch_bounds__(256) void final_kernel(
    const __half* __restrict__ XIJ, const __half* __restrict__ U,
    const __half* __restrict__ XZX,
    const float* __restrict__ xg, const float* __restrict__ xb,
    const float* __restrict__ zg, const float* __restrict__ zb,
    const float* __restrict__ zxg, const float* __restrict__ zxb,
    const float* __restrict__ lw, const float* __restrict__ lb,
    float* __restrict__ out, int E) {
    int e = blockIdx.x;
    int t = threadIdx.x;
    const __half* pxij = XIJ + (size_t)e * 768;
    const __half* pu1  = U   + (size_t)e * 768;
    const __half* pu2  = U   + (size_t)(E + e) * 768;
    const __half* pxzx = XZX + (size_t)e * 768;

    __shared__ float red[8][8];
    __shared__ float stats[8];
    __shared__ float dred[8];

    float v0[3], v1[3], v2[3], v3[3];
    float s[8];
    #pragma unroll
    for (int q = 0; q < 8; q++) s[q] = 0.0f;
    #pragma unroll
    for (int k = 0; k < 3; k++) {
        int col = t + k * 256;
        float a = __half2float(pxij[col]), b = __half2float(pu1[col]);
        float c = __half2float(pu2[col]),  d = __half2float(pxzx[col]);
        v0[k] = a; v1[k] = b; v2[k] = c; v3[k] = d;
        s[0] += a; s[1] += a * a;
        s[2] += b; s[3] += b * b;
        s[4] += c; s[5] += c * c;
        s[6] += d; s[7] += d * d;
    }
    #pragma unroll
    for (int off = 16; off > 0; off >>= 1)
        #pragma unroll
        for (int q = 0; q < 8; q++)
            s[q] += __shfl_down_sync(0xffffffffu, s[q], off);
    int warp = t >> 5, lane = t & 31;
    if (lane == 0)
        #pragma unroll
        for (int q = 0; q < 8; q++) red[q][warp] = s[q];
    __syncthreads();
    if (t < 8) {
        float tot = 0.0f;
        #pragma unroll
        for (int w = 0; w < 8; w++) tot += red[t][w];
        stats[t] = tot;
    }
    __syncthreads();

    const float inv = 1.0f / 768.0f;
    const float eps = 1e-5f;
    float m0 = stats[0] * inv, r0 = rsqrtf(stats[1] * inv - m0 * m0 + eps);
    float m1 = stats[2] * inv, r1 = rsqrtf(stats[3] * inv - m1 * m1 + eps);
    float m2 = stats[4] * inv, r2 = rsqrtf(stats[5] * inv - m2 * m2 + eps);
    float m3 = stats[6] * inv, r3 = rsqrtf(stats[7] * inv - m3 * m3 + eps);

    float dot = 0.0f;
    #pragma unroll
    for (int k = 0; k < 3; k++) {
        int col = t + k * 256;
        float a  = (v0[k] - m0) * r0 * xg[col]  + xb[col];
        float b1 = (v1[k] - m1) * r1 * zg[col]  + zb[col];
        float b2 = (v2[k] - m2) * r2 * zg[col]  + zb[col];
        float c  = (v3[k] - m3) * r3 * zxg[col] + zxb[col];
        dot += a * (b1 + b2) * c * lw[col];
    }
    #pragma unroll
    for (int off = 16; off > 0; off >>= 1)
        dot += __shfl_down_sync(0xffffffffu, dot, off);
    if (lane == 0) dred[warp] = dot;
    __syncthreads();
    if (t == 0) {
        float tot = 0.0f;
        #pragma unroll
        for (int w = 0; w < 8; w++) tot += dred[w];
        out[e] = tot + lb[0];
    }
}

// ---------------- launch ----------------
extern "C" void kernel_launch(void* const* d_in, const int* in_sizes, int n_in,
                              void* d_out, int out_size) {
    const float* x   = (const float*)d_in[0];
    const float* Z   = (const float*)d_in[1];
    const int*   tar = (const int*)  d_in[3];
    const float* xij_w1 = (const float*)d_in[4];
    const float* xij_b1 = (const float*)d_in[5];
    const float* xij_w2 = (const float*)d_in[6];
    const float* xij_b2 = (const float*)d_in[7];
    const float* xij_ln_g = (const float*)d_in[8];
    const float* xij_ln_b = (const float*)d_in[9];
    const float* z_w1 = (const float*)d_in[10];
    const float* z_b1 = (const float*)d_in[11];
    const float* z_w2 = (const float*)d_in[12];
    const float* z_b2 = (const float*)d_in[13];
    const float* z_ln_g = (const float*)d_in[14];
    const float* z_ln_b = (const float*)d_in[15];
    const float* zc_w = (const float*)d_in[16];
    const float* zc_b = (const float*)d_in[17];
    const float* zx_w = (const float*)d_in[18];
    const float* zx_b = (const float*)d_in[19];
    const float* zx_ln_g = (const float*)d_in[20];
    const float* zx_ln_b = (const float*)d_in[21];
    const float* lin_w = (const float*)d_in[22];
    const float* lin_b = (const float*)d_in[23];

    int N = in_sizes[0] / 256;
    int E = in_sizes[3] / 2;
    float zx_coeff = (float)(1.0 / (sqrt((double)N) * 3840.0));

    float* ZXT;
    cudaGetSymbolAddress((void**)&ZXT, g_ZXT);
    __half *XIJ, *U, *XZX;
    cudaGetSymbolAddress((void**)&XIJ, g_XIJ);
    cudaGetSymbolAddress((void**)&U,   g_U);
    cudaGetSymbolAddress((void**)&XZX, g_XZX);

    __half *xh,*xl,*Zc,*Ph,*ZZh,*Gh,*Hh,*Th;
    __half *W1,*W2,*ZW2,*ZXW,*ZXTq;
    cudaGetSymbolAddress((void**)&xh,  g_xh);  cudaGetSymbolAddress((void**)&xl,  g_xl);
    cudaGetSymbolAddress((void**)&Zc,  g_Zc);
    cudaGetSymbolAddress((void**)&Ph,  g_Ph);
    cudaGetSymbolAddress((void**)&ZZh, g_ZZh);
    cudaGetSymbolAddress((void**)&Gh,  g_Gh);
    cudaGetSymbolAddress((void**)&Hh,  g_Hh);
    cudaGetSymbolAddress((void**)&Th,  g_Th);
    cudaGetSymbolAddress((void**)&W1,  g_W1);  cudaGetSymbolAddress((void**)&W2,  g_W2);
    cudaGetSymbolAddress((void**)&ZW2, g_ZW2); cudaGetSymbolAddress((void**)&ZXW, g_ZXW);
    cudaGetSymbolAddress((void**)&ZXTq,g_ZXTq);

    cudaFuncSetAttribute(gemm_mma<true >, cudaFuncAttributeMaxDynamicSharedMemorySize, GEMM_SMEM);
    cudaFuncSetAttribute(gemm_mma<false>, cudaFuncAttributeMaxDynamicSharedMemorySize, GEMM_SMEM);
    cudaFuncSetAttribute(gemm_tn_mma, cudaFuncAttributeMaxDynamicSharedMemorySize, TK_SMEM);

    // weight converts
    convert_kernel<<<(65536 + 255) / 256, 256>>>(xij_w1, W1, 65536);
    convert_kernel<<<(196608 + 255) / 256, 256>>>(xij_w2, W2, 196608);
    convert_kernel<<<(196608 + 255) / 256, 256>>>(z_w2,  ZW2, 196608);
    convert_kernel<<<(196608 + 255) / 256, 256>>>(zx_w,  ZXW, 196608);

    // zx node path (split-K, x hi/lo for accuracy)
    int NL = N * 128;
    split_kernel<<<(N * 256 + 255) / 256, 256>>>(x, xh, xl, N * 256);
    zc_kernel<<<(NL + 255) / 256, 256>>>(Z, zc_w, zc_b, Zc, NL);
    cudaMemsetAsync(ZXT, 0, 256 * 384 * sizeof(float), 0);
    {
        int kChunk = 4000;
        int splits = (N + kChunk - 1) / kChunk;
        dim3 grid(3, 2, splits);
        gemm_tn_mma<<<grid, 256, TK_SMEM>>>(xh, xl, Zc, ZXT, 256, 384, N, kChunk, zx_coeff);
    }
    convert_kernel<<<(98304 + 255) / 256, 256>>>(ZXT, ZXTq, 98304);

    // edge prep
    edge_prep<<<E, 128>>>(x, Z, tar, z_w1, z_b1, Ph, ZZh, Gh, E);

    // edge GEMMs — all 1-pass fp16
    dim3 g256(2, E / 256), g768(6, E / 256), gU(6, 2 * E / 256);
    gemm_mma<true ><<<g256, 256, GEMM_SMEM>>>(Ph, W1, xij_b1, Hh, E, 256, 256);
    gemm_mma<false><<<g768, 256, GEMM_SMEM>>>(Hh, W2, xij_b2, XIJ, E, 768, 256);
    gemm_mma<true ><<<gU,   256, GEMM_SMEM>>>(Gh, ZW2, z_b2, U, 2 * E, 768, 256);
    gemm_mma<false><<<g256, 256, GEMM_SMEM>>>(ZZh, ZXTq, nullptr, Th, E, 256, 384);
    gemm_mma<false><<<g768, 256, GEMM_SMEM>>>(Th, ZXW, zx_b, XZX, E, 768, 256);

    final_kernel<<<E, 256>>>(XIJ, U, XZX,
                             xij_ln_g, xij_ln_b, z_ln_g, z_ln_b,
                             zx_ln_g, zx_ln_b, lin_w, lin_b,
                             (float*)d_out, E);
}